// round 9
// baseline (speedup 1.0000x reference)
#include <cuda_runtime.h>
#include <cuda_bf16.h>
#include <math.h>
#include <stdint.h>

#define B_ 2
#define RESO_ 32
#define G_ 32768
#define BG_ 65536
#define HID_ 32
#define NMAX_ 524288
#define BDIM 128
#define MT 64
#define APAD 400
#define BP32 80
#define BP64 144

#define O_A   0
#define O_W0  25600
#define O_WS  40960
#define O_W1  56320
#define O_SB0 64000
#define O_SB1 64128
#define SM_POOL 64256
#define O_FC  64256
#define O_SFB 71936
#define SM_FIN 72064
#define O_WP  25600
#define P_W0  53248
#define P_WS  68608
#define P_W1  83968
#define P_SB0 91648
#define P_SB1 91776
#define P_SBP 91904
#define SM_P0 92160

/* -------- scratch -------- */
__device__ float g_net[(size_t)NMAX_*HID_];
__device__ float g_psort[(size_t)NMAX_*3];
__device__ int   g_gidx[NMAX_];
__device__ int   g_sgidx[NMAX_];
__device__ int   g_hist[BG_];
__device__ int   g_start[BG_];
__device__ int   g_cursor[BG_];
__device__ float g_cellA[BG_*HID_];
__device__ float g_cellB[BG_*HID_];

/* -------- helpers -------- */
__device__ __forceinline__ uint32_t smem_u32(const void* p) {
    uint32_t a;
    asm("{ .reg .u64 t; cvta.to.shared.u64 t, %1; cvt.u32.u64 %0, t; }" : "=r"(a) : "l"(p));
    return a;
}
__device__ __forceinline__ void ldmA(uint32_t a[4], uint32_t addr) {
    asm volatile("ldmatrix.sync.aligned.m8n8.x4.shared.b16 {%0,%1,%2,%3}, [%4];"
        : "=r"(a[0]), "=r"(a[1]), "=r"(a[2]), "=r"(a[3]) : "r"(addr));
}
__device__ __forceinline__ void ldmB(uint32_t b[2], uint32_t addr) {
    asm volatile("ldmatrix.sync.aligned.m8n8.x2.trans.shared.b16 {%0,%1}, [%2];"
        : "=r"(b[0]), "=r"(b[1]) : "r"(addr));
}
__device__ __forceinline__ void mma16816(float d[4], const uint32_t a[4], const uint32_t b[2]) {
    asm volatile("mma.sync.aligned.m16n8k16.row.col.f32.bf16.bf16.f32 "
        "{%0,%1,%2,%3},{%4,%5,%6,%7},{%8,%9},{%0,%1,%2,%3};"
        : "+f"(d[0]), "+f"(d[1]), "+f"(d[2]), "+f"(d[3])
        : "r"(a[0]), "r"(a[1]), "r"(a[2]), "r"(a[3]), "r"(b[0]), "r"(b[1]));
}
__device__ __forceinline__ void hm(float a, float b, uint32_t& H, uint32_t& M) {
    __nv_bfloat16 h0 = __float2bfloat16(a), h1 = __float2bfloat16(b);
    uint16_t u0 = *reinterpret_cast<uint16_t*>(&h0), u1 = *reinterpret_cast<uint16_t*>(&h1);
    H = ((uint32_t)u1 << 16) | u0;
    __nv_bfloat162 m = __floats2bfloat162_rn(a - __bfloat162float(h0), b - __bfloat162float(h1));
    M = *reinterpret_cast<uint32_t*>(&m);
}
/* full row v[64] -> stack [hi|mid|hi] */
__device__ __forceinline__ void writeRow64(char* A, int row, const float* v, bool dorelu) {
    char* base = A + row*APAD;
#pragma unroll
    for (int g = 0; g < 8; g++) {
        uint32_t H[4], M[4];
#pragma unroll
        for (int j = 0; j < 4; j++) {
            float a = v[8*g+2*j], b = v[8*g+2*j+1];
            if (dorelu) { a = fmaxf(a, 0.f); b = fmaxf(b, 0.f); }
            hm(a, b, H[j], M[j]);
        }
        *(uint4*)(base + g*16)       = make_uint4(H[0], H[1], H[2], H[3]);
        *(uint4*)(base + 128 + g*16) = make_uint4(M[0], M[1], M[2], M[3]);
        *(uint4*)(base + 256 + g*16) = make_uint4(H[0], H[1], H[2], H[3]);
    }
}
/* half row (32 values) -> its part of the stack */
__device__ __forceinline__ void writeHalf32(char* A, int row, int half, const float* v, bool dorelu) {
    char* base = A + row*APAD + half*64;
#pragma unroll
    for (int g = 0; g < 4; g++) {
        uint32_t H[4], M[4];
#pragma unroll
        for (int j = 0; j < 4; j++) {
            float a = v[8*g+2*j], b = v[8*g+2*j+1];
            if (dorelu) { a = fmaxf(a, 0.f); b = fmaxf(b, 0.f); }
            hm(a, b, H[j], M[j]);
        }
        *(uint4*)(base + g*16)       = make_uint4(H[0], H[1], H[2], H[3]);
        *(uint4*)(base + 128 + g*16) = make_uint4(M[0], M[1], M[2], M[3]);
        *(uint4*)(base + 256 + g*16) = make_uint4(H[0], H[1], H[2], H[3]);
    }
}
template<int NT>
__device__ __forceinline__ void fragToA(char* A, int wid, int lane,
                                        float acc[NT][4], const float* bias, bool dorelu) {
    const int K2 = NT*16, K4 = NT*32;
    int r0 = wid*16 + (lane >> 2);
    int cb = (lane & 3)*2;
#pragma unroll
    for (int half = 0; half < 2; half++) {
        char* base = A + (r0 + half*8)*APAD;
#pragma unroll
        for (int nt = 0; nt < NT; nt++) {
            int c = nt*8 + cb;
            float v0 = acc[nt][half*2+0] + bias[c];
            float v1 = acc[nt][half*2+1] + bias[c+1];
            if (dorelu) { v0 = fmaxf(v0, 0.f); v1 = fmaxf(v1, 0.f); }
            uint32_t H, M; hm(v0, v1, H, M);
            *(uint32_t*)(base + c*2)      = H;
            *(uint32_t*)(base + K2 + c*2) = M;
            *(uint32_t*)(base + K4 + c*2) = H;
        }
    }
}
__device__ __forceinline__ void fragStore(int ctaBase, int N, int wid, int lane,
                                          float acc[4][4], const float* bias) {
    int r0 = wid*16 + (lane >> 2);
    int cb = (lane & 3)*2;
#pragma unroll
    for (int half = 0; half < 2; half++) {
        int slot = ctaBase + r0 + half*8;
        if (slot < N) {
            float* g = &g_net[(size_t)slot*HID_];
#pragma unroll
            for (int nt = 0; nt < 4; nt++) {
                int c = nt*8 + cb;
                *(float2*)(g + c) = make_float2(acc[nt][half*2] + bias[c],
                                                acc[nt][half*2+1] + bias[c+1]);
            }
        }
    }
}
template<int KT, int NT>
__device__ __forceinline__ void warp_gemm(uint32_t aU, uint32_t bU, int bpad,
                                          int wid, int lane, float acc[NT][4]) {
    uint32_t aAddr = aU + (uint32_t)(wid*16 + (lane & 15))*APAD + (uint32_t)((lane & 16) ? 16 : 0);
    uint32_t bRow = (uint32_t)(lane & 15);
#pragma unroll
    for (int kt = 0; kt < KT; kt++) {
        uint32_t a0[4];
        ldmA(a0, aAddr + kt*32);
#pragma unroll
        for (int nt = 0; nt < NT; nt++) {
            uint32_t b[2];
            ldmB(b, bU + (kt*16 + bRow)*bpad + nt*16);
            mma16816(acc[nt], a0, b);
        }
    }
}
/* weights gmem [K][N] -> stacked [Bh;Bh;Bm] */
__device__ void prepB(char* dst, int tid, const float* __restrict__ g,
                      int K, int Kpad, int N, int bpad) {
    for (int t = tid; t < K*N; t += BDIM) {
        int k = t / N, n = t - k*N;
        float w = g[t];
        __nv_bfloat16 h = __float2bfloat16(w);
        __nv_bfloat16 m = __float2bfloat16(w - __bfloat162float(h));
        *(__nv_bfloat16*)(dst + k*bpad + n*2) = h;
        *(__nv_bfloat16*)(dst + (Kpad+k)*bpad + n*2) = h;
        *(__nv_bfloat16*)(dst + (2*Kpad+k)*bpad + n*2) = m;
    }
}

/* -------- sort pre-pass + pooling -------- */
__global__ void zero_hist_kernel() {
    int s = gridDim.x*blockDim.x;
    for (int i = blockIdx.x*blockDim.x + threadIdx.x; i < BG_; i += s) g_hist[i] = 0;
}
__global__ void index_hist_kernel(const float* __restrict__ p, int T, int N) {
    int i = blockIdx.x*blockDim.x + threadIdx.x;
    if (i >= N) return;
    float p0 = p[3*i+0], p1 = p[3*i+1], p2 = p[3*i+2];
    int b = i / T;
    float pn0 = fminf(fmaxf(__fdiv_rn(p0, 1.101f) + 0.5f, 0.0f), 0.999f);
    float pn1 = fminf(fmaxf(__fdiv_rn(p1, 1.101f) + 0.5f, 0.0f), 0.999f);
    float pn2 = fminf(fmaxf(__fdiv_rn(p2, 1.101f) + 0.5f, 0.0f), 0.999f);
    int gidx = (int)floorf(pn0*32.f) + RESO_*((int)floorf(pn1*32.f) + RESO_*(int)floorf(pn2*32.f)) + b*G_;
    g_gidx[i] = gidx;
    atomicAdd(&g_hist[gidx], 1);
}
__global__ void scan_kernel() {
    __shared__ int part[1024];
    int t = threadIdx.x, base = t*64, s = 0;
#pragma unroll
    for (int j = 0; j < 64; j++) s += g_hist[base+j];
    part[t] = s; __syncthreads();
    for (int off = 1; off < 1024; off <<= 1) {
        int v = (t >= off) ? part[t-off] : 0;
        __syncthreads(); part[t] += v; __syncthreads();
    }
    int run = (t == 0) ? 0 : part[t-1];
#pragma unroll
    for (int j = 0; j < 64; j++) {
        int c = g_hist[base+j];
        g_start[base+j] = run; g_cursor[base+j] = run; run += c;
    }
}
__global__ void perm_kernel(const float* __restrict__ p, int N) {
    int i = blockIdx.x*blockDim.x + threadIdx.x;
    if (i >= N) return;
    int gidx = g_gidx[i];
    int slot = atomicAdd(&g_cursor[gidx], 1);
    g_sgidx[slot] = gidx;
    g_psort[(size_t)slot*3+0] = p[3*i+0];
    g_psort[(size_t)slot*3+1] = p[3*i+1];
    g_psort[(size_t)slot*3+2] = p[3*i+2];
}
__global__ void maxpool_kernel(float* __restrict__ dst) {
    int t = blockIdx.x*blockDim.x + threadIdx.x;
    if (t >= BG_*8) return;
    int cell = t >> 3, q = (t & 7) * 4;
    int s = g_start[cell], n = g_hist[cell];
    float4 m = make_float4(0.f, 0.f, 0.f, 0.f);
    if (n > 0) {
        m = *reinterpret_cast<const float4*>(&g_net[(size_t)s*HID_ + q]);
        for (int k = 1; k < n; k++) {
            float4 v = *reinterpret_cast<const float4*>(&g_net[(size_t)(s+k)*HID_ + q]);
            m.x = fmaxf(m.x, v.x); m.y = fmaxf(m.y, v.y);
            m.z = fmaxf(m.z, v.z); m.w = fmaxf(m.w, v.w);
        }
    }
    *reinterpret_cast<float4*>(&dst[cell*HID_ + q]) = m;
}

/* -------- stage 0 -------- */
__global__ void __launch_bounds__(BDIM) point0_kernel(
    const float* __restrict__ Wp, const float* __restrict__ Bp,
    const float* __restrict__ w0, const float* __restrict__ b0g,
    const float* __restrict__ w1, const float* __restrict__ b1g,
    const float* __restrict__ ws, int N)
{
    extern __shared__ __align__(16) char sm[];
    uint32_t su = smem_u32(sm);
    int tid = threadIdx.x, wid = tid >> 5, lane = tid & 31;
    for (int t = tid; t < 27648/4; t += BDIM) ((uint32_t*)(sm + O_WP))[t] = 0;
    __syncthreads();
    prepB(sm+O_WP, tid, Wp, 60, 64, 64, BP64);
    prepB(sm+P_W0, tid, w0, 64, 64, 32, BP32);
    prepB(sm+P_WS, tid, ws, 64, 64, 32, BP32);
    prepB(sm+P_W1, tid, w1, 32, 32, 32, BP32);
    if (tid < 32) { ((float*)(sm+P_SB0))[tid] = b0g[tid]; ((float*)(sm+P_SB1))[tid] = b1g[tid]; }
    if (tid < 64) ((float*)(sm+P_SBP))[tid] = Bp[tid];
    __syncthreads();
    const float* b0 = (const float*)(sm+P_SB0);
    const float* b1 = (const float*)(sm+P_SB1);
    const float* sbp = (const float*)(sm+P_SBP);

    int ctaBase = blockIdx.x*MT;
    if (tid < MT) {
        int slot = ctaBase + tid;
        float p0 = 0.f, p1 = 0.f, p2 = 0.f;
        if (slot < N) { p0 = g_psort[(size_t)slot*3]; p1 = g_psort[(size_t)slot*3+1]; p2 = g_psort[(size_t)slot*3+2]; }
        float pe[64];
#pragma unroll
        for (int j = 60; j < 64; j++) pe[j] = 0.f;
        float q[3] = {2.f*p0-1.f, 2.f*p1-1.f, 2.f*p2-1.f};
#pragma unroll
        for (int d = 0; d < 3; d++) {
            float y = q[d];
#pragma unroll 1
            for (int l = 0; l < 10; l++) {
                float s, c; sincospif(y, &s, &c);
                pe[l*6+d] = s; pe[l*6+3+d] = c;
                y *= 2.f;
            }
        }
        writeRow64(sm+O_A, tid, pe, false);
    }
    __syncthreads();
    float accX[8][4] = {};
    warp_gemm<12,8>(su+O_A, su+O_WP, BP64, wid, lane, accX);
    __syncwarp();
    fragToA<8>(sm+O_A, wid, lane, accX, sbp, true);
    __syncwarp();
    float accH[4][4] = {};
    warp_gemm<12,4>(su+O_A, su+P_W0, BP32, wid, lane, accH);
    __syncwarp();
    fragToA<8>(sm+O_A, wid, lane, accX, sbp, false);
    __syncwarp();
    float accO[4][4] = {};
    warp_gemm<12,4>(su+O_A, su+P_WS, BP32, wid, lane, accO);
    __syncwarp();
    fragToA<4>(sm+O_A, wid, lane, accH, b0, true);
    __syncwarp();
    warp_gemm<6,4>(su+O_A, su+P_W1, BP32, wid, lane, accO);
    fragStore(ctaBase, N, wid, lane, accO, b1);
}

/* -------- stages 1..3 -------- */
__global__ void __launch_bounds__(BDIM) pool_block_kernel(
    const float* __restrict__ w0, const float* __restrict__ b0g,
    const float* __restrict__ w1, const float* __restrict__ b1g,
    const float* __restrict__ ws, const float* __restrict__ cellSrc, int N)
{
    extern __shared__ __align__(16) char sm[];
    uint32_t su = smem_u32(sm);
    int tid = threadIdx.x, wid = tid >> 5, lane = tid & 31;
    prepB(sm+O_W0, tid, w0, 64, 64, 32, BP32);
    prepB(sm+O_WS, tid, ws, 64, 64, 32, BP32);
    prepB(sm+O_W1, tid, w1, 32, 32, 32, BP32);
    if (tid < 32) { ((float*)(sm+O_SB0))[tid] = b0g[tid]; ((float*)(sm+O_SB1))[tid] = b1g[tid]; }

    int row = tid & 63, half = tid >> 6;
    int ctaBase = blockIdx.x*MT;
    int slot = ctaBase + row;
    float v[32];
    if (slot < N) {
        const float4* src;
        if (half == 0) src = (const float4*)&g_net[(size_t)slot*HID_];
        else           src = (const float4*)&cellSrc[g_sgidx[slot]*HID_];
#pragma unroll
        for (int j = 0; j < 8; j++) {
            float4 a = src[j];
            v[4*j] = a.x; v[4*j+1] = a.y; v[4*j+2] = a.z; v[4*j+3] = a.w;
        }
    } else {
#pragma unroll
        for (int j = 0; j < 32; j++) v[j] = 0.f;
    }
    __syncthreads();
    const float* b0 = (const float*)(sm+O_SB0);
    const float* b1 = (const float*)(sm+O_SB1);

    writeHalf32(sm+O_A, row, half, v, true);
    __syncthreads();
    float accH[4][4] = {};
    warp_gemm<12,4>(su+O_A, su+O_W0, BP32, wid, lane, accH);
    __syncthreads();
    writeHalf32(sm+O_A, row, half, v, false);
    __syncthreads();
    float accO[4][4] = {};
    warp_gemm<12,4>(su+O_A, su+O_WS, BP32, wid, lane, accO);
    __syncwarp();
    fragToA<4>(sm+O_A, wid, lane, accH, b0, true);
    __syncwarp();
    warp_gemm<6,4>(su+O_A, su+O_W1, BP32, wid, lane, accO);
    fragStore(ctaBase, N, wid, lane, accO, b1);
}

/* -------- stage 4 + fc_c -------- */
__global__ void __launch_bounds__(BDIM) final_kernel(
    const float* __restrict__ w0, const float* __restrict__ b0g,
    const float* __restrict__ w1, const float* __restrict__ b1g,
    const float* __restrict__ ws,
    const float* __restrict__ fcw, const float* __restrict__ fcb,
    const float* __restrict__ cellSrc, int N)
{
    extern __shared__ __align__(16) char sm[];
    uint32_t su = smem_u32(sm);
    int tid = threadIdx.x, wid = tid >> 5, lane = tid & 31;
    prepB(sm+O_W0, tid, w0, 64, 64, 32, BP32);
    prepB(sm+O_WS, tid, ws, 64, 64, 32, BP32);
    prepB(sm+O_W1, tid, w1, 32, 32, 32, BP32);
    prepB(sm+O_FC, tid, fcw, 32, 32, 32, BP32);
    if (tid < 32) {
        ((float*)(sm+O_SB0))[tid] = b0g[tid];
        ((float*)(sm+O_SB1))[tid] = b1g[tid];
        ((float*)(sm+O_SFB))[tid] = fcb[tid];
    }
    int row = tid & 63, half = tid >> 6;
    int ctaBase = blockIdx.x*MT;
    int slot = ctaBase + row;
    float v[32];
    if (slot < N) {
        const float4* src;
        if (half == 0) src = (const float4*)&g_net[(size_t)slot*HID_];
        else           src = (const float4*)&cellSrc[g_sgidx[slot]*HID_];
#pragma unroll
        for (int j = 0; j < 8; j++) {
            float4 a = src[j];
            v[4*j] = a.x; v[4*j+1] = a.y; v[4*j+2] = a.z; v[4*j+3] = a.w;
        }
    } else {
#pragma unroll
        for (int j = 0; j < 32; j++) v[j] = 0.f;
    }
    __syncthreads();
    const float* b0 = (const float*)(sm+O_SB0);
    const float* b1 = (const float*)(sm+O_SB1);
    const float* sfb = (const float*)(sm+O_SFB);

    writeHalf32(sm+O_A, row, half, v, true);
    __syncthreads();
    float accH[4][4] = {};
    warp_gemm<12,4>(su+O_A, su+O_W0, BP32, wid, lane, accH);
    __syncthreads();
    writeHalf32(sm+O_A, row, half, v, false);
    __syncthreads();
    float accO[4][4] = {};
    warp_gemm<12,4>(su+O_A, su+O_WS, BP32, wid, lane, accO);
    __syncwarp();
    fragToA<4>(sm+O_A, wid, lane, accH, b0, true);
    __syncwarp();
    warp_gemm<6,4>(su+O_A, su+O_W1, BP32, wid, lane, accO);
    __syncwarp();
    fragToA<4>(sm+O_A, wid, lane, accO, b1, false);
    __syncwarp();
    float accC[4][4] = {};
    warp_gemm<6,4>(su+O_A, su+O_FC, BP32, wid, lane, accC);
    fragStore(ctaBase, N, wid, lane, accC, sfb);
}

/* -------- output: CSR mean + transpose -------- */
__global__ void output_kernel(float* __restrict__ out, int total) {
    int t = blockIdx.x*blockDim.x + threadIdx.x;
    if (t >= total) return;
    int bg = t >> 5, ch = t & 31;
    int s = g_start[bg], n = g_hist[bg];
    float sum = 0.0f;
    for (int k = 0; k < n; k++) sum += g_net[(size_t)(s+k)*HID_ + ch];
    float mean = sum / fmaxf((float)n, 1.0f);
    int b = bg >> 15, g = bg & (G_ - 1);
    out[((size_t)b*HID_ + ch)*G_ + g] = mean;
}

/* -------- host -------- */
extern "C" void kernel_launch(void* const* d_in, const int* in_sizes, int n_in,
                              void* d_out, int out_size) {
    const float* p   = (const float*)d_in[0];
    const float* Wp  = (const float*)d_in[1];
    const float* Bp  = (const float*)d_in[2];
    const float* W0  = (const float*)d_in[3];
    const float* B0  = (const float*)d_in[4];
    const float* W1  = (const float*)d_in[5];
    const float* B1  = (const float*)d_in[6];
    const float* Ws  = (const float*)d_in[7];
    const float* Fc  = (const float*)d_in[8];
    const float* FcB = (const float*)d_in[9];
    float* out = (float*)d_out;

    int T = in_sizes[0] / (B_ * 3);
    int N = B_ * T;
    int nbp = (N + BDIM - 1) / BDIM;
    int nb = (N + MT - 1) / MT;

    cudaFuncSetAttribute(point0_kernel, cudaFuncAttributeMaxDynamicSharedMemorySize, SM_P0);
    cudaFuncSetAttribute(pool_block_kernel, cudaFuncAttributeMaxDynamicSharedMemorySize, SM_POOL);
    cudaFuncSetAttribute(final_kernel, cudaFuncAttributeMaxDynamicSharedMemorySize, SM_FIN);

    float* cellA; cudaGetSymbolAddress((void**)&cellA, g_cellA);
    float* cellB; cudaGetSymbolAddress((void**)&cellB, g_cellB);

    zero_hist_kernel<<<64, 256>>>();
    index_hist_kernel<<<nbp, BDIM>>>(p, T, N);
    scan_kernel<<<1, 1024>>>();
    perm_kernel<<<nbp, BDIM>>>(p, N);

    point0_kernel<<<nb, BDIM, SM_P0>>>(Wp, Bp, W0, B0, W1, B1, Ws, N);
    maxpool_kernel<<<BG_*8/256, 256>>>(cellA);

    pool_block_kernel<<<nb, BDIM, SM_POOL>>>(W0 + 1*64*HID_, B0 + 1*HID_,
        W1 + 1*HID_*HID_, B1 + 1*HID_, Ws + 1*64*HID_, cellA, N);
    maxpool_kernel<<<BG_*8/256, 256>>>(cellB);

    pool_block_kernel<<<nb, BDIM, SM_POOL>>>(W0 + 2*64*HID_, B0 + 2*HID_,
        W1 + 2*HID_*HID_, B1 + 2*HID_, Ws + 2*64*HID_, cellB, N);
    maxpool_kernel<<<BG_*8/256, 256>>>(cellA);

    pool_block_kernel<<<nb, BDIM, SM_POOL>>>(W0 + 3*64*HID_, B0 + 3*HID_,
        W1 + 3*HID_*HID_, B1 + 3*HID_, Ws + 3*64*HID_, cellA, N);
    maxpool_kernel<<<BG_*8/256, 256>>>(cellB);

    final_kernel<<<nb, BDIM, SM_FIN>>>(W0 + 4*64*HID_, B0 + 4*HID_,
        W1 + 4*HID_*HID_, B1 + 4*HID_, Ws + 4*64*HID_, Fc, FcB, cellB, N);

    output_kernel<<<(out_size + 255)/256, 256>>>(out, out_size);
}

// round 10
// speedup vs baseline: 1.4236x; 1.4236x over previous
#include <cuda_runtime.h>
#include <cuda_bf16.h>
#include <math.h>
#include <stdint.h>

#define B_ 2
#define RESO_ 32
#define G_ 32768
#define BG_ 65536
#define HID_ 32
#define NMAX_ 524288
#define BDIM 128
#define TILES 4
#define APAD 400
#define BP32 80
#define BP64 144

#define O_A   0
#define O_W0  51200
#define O_WS  66560
#define O_W1  81920
#define O_SB0 89600
#define O_SB1 89728
#define SM_POOL 89856
#define O_FC  89856
#define O_SFB 97536
#define SM_FIN 97664
#define O_WP  51200
#define P_W0  78848
#define P_WS  94208
#define P_W1  109568
#define P_SB0 117248
#define P_SB1 117376
#define P_SBP 117504
#define SM_P0 117760

/* -------- scratch -------- */
__device__ float g_net[(size_t)NMAX_*HID_];
__device__ float g_psort[(size_t)NMAX_*3];
__device__ int   g_gidx[NMAX_];
__device__ int   g_sgidx[NMAX_];
__device__ int   g_hist[BG_];
__device__ int   g_start[BG_];
__device__ int   g_cursor[BG_];
__device__ float g_cellA[BG_*HID_];
__device__ float g_cellB[BG_*HID_];

/* -------- helpers -------- */
__device__ __forceinline__ uint32_t smem_u32(const void* p) {
    uint32_t a;
    asm("{ .reg .u64 t; cvta.to.shared.u64 t, %1; cvt.u32.u64 %0, t; }" : "=r"(a) : "l"(p));
    return a;
}
__device__ __forceinline__ void ldmA(uint32_t a[4], uint32_t addr) {
    asm volatile("ldmatrix.sync.aligned.m8n8.x4.shared.b16 {%0,%1,%2,%3}, [%4];"
        : "=r"(a[0]), "=r"(a[1]), "=r"(a[2]), "=r"(a[3]) : "r"(addr));
}
__device__ __forceinline__ void ldmB(uint32_t b[2], uint32_t addr) {
    asm volatile("ldmatrix.sync.aligned.m8n8.x2.trans.shared.b16 {%0,%1}, [%2];"
        : "=r"(b[0]), "=r"(b[1]) : "r"(addr));
}
__device__ __forceinline__ void mma16816(float d[4], const uint32_t a[4], const uint32_t b[2]) {
    asm volatile("mma.sync.aligned.m16n8k16.row.col.f32.bf16.bf16.f32 "
        "{%0,%1,%2,%3},{%4,%5,%6,%7},{%8,%9},{%0,%1,%2,%3};"
        : "+f"(d[0]), "+f"(d[1]), "+f"(d[2]), "+f"(d[3])
        : "r"(a[0]), "r"(a[1]), "r"(a[2]), "r"(a[3]), "r"(b[0]), "r"(b[1]));
}
__device__ __forceinline__ void hm(float a, float b, uint32_t& H, uint32_t& M) {
    __nv_bfloat16 h0 = __float2bfloat16(a), h1 = __float2bfloat16(b);
    uint16_t u0 = *reinterpret_cast<uint16_t*>(&h0), u1 = *reinterpret_cast<uint16_t*>(&h1);
    H = ((uint32_t)u1 << 16) | u0;
    __nv_bfloat162 m = __floats2bfloat162_rn(a - __bfloat162float(h0), b - __bfloat162float(h1));
    M = *reinterpret_cast<uint32_t*>(&m);
}
__device__ __forceinline__ void writeRow64(char* A, int row, const float* v, bool dorelu) {
    char* base = A + row*APAD;
#pragma unroll
    for (int g = 0; g < 8; g++) {
        uint32_t H[4], M[4];
#pragma unroll
        for (int j = 0; j < 4; j++) {
            float a = v[8*g+2*j], b = v[8*g+2*j+1];
            if (dorelu) { a = fmaxf(a, 0.f); b = fmaxf(b, 0.f); }
            hm(a, b, H[j], M[j]);
        }
        *(uint4*)(base + g*16)       = make_uint4(H[0], H[1], H[2], H[3]);
        *(uint4*)(base + 128 + g*16) = make_uint4(M[0], M[1], M[2], M[3]);
        *(uint4*)(base + 256 + g*16) = make_uint4(H[0], H[1], H[2], H[3]);
    }
}
template<int NT>
__device__ __forceinline__ void fragToA(char* A, int wid, int lane,
                                        float acc[2][NT][4], const float* bias, bool dorelu) {
    const int K2 = NT*16, K4 = NT*32;
    int r0 = wid*32 + (lane >> 2);
    int cb = (lane & 3)*2;
#pragma unroll
    for (int mt = 0; mt < 2; mt++)
#pragma unroll
    for (int half = 0; half < 2; half++) {
        char* base = A + (r0 + mt*16 + half*8)*APAD;
#pragma unroll
        for (int nt = 0; nt < NT; nt++) {
            int c = nt*8 + cb;
            float v0 = acc[mt][nt][half*2+0] + bias[c];
            float v1 = acc[mt][nt][half*2+1] + bias[c+1];
            if (dorelu) { v0 = fmaxf(v0, 0.f); v1 = fmaxf(v1, 0.f); }
            uint32_t H, M; hm(v0, v1, H, M);
            *(uint32_t*)(base + c*2)      = H;
            *(uint32_t*)(base + K2 + c*2) = M;
            *(uint32_t*)(base + K4 + c*2) = H;
        }
    }
}
__device__ __forceinline__ void fragStore(int ctaBase, int N, int wid, int lane,
                                          float acc[2][4][4], const float* bias) {
    int r0 = wid*32 + (lane >> 2);
    int cb = (lane & 3)*2;
#pragma unroll
    for (int mt = 0; mt < 2; mt++)
#pragma unroll
    for (int half = 0; half < 2; half++) {
        int slot = ctaBase + r0 + mt*16 + half*8;
        if (slot < N) {
            float* g = &g_net[(size_t)slot*HID_];
#pragma unroll
            for (int nt = 0; nt < 4; nt++) {
                int c = nt*8 + cb;
                *(float2*)(g + c) = make_float2(acc[mt][nt][half*2] + bias[c],
                                                acc[mt][nt][half*2+1] + bias[c+1]);
            }
        }
    }
}
template<int KT, int NT>
__device__ __forceinline__ void warp_gemm(uint32_t aU, uint32_t bU, int bpad,
                                          int wid, int lane, float acc[2][NT][4]) {
    uint32_t aAddr = aU + (uint32_t)(wid*32 + (lane & 15))*APAD + (uint32_t)((lane & 16) ? 16 : 0);
    uint32_t bRow = (uint32_t)(lane & 15);
#pragma unroll
    for (int kt = 0; kt < KT; kt++) {
        uint32_t a0[4], a1[4];
        ldmA(a0, aAddr + kt*32);
        ldmA(a1, aAddr + kt*32 + 16*APAD);
#pragma unroll
        for (int nt = 0; nt < NT; nt++) {
            uint32_t b[2];
            ldmB(b, bU + (kt*16 + bRow)*bpad + nt*16);
            mma16816(acc[0][nt], a0, b);
            mma16816(acc[1][nt], a1, b);
        }
    }
}
__device__ void prepB(char* dst, int tid, const float* __restrict__ g,
                      int K, int Kpad, int N, int bpad) {
    for (int t = tid; t < K*N; t += BDIM) {
        int k = t / N, n = t - k*N;
        float w = g[t];
        __nv_bfloat16 h = __float2bfloat16(w);
        __nv_bfloat16 m = __float2bfloat16(w - __bfloat162float(h));
        *(__nv_bfloat16*)(dst + k*bpad + n*2) = h;
        *(__nv_bfloat16*)(dst + (Kpad+k)*bpad + n*2) = h;
        *(__nv_bfloat16*)(dst + (2*Kpad+k)*bpad + n*2) = m;
    }
}

/* -------- sort pre-pass + pooling -------- */
__global__ void zero_hist_kernel() {
    int s = gridDim.x*blockDim.x;
    for (int i = blockIdx.x*blockDim.x + threadIdx.x; i < BG_; i += s) g_hist[i] = 0;
}
__global__ void index_hist_kernel(const float* __restrict__ p, int T, int N) {
    int i = blockIdx.x*blockDim.x + threadIdx.x;
    if (i >= N) return;
    float p0 = p[3*i+0], p1 = p[3*i+1], p2 = p[3*i+2];
    int b = i / T;
    float pn0 = fminf(fmaxf(__fdiv_rn(p0, 1.101f) + 0.5f, 0.0f), 0.999f);
    float pn1 = fminf(fmaxf(__fdiv_rn(p1, 1.101f) + 0.5f, 0.0f), 0.999f);
    float pn2 = fminf(fmaxf(__fdiv_rn(p2, 1.101f) + 0.5f, 0.0f), 0.999f);
    int gidx = (int)floorf(pn0*32.f) + RESO_*((int)floorf(pn1*32.f) + RESO_*(int)floorf(pn2*32.f)) + b*G_;
    g_gidx[i] = gidx;
    atomicAdd(&g_hist[gidx], 1);
}
__global__ void scan_kernel() {
    __shared__ int part[1024];
    int t = threadIdx.x, base = t*64, s = 0;
#pragma unroll
    for (int j = 0; j < 64; j++) s += g_hist[base+j];
    part[t] = s; __syncthreads();
    for (int off = 1; off < 1024; off <<= 1) {
        int v = (t >= off) ? part[t-off] : 0;
        __syncthreads(); part[t] += v; __syncthreads();
    }
    int run = (t == 0) ? 0 : part[t-1];
#pragma unroll
    for (int j = 0; j < 64; j++) {
        int c = g_hist[base+j];
        g_start[base+j] = run; g_cursor[base+j] = run; run += c;
    }
}
__global__ void perm_kernel(const float* __restrict__ p, int N) {
    int i = blockIdx.x*blockDim.x + threadIdx.x;
    if (i >= N) return;
    int gidx = g_gidx[i];
    int slot = atomicAdd(&g_cursor[gidx], 1);
    g_sgidx[slot] = gidx;
    g_psort[(size_t)slot*3+0] = p[3*i+0];
    g_psort[(size_t)slot*3+1] = p[3*i+1];
    g_psort[(size_t)slot*3+2] = p[3*i+2];
}
__global__ void maxpool_kernel(float* __restrict__ dst) {
    int t = blockIdx.x*blockDim.x + threadIdx.x;
    if (t >= BG_*8) return;
    int cell = t >> 3, q = (t & 7) * 4;
    int s = g_start[cell], n = g_hist[cell];
    float4 m = make_float4(0.f, 0.f, 0.f, 0.f);
    if (n > 0) {
        m = *reinterpret_cast<const float4*>(&g_net[(size_t)s*HID_ + q]);
        for (int k = 1; k < n; k++) {
            float4 v = *reinterpret_cast<const float4*>(&g_net[(size_t)(s+k)*HID_ + q]);
            m.x = fmaxf(m.x, v.x); m.y = fmaxf(m.y, v.y);
            m.z = fmaxf(m.z, v.z); m.w = fmaxf(m.w, v.w);
        }
    }
    *reinterpret_cast<float4*>(&dst[cell*HID_ + q]) = m;
}

/* -------- stage 0 (persistent over TILES) -------- */
__global__ void __launch_bounds__(BDIM) point0_kernel(
    const float* __restrict__ Wp, const float* __restrict__ Bp,
    const float* __restrict__ w0, const float* __restrict__ b0g,
    const float* __restrict__ w1, const float* __restrict__ b1g,
    const float* __restrict__ ws, int N)
{
    extern __shared__ __align__(16) char sm[];
    uint32_t su = smem_u32(sm);
    int tid = threadIdx.x, wid = tid >> 5, lane = tid & 31;
    for (int t = tid; t < 27648/4; t += BDIM) ((uint32_t*)(sm + O_WP))[t] = 0;
    __syncthreads();
    prepB(sm+O_WP, tid, Wp, 60, 64, 64, BP64);
    prepB(sm+P_W0, tid, w0, 64, 64, 32, BP32);
    prepB(sm+P_WS, tid, ws, 64, 64, 32, BP32);
    prepB(sm+P_W1, tid, w1, 32, 32, 32, BP32);
    if (tid < 32) { ((float*)(sm+P_SB0))[tid] = b0g[tid]; ((float*)(sm+P_SB1))[tid] = b1g[tid]; }
    if (tid < 64) ((float*)(sm+P_SBP))[tid] = Bp[tid];
    __syncthreads();
    const float* b0 = (const float*)(sm+P_SB0);
    const float* b1 = (const float*)(sm+P_SB1);
    const float* sbp = (const float*)(sm+P_SBP);

    for (int tile = 0; tile < TILES; tile++) {
        int ctaBase = (blockIdx.x*TILES + tile)*BDIM;
        if (ctaBase >= N) break;
        int slot = ctaBase + tid;
        float p0 = 0.f, p1 = 0.f, p2 = 0.f;
        if (slot < N) { p0 = g_psort[(size_t)slot*3]; p1 = g_psort[(size_t)slot*3+1]; p2 = g_psort[(size_t)slot*3+2]; }
        float pe[64];
#pragma unroll
        for (int j = 60; j < 64; j++) pe[j] = 0.f;
        float q[3] = {2.f*p0-1.f, 2.f*p1-1.f, 2.f*p2-1.f};
#pragma unroll
        for (int d = 0; d < 3; d++) {
            float y = q[d];
#pragma unroll 1
            for (int l = 0; l < 10; l++) {
                float s, c; sincospif(y, &s, &c);
                pe[l*6+d] = s; pe[l*6+3+d] = c;
                y *= 2.f;
            }
        }
        writeRow64(sm+O_A, tid, pe, false);
        __syncwarp();
        float accX[2][8][4] = {};
        warp_gemm<12,8>(su+O_A, su+O_WP, BP64, wid, lane, accX);
        __syncwarp();
        fragToA<8>(sm+O_A, wid, lane, accX, sbp, true);
        __syncwarp();
        float accH[2][4][4] = {};
        warp_gemm<12,4>(su+O_A, su+P_W0, BP32, wid, lane, accH);
        __syncwarp();
        fragToA<8>(sm+O_A, wid, lane, accX, sbp, false);
        __syncwarp();
        float accO[2][4][4] = {};
        warp_gemm<12,4>(su+O_A, su+P_WS, BP32, wid, lane, accO);
        __syncwarp();
        fragToA<4>(sm+O_A, wid, lane, accH, b0, true);
        __syncwarp();
        warp_gemm<6,4>(su+O_A, su+P_W1, BP32, wid, lane, accO);
        fragStore(ctaBase, N, wid, lane, accO, b1);
        __syncwarp();
    }
}

/* -------- stages 1..3 (persistent over TILES) -------- */
__global__ void __launch_bounds__(BDIM) pool_block_kernel(
    const float* __restrict__ w0, const float* __restrict__ b0g,
    const float* __restrict__ w1, const float* __restrict__ b1g,
    const float* __restrict__ ws, const float* __restrict__ cellSrc, int N)
{
    extern __shared__ __align__(16) char sm[];
    uint32_t su = smem_u32(sm);
    int tid = threadIdx.x, wid = tid >> 5, lane = tid & 31;
    prepB(sm+O_W0, tid, w0, 64, 64, 32, BP32);
    prepB(sm+O_WS, tid, ws, 64, 64, 32, BP32);
    prepB(sm+O_W1, tid, w1, 32, 32, 32, BP32);
    if (tid < 32) { ((float*)(sm+O_SB0))[tid] = b0g[tid]; ((float*)(sm+O_SB1))[tid] = b1g[tid]; }
    __syncthreads();
    const float* b0 = (const float*)(sm+O_SB0);
    const float* b1 = (const float*)(sm+O_SB1);

    for (int tile = 0; tile < TILES; tile++) {
        int ctaBase = (blockIdx.x*TILES + tile)*BDIM;
        if (ctaBase >= N) break;
        int slot = ctaBase + tid;
        float x[64];
        if (slot < N) {
            int gidx = g_sgidx[slot];
            const float4* np = (const float4*)&g_net[(size_t)slot*HID_];
            const float4* pp = (const float4*)&cellSrc[gidx*HID_];
#pragma unroll
            for (int j = 0; j < 8; j++) {
                float4 a = np[j]; x[4*j]=a.x; x[4*j+1]=a.y; x[4*j+2]=a.z; x[4*j+3]=a.w;
                float4 pb = pp[j]; x[32+4*j]=pb.x; x[32+4*j+1]=pb.y; x[32+4*j+2]=pb.z; x[32+4*j+3]=pb.w;
            }
        } else {
#pragma unroll
            for (int j = 0; j < 64; j++) x[j] = 0.f;
        }
        writeRow64(sm+O_A, tid, x, true);
        __syncwarp();
        float accH[2][4][4] = {};
        warp_gemm<12,4>(su+O_A, su+O_W0, BP32, wid, lane, accH);
        __syncwarp();
        writeRow64(sm+O_A, tid, x, false);
        __syncwarp();
        float accO[2][4][4] = {};
        warp_gemm<12,4>(su+O_A, su+O_WS, BP32, wid, lane, accO);
        __syncwarp();
        fragToA<4>(sm+O_A, wid, lane, accH, b0, true);
        __syncwarp();
        warp_gemm<6,4>(su+O_A, su+O_W1, BP32, wid, lane, accO);
        fragStore(ctaBase, N, wid, lane, accO, b1);
        __syncwarp();
    }
}

/* -------- stage 4 + fc_c (persistent over TILES) -------- */
__global__ void __launch_bounds__(BDIM) final_kernel(
    const float* __restrict__ w0, const float* __restrict__ b0g,
    const float* __restrict__ w1, const float* __restrict__ b1g,
    const float* __restrict__ ws,
    const float* __restrict__ fcw, const float* __restrict__ fcb,
    const float* __restrict__ cellSrc, int N)
{
    extern __shared__ __align__(16) char sm[];
    uint32_t su = smem_u32(sm);
    int tid = threadIdx.x, wid = tid >> 5, lane = tid & 31;
    prepB(sm+O_W0, tid, w0, 64, 64, 32, BP32);
    prepB(sm+O_WS, tid, ws, 64, 64, 32, BP32);
    prepB(sm+O_W1, tid, w1, 32, 32, 32, BP32);
    prepB(sm+O_FC, tid, fcw, 32, 32, 32, BP32);
    if (tid < 32) {
        ((float*)(sm+O_SB0))[tid] = b0g[tid];
        ((float*)(sm+O_SB1))[tid] = b1g[tid];
        ((float*)(sm+O_SFB))[tid] = fcb[tid];
    }
    __syncthreads();
    const float* b0 = (const float*)(sm+O_SB0);
    const float* b1 = (const float*)(sm+O_SB1);
    const float* sfb = (const float*)(sm+O_SFB);

    for (int tile = 0; tile < TILES; tile++) {
        int ctaBase = (blockIdx.x*TILES + tile)*BDIM;
        if (ctaBase >= N) break;
        int slot = ctaBase + tid;
        float x[64];
        if (slot < N) {
            int gidx = g_sgidx[slot];
            const float4* np = (const float4*)&g_net[(size_t)slot*HID_];
            const float4* pp = (const float4*)&cellSrc[gidx*HID_];
#pragma unroll
            for (int j = 0; j < 8; j++) {
                float4 a = np[j]; x[4*j]=a.x; x[4*j+1]=a.y; x[4*j+2]=a.z; x[4*j+3]=a.w;
                float4 pb = pp[j]; x[32+4*j]=pb.x; x[32+4*j+1]=pb.y; x[32+4*j+2]=pb.z; x[32+4*j+3]=pb.w;
            }
        } else {
#pragma unroll
            for (int j = 0; j < 64; j++) x[j] = 0.f;
        }
        writeRow64(sm+O_A, tid, x, true);
        __syncwarp();
        float accH[2][4][4] = {};
        warp_gemm<12,4>(su+O_A, su+O_W0, BP32, wid, lane, accH);
        __syncwarp();
        writeRow64(sm+O_A, tid, x, false);
        __syncwarp();
        float accO[2][4][4] = {};
        warp_gemm<12,4>(su+O_A, su+O_WS, BP32, wid, lane, accO);
        __syncwarp();
        fragToA<4>(sm+O_A, wid, lane, accH, b0, true);
        __syncwarp();
        warp_gemm<6,4>(su+O_A, su+O_W1, BP32, wid, lane, accO);
        __syncwarp();
        fragToA<4>(sm+O_A, wid, lane, accO, b1, false);
        __syncwarp();
        float accC[2][4][4] = {};
        warp_gemm<6,4>(su+O_A, su+O_FC, BP32, wid, lane, accC);
        fragStore(ctaBase, N, wid, lane, accC, sfb);
        __syncwarp();
    }
}

/* -------- output: CSR mean + transpose -------- */
__global__ void output_kernel(float* __restrict__ out, int total) {
    int t = blockIdx.x*blockDim.x + threadIdx.x;
    if (t >= total) return;
    int bg = t >> 5, ch = t & 31;
    int s = g_start[bg], n = g_hist[bg];
    float sum = 0.0f;
    for (int k = 0; k < n; k++) sum += g_net[(size_t)(s+k)*HID_ + ch];
    float mean = sum / fmaxf((float)n, 1.0f);
    int b = bg >> 15, g = bg & (G_ - 1);
    out[((size_t)b*HID_ + ch)*G_ + g] = mean;
}

/* -------- host -------- */
extern "C" void kernel_launch(void* const* d_in, const int* in_sizes, int n_in,
                              void* d_out, int out_size) {
    const float* p   = (const float*)d_in[0];
    const float* Wp  = (const float*)d_in[1];
    const float* Bp  = (const float*)d_in[2];
    const float* W0  = (const float*)d_in[3];
    const float* B0  = (const float*)d_in[4];
    const float* W1  = (const float*)d_in[5];
    const float* B1  = (const float*)d_in[6];
    const float* Ws  = (const float*)d_in[7];
    const float* Fc  = (const float*)d_in[8];
    const float* FcB = (const float*)d_in[9];
    float* out = (float*)d_out;

    int T = in_sizes[0] / (B_ * 3);
    int N = B_ * T;
    int nbp = (N + BDIM - 1) / BDIM;
    int nb = (N + BDIM*TILES - 1) / (BDIM*TILES);

    cudaFuncSetAttribute(point0_kernel, cudaFuncAttributeMaxDynamicSharedMemorySize, SM_P0);
    cudaFuncSetAttribute(pool_block_kernel, cudaFuncAttributeMaxDynamicSharedMemorySize, SM_POOL);
    cudaFuncSetAttribute(final_kernel, cudaFuncAttributeMaxDynamicSharedMemorySize, SM_FIN);

    float* cellA; cudaGetSymbolAddress((void**)&cellA, g_cellA);
    float* cellB; cudaGetSymbolAddress((void**)&cellB, g_cellB);

    zero_hist_kernel<<<64, 256>>>();
    index_hist_kernel<<<nbp, BDIM>>>(p, T, N);
    scan_kernel<<<1, 1024>>>();
    perm_kernel<<<nbp, BDIM>>>(p, N);

    point0_kernel<<<nb, BDIM, SM_P0>>>(Wp, Bp, W0, B0, W1, B1, Ws, N);
    maxpool_kernel<<<BG_*8/256, 256>>>(cellA);

    pool_block_kernel<<<nb, BDIM, SM_POOL>>>(W0 + 1*64*HID_, B0 + 1*HID_,
        W1 + 1*HID_*HID_, B1 + 1*HID_, Ws + 1*64*HID_, cellA, N);
    maxpool_kernel<<<BG_*8/256, 256>>>(cellB);

    pool_block_kernel<<<nb, BDIM, SM_POOL>>>(W0 + 2*64*HID_, B0 + 2*HID_,
        W1 + 2*HID_*HID_, B1 + 2*HID_, Ws + 2*64*HID_, cellB, N);
    maxpool_kernel<<<BG_*8/256, 256>>>(cellA);

    pool_block_kernel<<<nb, BDIM, SM_POOL>>>(W0 + 3*64*HID_, B0 + 3*HID_,
        W1 + 3*HID_*HID_, B1 + 3*HID_, Ws + 3*64*HID_, cellA, N);
    maxpool_kernel<<<BG_*8/256, 256>>>(cellB);

    final_kernel<<<nb, BDIM, SM_FIN>>>(W0 + 4*64*HID_, B0 + 4*HID_,
        W1 + 4*HID_*HID_, B1 + 4*HID_, Ws + 4*64*HID_, Fc, FcB, cellB, N);

    output_kernel<<<(out_size + 255)/256, 256>>>(out, out_size);
}

// round 11
// speedup vs baseline: 1.5856x; 1.1138x over previous
#include <cuda_runtime.h>
#include <cuda_bf16.h>
#include <math.h>
#include <stdint.h>

#define B_ 2
#define RESO_ 32
#define G_ 32768
#define BG_ 65536
#define HID_ 32
#define NMAX_ 524288
#define BDIM 128
#define APAD 400
#define BP32 80
#define BP64 144
#define MAXCTA 296

#define O_A   0
#define O_W0  51200
#define O_WS  66560
#define O_W1  81920
#define O_SB0 89600
#define O_SB1 89728
#define SM_POOL 89856
#define O_FC  89856
#define O_SFB 97536
#define SM_FIN 97664
#define O_WP  51200
#define P_W0  78848
#define P_WS  94208
#define P_W1  109568
#define P_SB0 117248
#define P_SB1 117376
#define P_SBP 117504
#define SM_P0 117760

/* -------- scratch -------- */
__device__ float g_net[(size_t)NMAX_*HID_];
__device__ float g_psort[(size_t)NMAX_*3];
__device__ int   g_gidx[NMAX_];
__device__ int   g_sgidx[NMAX_];
__device__ int   g_hist[BG_];
__device__ int   g_start[BG_];
__device__ int   g_cursor[BG_];
__device__ float g_cellA[BG_*HID_];
__device__ float g_cellB[BG_*HID_];

/* -------- helpers -------- */
__device__ __forceinline__ uint32_t smem_u32(const void* p) {
    uint32_t a;
    asm("{ .reg .u64 t; cvta.to.shared.u64 t, %1; cvt.u32.u64 %0, t; }" : "=r"(a) : "l"(p));
    return a;
}
__device__ __forceinline__ void ldmA(uint32_t a[4], uint32_t addr) {
    asm volatile("ldmatrix.sync.aligned.m8n8.x4.shared.b16 {%0,%1,%2,%3}, [%4];"
        : "=r"(a[0]), "=r"(a[1]), "=r"(a[2]), "=r"(a[3]) : "r"(addr));
}
__device__ __forceinline__ void ldmB(uint32_t b[2], uint32_t addr) {
    asm volatile("ldmatrix.sync.aligned.m8n8.x2.trans.shared.b16 {%0,%1}, [%2];"
        : "=r"(b[0]), "=r"(b[1]) : "r"(addr));
}
__device__ __forceinline__ void mma16816(float d[4], const uint32_t a[4], const uint32_t b[2]) {
    asm volatile("mma.sync.aligned.m16n8k16.row.col.f32.bf16.bf16.f32 "
        "{%0,%1,%2,%3},{%4,%5,%6,%7},{%8,%9},{%0,%1,%2,%3};"
        : "+f"(d[0]), "+f"(d[1]), "+f"(d[2]), "+f"(d[3])
        : "r"(a[0]), "r"(a[1]), "r"(a[2]), "r"(a[3]), "r"(b[0]), "r"(b[1]));
}
__device__ __forceinline__ void hm(float a, float b, uint32_t& H, uint32_t& M) {
    __nv_bfloat16 h0 = __float2bfloat16(a), h1 = __float2bfloat16(b);
    uint16_t u0 = *reinterpret_cast<uint16_t*>(&h0), u1 = *reinterpret_cast<uint16_t*>(&h1);
    H = ((uint32_t)u1 << 16) | u0;
    __nv_bfloat162 m = __floats2bfloat162_rn(a - __bfloat162float(h0), b - __bfloat162float(h1));
    M = *reinterpret_cast<uint32_t*>(&m);
}
__device__ __forceinline__ void writeRow64(char* A, int row, const float* v, bool dorelu) {
    char* base = A + row*APAD;
#pragma unroll
    for (int g = 0; g < 8; g++) {
        uint32_t H[4], M[4];
#pragma unroll
        for (int j = 0; j < 4; j++) {
            float a = v[8*g+2*j], b = v[8*g+2*j+1];
            if (dorelu) { a = fmaxf(a, 0.f); b = fmaxf(b, 0.f); }
            hm(a, b, H[j], M[j]);
        }
        *(uint4*)(base + g*16)       = make_uint4(H[0], H[1], H[2], H[3]);
        *(uint4*)(base + 128 + g*16) = make_uint4(M[0], M[1], M[2], M[3]);
        *(uint4*)(base + 256 + g*16) = make_uint4(H[0], H[1], H[2], H[3]);
    }
}
template<int NT>
__device__ __forceinline__ void fragToA(char* A, int wid, int lane,
                                        float acc[2][NT][4], const float* bias, bool dorelu) {
    const int K2 = NT*16, K4 = NT*32;
    int r0 = wid*32 + (lane >> 2);
    int cb = (lane & 3)*2;
#pragma unroll
    for (int mt = 0; mt < 2; mt++)
#pragma unroll
    for (int half = 0; half < 2; half++) {
        char* base = A + (r0 + mt*16 + half*8)*APAD;
#pragma unroll
        for (int nt = 0; nt < NT; nt++) {
            int c = nt*8 + cb;
            float v0 = acc[mt][nt][half*2+0] + bias[c];
            float v1 = acc[mt][nt][half*2+1] + bias[c+1];
            if (dorelu) { v0 = fmaxf(v0, 0.f); v1 = fmaxf(v1, 0.f); }
            uint32_t H, M; hm(v0, v1, H, M);
            *(uint32_t*)(base + c*2)      = H;
            *(uint32_t*)(base + K2 + c*2) = M;
            *(uint32_t*)(base + K4 + c*2) = H;
        }
    }
}
__device__ __forceinline__ void fragStore(int ctaBase, int N, int wid, int lane,
                                          float acc[2][4][4], const float* bias) {
    int r0 = wid*32 + (lane >> 2);
    int cb = (lane & 3)*2;
#pragma unroll
    for (int mt = 0; mt < 2; mt++)
#pragma unroll
    for (int half = 0; half < 2; half++) {
        int slot = ctaBase + r0 + mt*16 + half*8;
        if (slot < N) {
            float* g = &g_net[(size_t)slot*HID_];
#pragma unroll
            for (int nt = 0; nt < 4; nt++) {
                int c = nt*8 + cb;
                *(float2*)(g + c) = make_float2(acc[mt][nt][half*2] + bias[c],
                                                acc[mt][nt][half*2+1] + bias[c+1]);
            }
        }
    }
}
template<int KT, int NT>
__device__ __forceinline__ void warp_gemm(uint32_t aU, uint32_t bU, int bpad,
                                          int wid, int lane, float acc[2][NT][4]) {
    uint32_t aAddr = aU + (uint32_t)(wid*32 + (lane & 15))*APAD + (uint32_t)((lane & 16) ? 16 : 0);
    uint32_t bRow = (uint32_t)(lane & 15);
#pragma unroll
    for (int kt = 0; kt < KT; kt++) {
        uint32_t a0[4], a1[4];
        ldmA(a0, aAddr + kt*32);
        ldmA(a1, aAddr + kt*32 + 16*APAD);
#pragma unroll
        for (int nt = 0; nt < NT; nt++) {
            uint32_t b[2];
            ldmB(b, bU + (kt*16 + bRow)*bpad + nt*16);
            mma16816(acc[0][nt], a0, b);
            mma16816(acc[1][nt], a1, b);
        }
    }
}
__device__ void prepB(char* dst, int tid, const float* __restrict__ g,
                      int K, int Kpad, int N, int bpad) {
    for (int t = tid; t < K*N; t += BDIM) {
        int k = t / N, n = t - k*N;
        float w = g[t];
        __nv_bfloat16 h = __float2bfloat16(w);
        __nv_bfloat16 m = __float2bfloat16(w - __bfloat162float(h));
        *(__nv_bfloat16*)(dst + k*bpad + n*2) = h;
        *(__nv_bfloat16*)(dst + (Kpad+k)*bpad + n*2) = h;
        *(__nv_bfloat16*)(dst + (2*Kpad+k)*bpad + n*2) = m;
    }
}

/* -------- sort pre-pass + pooling -------- */
__global__ void zero_hist_kernel() {
    int s = gridDim.x*blockDim.x;
    for (int i = blockIdx.x*blockDim.x + threadIdx.x; i < BG_; i += s) g_hist[i] = 0;
}
__global__ void index_hist_kernel(const float* __restrict__ p, int T, int N) {
    int i = blockIdx.x*blockDim.x + threadIdx.x;
    if (i >= N) return;
    float p0 = p[3*i+0], p1 = p[3*i+1], p2 = p[3*i+2];
    int b = i / T;
    float pn0 = fminf(fmaxf(__fdiv_rn(p0, 1.101f) + 0.5f, 0.0f), 0.999f);
    float pn1 = fminf(fmaxf(__fdiv_rn(p1, 1.101f) + 0.5f, 0.0f), 0.999f);
    float pn2 = fminf(fmaxf(__fdiv_rn(p2, 1.101f) + 0.5f, 0.0f), 0.999f);
    int gidx = (int)floorf(pn0*32.f) + RESO_*((int)floorf(pn1*32.f) + RESO_*(int)floorf(pn2*32.f)) + b*G_;
    g_gidx[i] = gidx;
    atomicAdd(&g_hist[gidx], 1);
}
__global__ void scan_kernel() {
    __shared__ int part[1024];
    int t = threadIdx.x, base = t*64, s = 0;
#pragma unroll
    for (int j = 0; j < 64; j++) s += g_hist[base+j];
    part[t] = s; __syncthreads();
    for (int off = 1; off < 1024; off <<= 1) {
        int v = (t >= off) ? part[t-off] : 0;
        __syncthreads(); part[t] += v; __syncthreads();
    }
    int run = (t == 0) ? 0 : part[t-1];
#pragma unroll
    for (int j = 0; j < 64; j++) {
        int c = g_hist[base+j];
        g_start[base+j] = run; g_cursor[base+j] = run; run += c;
    }
}
__global__ void perm_kernel(const float* __restrict__ p, int N) {
    int i = blockIdx.x*blockDim.x + threadIdx.x;
    if (i >= N) return;
    int gidx = g_gidx[i];
    int slot = atomicAdd(&g_cursor[gidx], 1);
    g_sgidx[slot] = gidx;
    g_psort[(size_t)slot*3+0] = p[3*i+0];
    g_psort[(size_t)slot*3+1] = p[3*i+1];
    g_psort[(size_t)slot*3+2] = p[3*i+2];
}
__global__ void maxpool_kernel(float* __restrict__ dst) {
    int t = blockIdx.x*blockDim.x + threadIdx.x;
    if (t >= BG_*8) return;
    int cell = t >> 3, q = (t & 7) * 4;
    int s = g_start[cell], n = g_hist[cell];
    float4 m = make_float4(0.f, 0.f, 0.f, 0.f);
    if (n > 0) {
        m = *reinterpret_cast<const float4*>(&g_net[(size_t)s*HID_ + q]);
        for (int k = 1; k < n; k++) {
            float4 v = *reinterpret_cast<const float4*>(&g_net[(size_t)(s+k)*HID_ + q]);
            m.x = fmaxf(m.x, v.x); m.y = fmaxf(m.y, v.y);
            m.z = fmaxf(m.z, v.z); m.w = fmaxf(m.w, v.w);
        }
    }
    *reinterpret_cast<float4*>(&dst[cell*HID_ + q]) = m;
}

/* -------- stage 0 (one-wave persistent) -------- */
__global__ void __launch_bounds__(BDIM) point0_kernel(
    const float* __restrict__ Wp, const float* __restrict__ Bp,
    const float* __restrict__ w0, const float* __restrict__ b0g,
    const float* __restrict__ w1, const float* __restrict__ b1g,
    const float* __restrict__ ws, int N)
{
    extern __shared__ __align__(16) char sm[];
    uint32_t su = smem_u32(sm);
    int tid = threadIdx.x, wid = tid >> 5, lane = tid & 31;
    for (int t = tid; t < 27648/4; t += BDIM) ((uint32_t*)(sm + O_WP))[t] = 0;
    __syncthreads();
    prepB(sm+O_WP, tid, Wp, 60, 64, 64, BP64);
    prepB(sm+P_W0, tid, w0, 64, 64, 32, BP32);
    prepB(sm+P_WS, tid, ws, 64, 64, 32, BP32);
    prepB(sm+P_W1, tid, w1, 32, 32, 32, BP32);
    if (tid < 32) { ((float*)(sm+P_SB0))[tid] = b0g[tid]; ((float*)(sm+P_SB1))[tid] = b1g[tid]; }
    if (tid < 64) ((float*)(sm+P_SBP))[tid] = Bp[tid];
    __syncthreads();
    const float* b0 = (const float*)(sm+P_SB0);
    const float* b1 = (const float*)(sm+P_SB1);
    const float* sbp = (const float*)(sm+P_SBP);

    int nTiles = (N + BDIM - 1) / BDIM;
    for (int tile = blockIdx.x; tile < nTiles; tile += gridDim.x) {
        int ctaBase = tile*BDIM;
        int slot = ctaBase + tid;
        float p0 = 0.f, p1 = 0.f, p2 = 0.f;
        if (slot < N) { p0 = g_psort[(size_t)slot*3]; p1 = g_psort[(size_t)slot*3+1]; p2 = g_psort[(size_t)slot*3+2]; }
        float pe[64];
#pragma unroll
        for (int j = 60; j < 64; j++) pe[j] = 0.f;
        float q[3] = {2.f*p0-1.f, 2.f*p1-1.f, 2.f*p2-1.f};
#pragma unroll
        for (int d = 0; d < 3; d++) {
            float y = q[d];
#pragma unroll 1
            for (int l = 0; l < 10; l++) {
                float s, c; sincospif(y, &s, &c);
                pe[l*6+d] = s; pe[l*6+3+d] = c;
                y *= 2.f;
            }
        }
        writeRow64(sm+O_A, tid, pe, false);
        __syncwarp();
        float accX[2][8][4] = {};
        warp_gemm<12,8>(su+O_A, su+O_WP, BP64, wid, lane, accX);
        __syncwarp();
        fragToA<8>(sm+O_A, wid, lane, accX, sbp, true);
        __syncwarp();
        float accH[2][4][4] = {};
        warp_gemm<12,4>(su+O_A, su+P_W0, BP32, wid, lane, accH);
        __syncwarp();
        fragToA<8>(sm+O_A, wid, lane, accX, sbp, false);
        __syncwarp();
        float accO[2][4][4] = {};
        warp_gemm<12,4>(su+O_A, su+P_WS, BP32, wid, lane, accO);
        __syncwarp();
        fragToA<4>(sm+O_A, wid, lane, accH, b0, true);
        __syncwarp();
        warp_gemm<6,4>(su+O_A, su+P_W1, BP32, wid, lane, accO);
        fragStore(ctaBase, N, wid, lane, accO, b1);
        __syncwarp();
    }
}

/* -------- stages 1..3 (one-wave persistent) -------- */
__global__ void __launch_bounds__(BDIM) pool_block_kernel(
    const float* __restrict__ w0, const float* __restrict__ b0g,
    const float* __restrict__ w1, const float* __restrict__ b1g,
    const float* __restrict__ ws, const float* __restrict__ cellSrc, int N)
{
    extern __shared__ __align__(16) char sm[];
    uint32_t su = smem_u32(sm);
    int tid = threadIdx.x, wid = tid >> 5, lane = tid & 31;
    prepB(sm+O_W0, tid, w0, 64, 64, 32, BP32);
    prepB(sm+O_WS, tid, ws, 64, 64, 32, BP32);
    prepB(sm+O_W1, tid, w1, 32, 32, 32, BP32);
    if (tid < 32) { ((float*)(sm+O_SB0))[tid] = b0g[tid]; ((float*)(sm+O_SB1))[tid] = b1g[tid]; }
    __syncthreads();
    const float* b0 = (const float*)(sm+O_SB0);
    const float* b1 = (const float*)(sm+O_SB1);

    int nTiles = (N + BDIM - 1) / BDIM;
    for (int tile = blockIdx.x; tile < nTiles; tile += gridDim.x) {
        int ctaBase = tile*BDIM;
        int slot = ctaBase + tid;
        float x[64];
        if (slot < N) {
            int gidx = g_sgidx[slot];
            const float4* np = (const float4*)&g_net[(size_t)slot*HID_];
            const float4* pp = (const float4*)&cellSrc[gidx*HID_];
#pragma unroll
            for (int j = 0; j < 8; j++) {
                float4 a = np[j]; x[4*j]=a.x; x[4*j+1]=a.y; x[4*j+2]=a.z; x[4*j+3]=a.w;
                float4 pb = pp[j]; x[32+4*j]=pb.x; x[32+4*j+1]=pb.y; x[32+4*j+2]=pb.z; x[32+4*j+3]=pb.w;
            }
        } else {
#pragma unroll
            for (int j = 0; j < 64; j++) x[j] = 0.f;
        }
        writeRow64(sm+O_A, tid, x, true);
        __syncwarp();
        float accH[2][4][4] = {};
        warp_gemm<12,4>(su+O_A, su+O_W0, BP32, wid, lane, accH);
        __syncwarp();
        writeRow64(sm+O_A, tid, x, false);
        __syncwarp();
        float accO[2][4][4] = {};
        warp_gemm<12,4>(su+O_A, su+O_WS, BP32, wid, lane, accO);
        __syncwarp();
        fragToA<4>(sm+O_A, wid, lane, accH, b0, true);
        __syncwarp();
        warp_gemm<6,4>(su+O_A, su+O_W1, BP32, wid, lane, accO);
        fragStore(ctaBase, N, wid, lane, accO, b1);
        __syncwarp();
    }
}

/* -------- stage 4 + fc_c (one-wave persistent) -------- */
__global__ void __launch_bounds__(BDIM) final_kernel(
    const float* __restrict__ w0, const float* __restrict__ b0g,
    const float* __restrict__ w1, const float* __restrict__ b1g,
    const float* __restrict__ ws,
    const float* __restrict__ fcw, const float* __restrict__ fcb,
    const float* __restrict__ cellSrc, int N)
{
    extern __shared__ __align__(16) char sm[];
    uint32_t su = smem_u32(sm);
    int tid = threadIdx.x, wid = tid >> 5, lane = tid & 31;
    prepB(sm+O_W0, tid, w0, 64, 64, 32, BP32);
    prepB(sm+O_WS, tid, ws, 64, 64, 32, BP32);
    prepB(sm+O_W1, tid, w1, 32, 32, 32, BP32);
    prepB(sm+O_FC, tid, fcw, 32, 32, 32, BP32);
    if (tid < 32) {
        ((float*)(sm+O_SB0))[tid] = b0g[tid];
        ((float*)(sm+O_SB1))[tid] = b1g[tid];
        ((float*)(sm+O_SFB))[tid] = fcb[tid];
    }
    __syncthreads();
    const float* b0 = (const float*)(sm+O_SB0);
    const float* b1 = (const float*)(sm+O_SB1);
    const float* sfb = (const float*)(sm+O_SFB);

    int nTiles = (N + BDIM - 1) / BDIM;
    for (int tile = blockIdx.x; tile < nTiles; tile += gridDim.x) {
        int ctaBase = tile*BDIM;
        int slot = ctaBase + tid;
        float x[64];
        if (slot < N) {
            int gidx = g_sgidx[slot];
            const float4* np = (const float4*)&g_net[(size_t)slot*HID_];
            const float4* pp = (const float4*)&cellSrc[gidx*HID_];
#pragma unroll
            for (int j = 0; j < 8; j++) {
                float4 a = np[j]; x[4*j]=a.x; x[4*j+1]=a.y; x[4*j+2]=a.z; x[4*j+3]=a.w;
                float4 pb = pp[j]; x[32+4*j]=pb.x; x[32+4*j+1]=pb.y; x[32+4*j+2]=pb.z; x[32+4*j+3]=pb.w;
            }
        } else {
#pragma unroll
            for (int j = 0; j < 64; j++) x[j] = 0.f;
        }
        writeRow64(sm+O_A, tid, x, true);
        __syncwarp();
        float accH[2][4][4] = {};
        warp_gemm<12,4>(su+O_A, su+O_W0, BP32, wid, lane, accH);
        __syncwarp();
        writeRow64(sm+O_A, tid, x, false);
        __syncwarp();
        float accO[2][4][4] = {};
        warp_gemm<12,4>(su+O_A, su+O_WS, BP32, wid, lane, accO);
        __syncwarp();
        fragToA<4>(sm+O_A, wid, lane, accH, b0, true);
        __syncwarp();
        warp_gemm<6,4>(su+O_A, su+O_W1, BP32, wid, lane, accO);
        __syncwarp();
        fragToA<4>(sm+O_A, wid, lane, accO, b1, false);
        __syncwarp();
        float accC[2][4][4] = {};
        warp_gemm<6,4>(su+O_A, su+O_FC, BP32, wid, lane, accC);
        fragStore(ctaBase, N, wid, lane, accC, sfb);
        __syncwarp();
    }
}

/* -------- output: CSR mean + transpose -------- */
__global__ void output_kernel(float* __restrict__ out, int total) {
    int t = blockIdx.x*blockDim.x + threadIdx.x;
    if (t >= total) return;
    int bg = t >> 5, ch = t & 31;
    int s = g_start[bg], n = g_hist[bg];
    float sum = 0.0f;
    for (int k = 0; k < n; k++) sum += g_net[(size_t)(s+k)*HID_ + ch];
    float mean = sum / fmaxf((float)n, 1.0f);
    int b = bg >> 15, g = bg & (G_ - 1);
    out[((size_t)b*HID_ + ch)*G_ + g] = mean;
}

/* -------- host -------- */
extern "C" void kernel_launch(void* const* d_in, const int* in_sizes, int n_in,
                              void* d_out, int out_size) {
    const float* p   = (const float*)d_in[0];
    const float* Wp  = (const float*)d_in[1];
    const float* Bp  = (const float*)d_in[2];
    const float* W0  = (const float*)d_in[3];
    const float* B0  = (const float*)d_in[4];
    const float* W1  = (const float*)d_in[5];
    const float* B1  = (const float*)d_in[6];
    const float* Ws  = (const float*)d_in[7];
    const float* Fc  = (const float*)d_in[8];
    const float* FcB = (const float*)d_in[9];
    float* out = (float*)d_out;

    int T = in_sizes[0] / (B_ * 3);
    int N = B_ * T;
    int nbp = (N + BDIM - 1) / BDIM;
    int nTiles = nbp;
    int nbPool = nTiles < MAXCTA ? nTiles : MAXCTA;       /* 2 CTA/SM */
    int nbP0   = nTiles < 148 ? nTiles : 148;             /* 1 CTA/SM */

    cudaFuncSetAttribute(point0_kernel, cudaFuncAttributeMaxDynamicSharedMemorySize, SM_P0);
    cudaFuncSetAttribute(pool_block_kernel, cudaFuncAttributeMaxDynamicSharedMemorySize, SM_POOL);
    cudaFuncSetAttribute(final_kernel, cudaFuncAttributeMaxDynamicSharedMemorySize, SM_FIN);

    float* cellA; cudaGetSymbolAddress((void**)&cellA, g_cellA);
    float* cellB; cudaGetSymbolAddress((void**)&cellB, g_cellB);

    zero_hist_kernel<<<64, 256>>>();
    index_hist_kernel<<<nbp, BDIM>>>(p, T, N);
    scan_kernel<<<1, 1024>>>();
    perm_kernel<<<nbp, BDIM>>>(p, N);

    point0_kernel<<<nbP0, BDIM, SM_P0>>>(Wp, Bp, W0, B0, W1, B1, Ws, N);
    maxpool_kernel<<<BG_*8/256, 256>>>(cellA);

    pool_block_kernel<<<nbPool, BDIM, SM_POOL>>>(W0 + 1*64*HID_, B0 + 1*HID_,
        W1 + 1*HID_*HID_, B1 + 1*HID_, Ws + 1*64*HID_, cellA, N);
    maxpool_kernel<<<BG_*8/256, 256>>>(cellB);

    pool_block_kernel<<<nbPool, BDIM, SM_POOL>>>(W0 + 2*64*HID_, B0 + 2*HID_,
        W1 + 2*HID_*HID_, B1 + 2*HID_, Ws + 2*64*HID_, cellB, N);
    maxpool_kernel<<<BG_*8/256, 256>>>(cellA);

    pool_block_kernel<<<nbPool, BDIM, SM_POOL>>>(W0 + 3*64*HID_, B0 + 3*HID_,
        W1 + 3*HID_*HID_, B1 + 3*HID_, Ws + 3*64*HID_, cellA, N);
    maxpool_kernel<<<BG_*8/256, 256>>>(cellB);

    final_kernel<<<nbPool, BDIM, SM_FIN>>>(W0 + 4*64*HID_, B0 + 4*HID_,
        W1 + 4*HID_*HID_, B1 + 4*HID_, Ws + 4*64*HID_, Fc, FcB, cellB, N);

    output_kernel<<<(out_size + 255)/256, 256>>>(out, out_size);
}

// round 12
// speedup vs baseline: 1.7805x; 1.1229x over previous
#include <cuda_runtime.h>
#include <cuda_bf16.h>
#include <math.h>
#include <stdint.h>

#define B_ 2
#define RESO_ 32
#define G_ 32768
#define BG_ 65536
#define HID_ 32
#define NMAX_ 524288
#define BDIM 256
#define MTILE 256
#define APAD 400
#define BP32 80
#define BP64 144
#define MAXCTA 148

#define O_A   0
#define O_W0  102400
#define O_WS  117760
#define O_W1  133120
#define O_SB0 140800
#define O_SB1 140928
#define SM_POOL 141056
#define O_FC  141056
#define O_SFB 148736
#define SM_FIN 148864
#define O_WP  102400
#define P_W0  130048
#define P_WS  145408
#define P_W1  160768
#define P_SB0 168448
#define P_SB1 168576
#define P_SBP 168704
#define SM_P0 168960

/* -------- scratch -------- */
__device__ float g_net[(size_t)NMAX_*HID_];
__device__ float g_psort[(size_t)NMAX_*3];
__device__ int   g_gidx[NMAX_];
__device__ int   g_sgidx[NMAX_];
__device__ int   g_hist[BG_];
__device__ int   g_start[BG_];
__device__ int   g_cursor[BG_];
__device__ float g_cellA[BG_*HID_];
__device__ float g_cellB[BG_*HID_];

/* -------- helpers -------- */
__device__ __forceinline__ uint32_t smem_u32(const void* p) {
    uint32_t a;
    asm("{ .reg .u64 t; cvta.to.shared.u64 t, %1; cvt.u32.u64 %0, t; }" : "=r"(a) : "l"(p));
    return a;
}
__device__ __forceinline__ void ldmA(uint32_t a[4], uint32_t addr) {
    asm volatile("ldmatrix.sync.aligned.m8n8.x4.shared.b16 {%0,%1,%2,%3}, [%4];"
        : "=r"(a[0]), "=r"(a[1]), "=r"(a[2]), "=r"(a[3]) : "r"(addr));
}
__device__ __forceinline__ void ldmB(uint32_t b[2], uint32_t addr) {
    asm volatile("ldmatrix.sync.aligned.m8n8.x2.trans.shared.b16 {%0,%1}, [%2];"
        : "=r"(b[0]), "=r"(b[1]) : "r"(addr));
}
__device__ __forceinline__ void mma16816(float d[4], const uint32_t a[4], const uint32_t b[2]) {
    asm volatile("mma.sync.aligned.m16n8k16.row.col.f32.bf16.bf16.f32 "
        "{%0,%1,%2,%3},{%4,%5,%6,%7},{%8,%9},{%0,%1,%2,%3};"
        : "+f"(d[0]), "+f"(d[1]), "+f"(d[2]), "+f"(d[3])
        : "r"(a[0]), "r"(a[1]), "r"(a[2]), "r"(a[3]), "r"(b[0]), "r"(b[1]));
}
__device__ __forceinline__ void hm(float a, float b, uint32_t& H, uint32_t& M) {
    __nv_bfloat16 h0 = __float2bfloat16(a), h1 = __float2bfloat16(b);
    uint16_t u0 = *reinterpret_cast<uint16_t*>(&h0), u1 = *reinterpret_cast<uint16_t*>(&h1);
    H = ((uint32_t)u1 << 16) | u0;
    __nv_bfloat162 m = __floats2bfloat162_rn(a - __bfloat162float(h0), b - __bfloat162float(h1));
    M = *reinterpret_cast<uint32_t*>(&m);
}
__device__ __forceinline__ void writeRow64(char* A, int row, const float* v, bool dorelu) {
    char* base = A + row*APAD;
#pragma unroll
    for (int g = 0; g < 8; g++) {
        uint32_t H[4], M[4];
#pragma unroll
        for (int j = 0; j < 4; j++) {
            float a = v[8*g+2*j], b = v[8*g+2*j+1];
            if (dorelu) { a = fmaxf(a, 0.f); b = fmaxf(b, 0.f); }
            hm(a, b, H[j], M[j]);
        }
        *(uint4*)(base + g*16)       = make_uint4(H[0], H[1], H[2], H[3]);
        *(uint4*)(base + 128 + g*16) = make_uint4(M[0], M[1], M[2], M[3]);
        *(uint4*)(base + 256 + g*16) = make_uint4(H[0], H[1], H[2], H[3]);
    }
}
template<int NT>
__device__ __forceinline__ void fragToA(char* A, int wid, int lane,
                                        float acc[2][NT][4], const float* bias, bool dorelu) {
    const int K2 = NT*16, K4 = NT*32;
    int r0 = wid*32 + (lane >> 2);
    int cb = (lane & 3)*2;
#pragma unroll
    for (int mt = 0; mt < 2; mt++)
#pragma unroll
    for (int half = 0; half < 2; half++) {
        char* base = A + (r0 + mt*16 + half*8)*APAD;
#pragma unroll
        for (int nt = 0; nt < NT; nt++) {
            int c = nt*8 + cb;
            float v0 = acc[mt][nt][half*2+0] + bias[c];
            float v1 = acc[mt][nt][half*2+1] + bias[c+1];
            if (dorelu) { v0 = fmaxf(v0, 0.f); v1 = fmaxf(v1, 0.f); }
            uint32_t H, M; hm(v0, v1, H, M);
            *(uint32_t*)(base + c*2)      = H;
            *(uint32_t*)(base + K2 + c*2) = M;
            *(uint32_t*)(base + K4 + c*2) = H;
        }
    }
}
__device__ __forceinline__ void fragStore(int ctaBase, int N, int wid, int lane,
                                          float acc[2][4][4], const float* bias) {
    int r0 = wid*32 + (lane >> 2);
    int cb = (lane & 3)*2;
#pragma unroll
    for (int mt = 0; mt < 2; mt++)
#pragma unroll
    for (int half = 0; half < 2; half++) {
        int slot = ctaBase + r0 + mt*16 + half*8;
        if (slot < N) {
            float* g = &g_net[(size_t)slot*HID_];
#pragma unroll
            for (int nt = 0; nt < 4; nt++) {
                int c = nt*8 + cb;
                *(float2*)(g + c) = make_float2(acc[mt][nt][half*2] + bias[c],
                                                acc[mt][nt][half*2+1] + bias[c+1]);
            }
        }
    }
}
template<int KT, int NT>
__device__ __forceinline__ void warp_gemm(uint32_t aU, uint32_t bU, int bpad,
                                          int wid, int lane, float acc[2][NT][4]) {
    uint32_t aAddr = aU + (uint32_t)(wid*32 + (lane & 15))*APAD + (uint32_t)((lane & 16) ? 16 : 0);
    uint32_t bRow = (uint32_t)(lane & 15);
#pragma unroll
    for (int kt = 0; kt < KT; kt++) {
        uint32_t a0[4], a1[4];
        ldmA(a0, aAddr + kt*32);
        ldmA(a1, aAddr + kt*32 + 16*APAD);
#pragma unroll
        for (int nt = 0; nt < NT; nt++) {
            uint32_t b[2];
            ldmB(b, bU + (kt*16 + bRow)*bpad + nt*16);
            mma16816(acc[0][nt], a0, b);
            mma16816(acc[1][nt], a1, b);
        }
    }
}
__device__ void prepB(char* dst, int tid, const float* __restrict__ g,
                      int K, int Kpad, int N, int bpad) {
    for (int t = tid; t < K*N; t += BDIM) {
        int k = t / N, n = t - k*N;
        float w = g[t];
        __nv_bfloat16 h = __float2bfloat16(w);
        __nv_bfloat16 m = __float2bfloat16(w - __bfloat162float(h));
        *(__nv_bfloat16*)(dst + k*bpad + n*2) = h;
        *(__nv_bfloat16*)(dst + (Kpad+k)*bpad + n*2) = h;
        *(__nv_bfloat16*)(dst + (2*Kpad+k)*bpad + n*2) = m;
    }
}

/* -------- sort pre-pass + pooling -------- */
__global__ void zero_hist_kernel() {
    int s = gridDim.x*blockDim.x;
    for (int i = blockIdx.x*blockDim.x + threadIdx.x; i < BG_; i += s) g_hist[i] = 0;
}
__global__ void index_hist_kernel(const float* __restrict__ p, int T, int N) {
    int i = blockIdx.x*blockDim.x + threadIdx.x;
    if (i >= N) return;
    float p0 = p[3*i+0], p1 = p[3*i+1], p2 = p[3*i+2];
    int b = i / T;
    float pn0 = fminf(fmaxf(__fdiv_rn(p0, 1.101f) + 0.5f, 0.0f), 0.999f);
    float pn1 = fminf(fmaxf(__fdiv_rn(p1, 1.101f) + 0.5f, 0.0f), 0.999f);
    float pn2 = fminf(fmaxf(__fdiv_rn(p2, 1.101f) + 0.5f, 0.0f), 0.999f);
    int gidx = (int)floorf(pn0*32.f) + RESO_*((int)floorf(pn1*32.f) + RESO_*(int)floorf(pn2*32.f)) + b*G_;
    g_gidx[i] = gidx;
    atomicAdd(&g_hist[gidx], 1);
}
__global__ void scan_kernel() {
    __shared__ int part[1024];
    int t = threadIdx.x, base = t*64, s = 0;
#pragma unroll
    for (int j = 0; j < 64; j++) s += g_hist[base+j];
    part[t] = s; __syncthreads();
    for (int off = 1; off < 1024; off <<= 1) {
        int v = (t >= off) ? part[t-off] : 0;
        __syncthreads(); part[t] += v; __syncthreads();
    }
    int run = (t == 0) ? 0 : part[t-1];
#pragma unroll
    for (int j = 0; j < 64; j++) {
        int c = g_hist[base+j];
        g_start[base+j] = run; g_cursor[base+j] = run; run += c;
    }
}
__global__ void perm_kernel(const float* __restrict__ p, int N) {
    int i = blockIdx.x*blockDim.x + threadIdx.x;
    if (i >= N) return;
    int gidx = g_gidx[i];
    int slot = atomicAdd(&g_cursor[gidx], 1);
    g_sgidx[slot] = gidx;
    g_psort[(size_t)slot*3+0] = p[3*i+0];
    g_psort[(size_t)slot*3+1] = p[3*i+1];
    g_psort[(size_t)slot*3+2] = p[3*i+2];
}
__global__ void maxpool_kernel(float* __restrict__ dst) {
    int t = blockIdx.x*blockDim.x + threadIdx.x;
    if (t >= BG_*8) return;
    int cell = t >> 3, q = (t & 7) * 4;
    int s = g_start[cell], n = g_hist[cell];
    float4 m = make_float4(0.f, 0.f, 0.f, 0.f);
    if (n > 0) {
        m = *reinterpret_cast<const float4*>(&g_net[(size_t)s*HID_ + q]);
        for (int k = 1; k < n; k++) {
            float4 v = *reinterpret_cast<const float4*>(&g_net[(size_t)(s+k)*HID_ + q]);
            m.x = fmaxf(m.x, v.x); m.y = fmaxf(m.y, v.y);
            m.z = fmaxf(m.z, v.z); m.w = fmaxf(m.w, v.w);
        }
    }
    *reinterpret_cast<float4*>(&dst[cell*HID_ + q]) = m;
}

/* -------- stage 0 (persistent, M=256) -------- */
__global__ void __launch_bounds__(BDIM) point0_kernel(
    const float* __restrict__ Wp, const float* __restrict__ Bp,
    const float* __restrict__ w0, const float* __restrict__ b0g,
    const float* __restrict__ w1, const float* __restrict__ b1g,
    const float* __restrict__ ws, int N)
{
    extern __shared__ __align__(16) char sm[];
    uint32_t su = smem_u32(sm);
    int tid = threadIdx.x, wid = tid >> 5, lane = tid & 31;
    for (int t = tid; t < 27648/4; t += BDIM) ((uint32_t*)(sm + O_WP))[t] = 0;
    __syncthreads();
    prepB(sm+O_WP, tid, Wp, 60, 64, 64, BP64);
    prepB(sm+P_W0, tid, w0, 64, 64, 32, BP32);
    prepB(sm+P_WS, tid, ws, 64, 64, 32, BP32);
    prepB(sm+P_W1, tid, w1, 32, 32, 32, BP32);
    if (tid < 32) { ((float*)(sm+P_SB0))[tid] = b0g[tid]; ((float*)(sm+P_SB1))[tid] = b1g[tid]; }
    if (tid >= 64 && tid < 128) ((float*)(sm+P_SBP))[tid-64] = Bp[tid-64];
    __syncthreads();
    const float* b0 = (const float*)(sm+P_SB0);
    const float* b1 = (const float*)(sm+P_SB1);
    const float* sbp = (const float*)(sm+P_SBP);

    int nTiles = (N + MTILE - 1) / MTILE;
    for (int tile = blockIdx.x; tile < nTiles; tile += gridDim.x) {
        int ctaBase = tile*MTILE;
        int slot = ctaBase + tid;
        float p0 = 0.f, p1 = 0.f, p2 = 0.f;
        if (slot < N) { p0 = g_psort[(size_t)slot*3]; p1 = g_psort[(size_t)slot*3+1]; p2 = g_psort[(size_t)slot*3+2]; }
        float pe[64];
#pragma unroll
        for (int j = 60; j < 64; j++) pe[j] = 0.f;
        float q[3] = {2.f*p0-1.f, 2.f*p1-1.f, 2.f*p2-1.f};
#pragma unroll
        for (int d = 0; d < 3; d++) {
            float y = q[d];
#pragma unroll 1
            for (int l = 0; l < 10; l++) {
                float s, c; sincospif(y, &s, &c);
                pe[l*6+d] = s; pe[l*6+3+d] = c;
                y *= 2.f;
            }
        }
        writeRow64(sm+O_A, tid, pe, false);
        __syncwarp();
        float accX[2][8][4] = {};
        warp_gemm<12,8>(su+O_A, su+O_WP, BP64, wid, lane, accX);
        __syncwarp();
        fragToA<8>(sm+O_A, wid, lane, accX, sbp, true);
        __syncwarp();
        float accH[2][4][4] = {};
        warp_gemm<12,4>(su+O_A, su+P_W0, BP32, wid, lane, accH);
        __syncwarp();
        fragToA<8>(sm+O_A, wid, lane, accX, sbp, false);
        __syncwarp();
        float accO[2][4][4] = {};
        warp_gemm<12,4>(su+O_A, su+P_WS, BP32, wid, lane, accO);
        __syncwarp();
        fragToA<4>(sm+O_A, wid, lane, accH, b0, true);
        __syncwarp();
        warp_gemm<6,4>(su+O_A, su+P_W1, BP32, wid, lane, accO);
        fragStore(ctaBase, N, wid, lane, accO, b1);
        __syncwarp();
    }
}

/* -------- stages 1..3 (persistent, M=256) -------- */
__global__ void __launch_bounds__(BDIM) pool_block_kernel(
    const float* __restrict__ w0, const float* __restrict__ b0g,
    const float* __restrict__ w1, const float* __restrict__ b1g,
    const float* __restrict__ ws, const float* __restrict__ cellSrc, int N)
{
    extern __shared__ __align__(16) char sm[];
    uint32_t su = smem_u32(sm);
    int tid = threadIdx.x, wid = tid >> 5, lane = tid & 31;
    prepB(sm+O_W0, tid, w0, 64, 64, 32, BP32);
    prepB(sm+O_WS, tid, ws, 64, 64, 32, BP32);
    prepB(sm+O_W1, tid, w1, 32, 32, 32, BP32);
    if (tid < 32) { ((float*)(sm+O_SB0))[tid] = b0g[tid]; ((float*)(sm+O_SB1))[tid] = b1g[tid]; }
    __syncthreads();
    const float* b0 = (const float*)(sm+O_SB0);
    const float* b1 = (const float*)(sm+O_SB1);

    int nTiles = (N + MTILE - 1) / MTILE;
    for (int tile = blockIdx.x; tile < nTiles; tile += gridDim.x) {
        int ctaBase = tile*MTILE;
        int slot = ctaBase + tid;
        float x[64];
        if (slot < N) {
            int gidx = g_sgidx[slot];
            const float4* np = (const float4*)&g_net[(size_t)slot*HID_];
            const float4* pp = (const float4*)&cellSrc[gidx*HID_];
#pragma unroll
            for (int j = 0; j < 8; j++) {
                float4 a = np[j]; x[4*j]=a.x; x[4*j+1]=a.y; x[4*j+2]=a.z; x[4*j+3]=a.w;
                float4 pb = pp[j]; x[32+4*j]=pb.x; x[32+4*j+1]=pb.y; x[32+4*j+2]=pb.z; x[32+4*j+3]=pb.w;
            }
        } else {
#pragma unroll
            for (int j = 0; j < 64; j++) x[j] = 0.f;
        }
        writeRow64(sm+O_A, tid, x, true);
        __syncwarp();
        float accH[2][4][4] = {};
        warp_gemm<12,4>(su+O_A, su+O_W0, BP32, wid, lane, accH);
        __syncwarp();
        writeRow64(sm+O_A, tid, x, false);
        __syncwarp();
        float accO[2][4][4] = {};
        warp_gemm<12,4>(su+O_A, su+O_WS, BP32, wid, lane, accO);
        __syncwarp();
        fragToA<4>(sm+O_A, wid, lane, accH, b0, true);
        __syncwarp();
        warp_gemm<6,4>(su+O_A, su+O_W1, BP32, wid, lane, accO);
        fragStore(ctaBase, N, wid, lane, accO, b1);
        __syncwarp();
    }
}

/* -------- stage 4 + fc_c (persistent, M=256) -------- */
__global__ void __launch_bounds__(BDIM) final_kernel(
    const float* __restrict__ w0, const float* __restrict__ b0g,
    const float* __restrict__ w1, const float* __restrict__ b1g,
    const float* __restrict__ ws,
    const float* __restrict__ fcw, const float* __restrict__ fcb,
    const float* __restrict__ cellSrc, int N)
{
    extern __shared__ __align__(16) char sm[];
    uint32_t su = smem_u32(sm);
    int tid = threadIdx.x, wid = tid >> 5, lane = tid & 31;
    prepB(sm+O_W0, tid, w0, 64, 64, 32, BP32);
    prepB(sm+O_WS, tid, ws, 64, 64, 32, BP32);
    prepB(sm+O_W1, tid, w1, 32, 32, 32, BP32);
    prepB(sm+O_FC, tid, fcw, 32, 32, 32, BP32);
    if (tid < 32) {
        ((float*)(sm+O_SB0))[tid] = b0g[tid];
        ((float*)(sm+O_SB1))[tid] = b1g[tid];
        ((float*)(sm+O_SFB))[tid] = fcb[tid];
    }
    __syncthreads();
    const float* b0 = (const float*)(sm+O_SB0);
    const float* b1 = (const float*)(sm+O_SB1);
    const float* sfb = (const float*)(sm+O_SFB);

    int nTiles = (N + MTILE - 1) / MTILE;
    for (int tile = blockIdx.x; tile < nTiles; tile += gridDim.x) {
        int ctaBase = tile*MTILE;
        int slot = ctaBase + tid;
        float x[64];
        if (slot < N) {
            int gidx = g_sgidx[slot];
            const float4* np = (const float4*)&g_net[(size_t)slot*HID_];
            const float4* pp = (const float4*)&cellSrc[gidx*HID_];
#pragma unroll
            for (int j = 0; j < 8; j++) {
                float4 a = np[j]; x[4*j]=a.x; x[4*j+1]=a.y; x[4*j+2]=a.z; x[4*j+3]=a.w;
                float4 pb = pp[j]; x[32+4*j]=pb.x; x[32+4*j+1]=pb.y; x[32+4*j+2]=pb.z; x[32+4*j+3]=pb.w;
            }
        } else {
#pragma unroll
            for (int j = 0; j < 64; j++) x[j] = 0.f;
        }
        writeRow64(sm+O_A, tid, x, true);
        __syncwarp();
        float accH[2][4][4] = {};
        warp_gemm<12,4>(su+O_A, su+O_W0, BP32, wid, lane, accH);
        __syncwarp();
        writeRow64(sm+O_A, tid, x, false);
        __syncwarp();
        float accO[2][4][4] = {};
        warp_gemm<12,4>(su+O_A, su+O_WS, BP32, wid, lane, accO);
        __syncwarp();
        fragToA<4>(sm+O_A, wid, lane, accH, b0, true);
        __syncwarp();
        warp_gemm<6,4>(su+O_A, su+O_W1, BP32, wid, lane, accO);
        __syncwarp();
        fragToA<4>(sm+O_A, wid, lane, accO, b1, false);
        __syncwarp();
        float accC[2][4][4] = {};
        warp_gemm<6,4>(su+O_A, su+O_FC, BP32, wid, lane, accC);
        fragStore(ctaBase, N, wid, lane, accC, sfb);
        __syncwarp();
    }
}

/* -------- output: CSR mean + transpose -------- */
__global__ void output_kernel(float* __restrict__ out, int total) {
    int t = blockIdx.x*blockDim.x + threadIdx.x;
    if (t >= total) return;
    int bg = t >> 5, ch = t & 31;
    int s = g_start[bg], n = g_hist[bg];
    float sum = 0.0f;
    for (int k = 0; k < n; k++) sum += g_net[(size_t)(s+k)*HID_ + ch];
    float mean = sum / fmaxf((float)n, 1.0f);
    int b = bg >> 15, g = bg & (G_ - 1);
    out[((size_t)b*HID_ + ch)*G_ + g] = mean;
}

/* -------- host -------- */
extern "C" void kernel_launch(void* const* d_in, const int* in_sizes, int n_in,
                              void* d_out, int out_size) {
    const float* p   = (const float*)d_in[0];
    const float* Wp  = (const float*)d_in[1];
    const float* Bp  = (const float*)d_in[2];
    const float* W0  = (const float*)d_in[3];
    const float* B0  = (const float*)d_in[4];
    const float* W1  = (const float*)d_in[5];
    const float* B1  = (const float*)d_in[6];
    const float* Ws  = (const float*)d_in[7];
    const float* Fc  = (const float*)d_in[8];
    const float* FcB = (const float*)d_in[9];
    float* out = (float*)d_out;

    int T = in_sizes[0] / (B_ * 3);
    int N = B_ * T;
    int nbp = (N + 255) / 256;
    int nTiles = (N + MTILE - 1) / MTILE;
    int nb = nTiles < MAXCTA ? nTiles : MAXCTA;

    cudaFuncSetAttribute(point0_kernel, cudaFuncAttributeMaxDynamicSharedMemorySize, SM_P0);
    cudaFuncSetAttribute(pool_block_kernel, cudaFuncAttributeMaxDynamicSharedMemorySize, SM_POOL);
    cudaFuncSetAttribute(final_kernel, cudaFuncAttributeMaxDynamicSharedMemorySize, SM_FIN);

    float* cellA; cudaGetSymbolAddress((void**)&cellA, g_cellA);
    float* cellB; cudaGetSymbolAddress((void**)&cellB, g_cellB);

    zero_hist_kernel<<<64, 256>>>();
    index_hist_kernel<<<nbp, 256>>>(p, T, N);
    scan_kernel<<<1, 1024>>>();
    perm_kernel<<<nbp, 256>>>(p, N);

    point0_kernel<<<nb, BDIM, SM_P0>>>(Wp, Bp, W0, B0, W1, B1, Ws, N);
    maxpool_kernel<<<BG_*8/256, 256>>>(cellA);

    pool_block_kernel<<<nb, BDIM, SM_POOL>>>(W0 + 1*64*HID_, B0 + 1*HID_,
        W1 + 1*HID_*HID_, B1 + 1*HID_, Ws + 1*64*HID_, cellA, N);
    maxpool_kernel<<<BG_*8/256, 256>>>(cellB);

    pool_block_kernel<<<nb, BDIM, SM_POOL>>>(W0 + 2*64*HID_, B0 + 2*HID_,
        W1 + 2*HID_*HID_, B1 + 2*HID_, Ws + 2*64*HID_, cellB, N);
    maxpool_kernel<<<BG_*8/256, 256>>>(cellA);

    pool_block_kernel<<<nb, BDIM, SM_POOL>>>(W0 + 3*64*HID_, B0 + 3*HID_,
        W1 + 3*HID_*HID_, B1 + 3*HID_, Ws + 3*64*HID_, cellA, N);
    maxpool_kernel<<<BG_*8/256, 256>>>(cellB);

    final_kernel<<<nb, BDIM, SM_FIN>>>(W0 + 4*64*HID_, B0 + 4*HID_,
        W1 + 4*HID_*HID_, B1 + 4*HID_, Ws + 4*64*HID_, Fc, FcB, cellB, N);

    output_kernel<<<(out_size + 255)/256, 256>>>(out, out_size);
}

// round 13
// speedup vs baseline: 1.8022x; 1.0122x over previous
#include <cuda_runtime.h>
#include <cuda_bf16.h>
#include <math.h>
#include <stdint.h>

#define B_ 2
#define RESO_ 32
#define G_ 32768
#define BG_ 65536
#define HID_ 32
#define NMAX_ 524288
#define BDIM 256
#define MTILE 256
#define APAD 272
#define BP32 80
#define BP64 144
#define MAXCTA 296

/* pool: A 69632 */
#define O_A   0
#define O_W0  69632
#define O_WS  79872
#define O_W1  90112
#define O_SB0 95232
#define O_SB1 95360
#define SM_POOL 95488
#define O_FC  95488
#define O_SFB 100608
#define SM_FIN 100736
#define O_WP  69632
#define P_W0  88064
#define P_WS  98304
#define P_W1  108544
#define P_SB0 113664
#define P_SB1 113792
#define P_SBP 113920
#define SM_P0 114176

/* -------- scratch -------- */
__device__ float g_net[(size_t)NMAX_*HID_];
__device__ float g_psort[(size_t)NMAX_*3];
__device__ int   g_gidx[NMAX_];
__device__ int   g_sgidx[NMAX_];
__device__ int   g_hist[BG_];
__device__ int   g_start[BG_];
__device__ int   g_cursor[BG_];
__device__ float g_cellA[BG_*HID_];
__device__ float g_cellB[BG_*HID_];

/* -------- helpers -------- */
__device__ __forceinline__ uint32_t smem_u32(const void* p) {
    uint32_t a;
    asm("{ .reg .u64 t; cvta.to.shared.u64 t, %1; cvt.u32.u64 %0, t; }" : "=r"(a) : "l"(p));
    return a;
}
__device__ __forceinline__ void ldmA(uint32_t a[4], uint32_t addr) {
    asm volatile("ldmatrix.sync.aligned.m8n8.x4.shared.b16 {%0,%1,%2,%3}, [%4];"
        : "=r"(a[0]), "=r"(a[1]), "=r"(a[2]), "=r"(a[3]) : "r"(addr));
}
__device__ __forceinline__ void ldmB(uint32_t b[2], uint32_t addr) {
    asm volatile("ldmatrix.sync.aligned.m8n8.x2.trans.shared.b16 {%0,%1}, [%2];"
        : "=r"(b[0]), "=r"(b[1]) : "r"(addr));
}
__device__ __forceinline__ void mma16816(float d[4], const uint32_t a[4], const uint32_t b[2]) {
    asm volatile("mma.sync.aligned.m16n8k16.row.col.f32.bf16.bf16.f32 "
        "{%0,%1,%2,%3},{%4,%5,%6,%7},{%8,%9},{%0,%1,%2,%3};"
        : "+f"(d[0]), "+f"(d[1]), "+f"(d[2]), "+f"(d[3])
        : "r"(a[0]), "r"(a[1]), "r"(a[2]), "r"(a[3]), "r"(b[0]), "r"(b[1]));
}
__device__ __forceinline__ void hm(float a, float b, uint32_t& H, uint32_t& M) {
    __nv_bfloat16 h0 = __float2bfloat16(a), h1 = __float2bfloat16(b);
    uint16_t u0 = *reinterpret_cast<uint16_t*>(&h0), u1 = *reinterpret_cast<uint16_t*>(&h1);
    H = ((uint32_t)u1 << 16) | u0;
    __nv_bfloat162 m = __floats2bfloat162_rn(a - __bfloat162float(h0), b - __bfloat162float(h1));
    M = *reinterpret_cast<uint32_t*>(&m);
}
/* row v[64] -> A = [hi(128B) | mid(128B)] */
__device__ __forceinline__ void writeRow64(char* A, int row, const float* v, bool dorelu) {
    char* base = A + row*APAD;
#pragma unroll
    for (int g = 0; g < 8; g++) {
        uint32_t H[4], M[4];
#pragma unroll
        for (int j = 0; j < 4; j++) {
            float a = v[8*g+2*j], b = v[8*g+2*j+1];
            if (dorelu) { a = fmaxf(a, 0.f); b = fmaxf(b, 0.f); }
            hm(a, b, H[j], M[j]);
        }
        *(uint4*)(base + g*16)       = make_uint4(H[0], H[1], H[2], H[3]);
        *(uint4*)(base + 128 + g*16) = make_uint4(M[0], M[1], M[2], M[3]);
    }
}
/* frags -> A = [hi(NT*16B) | mid(NT*16B)] */
template<int NT>
__device__ __forceinline__ void fragToA(char* A, int wid, int lane,
                                        float acc[2][NT][4], const float* bias, bool dorelu) {
    const int K2 = NT*16;
    int r0 = wid*32 + (lane >> 2);
    int cb = (lane & 3)*2;
#pragma unroll
    for (int mt = 0; mt < 2; mt++)
#pragma unroll
    for (int half = 0; half < 2; half++) {
        char* base = A + (r0 + mt*16 + half*8)*APAD;
#pragma unroll
        for (int nt = 0; nt < NT; nt++) {
            int c = nt*8 + cb;
            float v0 = acc[mt][nt][half*2+0] + bias[c];
            float v1 = acc[mt][nt][half*2+1] + bias[c+1];
            if (dorelu) { v0 = fmaxf(v0, 0.f); v1 = fmaxf(v1, 0.f); }
            uint32_t H, M; hm(v0, v1, H, M);
            *(uint32_t*)(base + c*2)      = H;
            *(uint32_t*)(base + K2 + c*2) = M;
        }
    }
}
__device__ __forceinline__ void fragStore(int ctaBase, int N, int wid, int lane,
                                          float acc[2][4][4], const float* bias) {
    int r0 = wid*32 + (lane >> 2);
    int cb = (lane & 3)*2;
#pragma unroll
    for (int mt = 0; mt < 2; mt++)
#pragma unroll
    for (int half = 0; half < 2; half++) {
        int slot = ctaBase + r0 + mt*16 + half*8;
        if (slot < N) {
            float* g = &g_net[(size_t)slot*HID_];
#pragma unroll
            for (int nt = 0; nt < 4; nt++) {
                int c = nt*8 + cb;
                *(float2*)(g + c) = make_float2(acc[mt][nt][half*2] + bias[c],
                                                acc[mt][nt][half*2+1] + bias[c+1]);
            }
        }
    }
}
template<int KT, int NT>
__device__ __forceinline__ void warp_gemm(uint32_t aU, uint32_t bU, int bpad,
                                          int wid, int lane, float acc[2][NT][4]) {
    uint32_t aAddr = aU + (uint32_t)(wid*32 + (lane & 15))*APAD + (uint32_t)((lane & 16) ? 16 : 0);
    uint32_t bRow = (uint32_t)(lane & 15);
#pragma unroll
    for (int kt = 0; kt < KT; kt++) {
        uint32_t a0[4], a1[4];
        ldmA(a0, aAddr + kt*32);
        ldmA(a1, aAddr + kt*32 + 16*APAD);
#pragma unroll
        for (int nt = 0; nt < NT; nt++) {
            uint32_t b[2];
            ldmB(b, bU + (kt*16 + bRow)*bpad + nt*16);
            mma16816(acc[0][nt], a0, b);
            mma16816(acc[1][nt], a1, b);
        }
    }
}
/* 3-pass split GEMM: hi*Bh + mid*Bh + hi*Bm ; A=[hi|mid], B=[Bh;Bm] */
template<int KT, int NT>
__device__ __forceinline__ void gemm3(uint32_t aU, int aMid, uint32_t bU, int bMidRows, int bpad,
                                      int wid, int lane, float acc[2][NT][4]) {
    warp_gemm<KT,NT>(aU,        bU,                  bpad, wid, lane, acc);
    warp_gemm<KT,NT>(aU + aMid, bU,                  bpad, wid, lane, acc);
    warp_gemm<KT,NT>(aU,        bU + bMidRows*bpad,  bpad, wid, lane, acc);
}
/* weights gmem [K][N] -> [Bh; Bm] (mid block at row Kpad) */
__device__ void prepB(char* dst, int tid, const float* __restrict__ g,
                      int K, int Kpad, int N, int bpad) {
    for (int t = tid; t < K*N; t += BDIM) {
        int k = t / N, n = t - k*N;
        float w = g[t];
        __nv_bfloat16 h = __float2bfloat16(w);
        __nv_bfloat16 m = __float2bfloat16(w - __bfloat162float(h));
        *(__nv_bfloat16*)(dst + k*bpad + n*2) = h;
        *(__nv_bfloat16*)(dst + (Kpad+k)*bpad + n*2) = m;
    }
}

/* -------- sort pre-pass + pooling -------- */
__global__ void zero_hist_kernel() {
    int s = gridDim.x*blockDim.x;
    for (int i = blockIdx.x*blockDim.x + threadIdx.x; i < BG_; i += s) g_hist[i] = 0;
}
__global__ void index_hist_kernel(const float* __restrict__ p, int T, int N) {
    int i = blockIdx.x*blockDim.x + threadIdx.x;
    if (i >= N) return;
    float p0 = p[3*i+0], p1 = p[3*i+1], p2 = p[3*i+2];
    int b = i / T;
    float pn0 = fminf(fmaxf(__fdiv_rn(p0, 1.101f) + 0.5f, 0.0f), 0.999f);
    float pn1 = fminf(fmaxf(__fdiv_rn(p1, 1.101f) + 0.5f, 0.0f), 0.999f);
    float pn2 = fminf(fmaxf(__fdiv_rn(p2, 1.101f) + 0.5f, 0.0f), 0.999f);
    int gidx = (int)floorf(pn0*32.f) + RESO_*((int)floorf(pn1*32.f) + RESO_*(int)floorf(pn2*32.f)) + b*G_;
    g_gidx[i] = gidx;
    atomicAdd(&g_hist[gidx], 1);
}
__global__ void scan_kernel() {
    __shared__ int part[1024];
    int t = threadIdx.x, base = t*64, s = 0;
#pragma unroll
    for (int j = 0; j < 64; j++) s += g_hist[base+j];
    part[t] = s; __syncthreads();
    for (int off = 1; off < 1024; off <<= 1) {
        int v = (t >= off) ? part[t-off] : 0;
        __syncthreads(); part[t] += v; __syncthreads();
    }
    int run = (t == 0) ? 0 : part[t-1];
#pragma unroll
    for (int j = 0; j < 64; j++) {
        int c = g_hist[base+j];
        g_start[base+j] = run; g_cursor[base+j] = run; run += c;
    }
}
__global__ void perm_kernel(const float* __restrict__ p, int N) {
    int i = blockIdx.x*blockDim.x + threadIdx.x;
    if (i >= N) return;
    int gidx = g_gidx[i];
    int slot = atomicAdd(&g_cursor[gidx], 1);
    g_sgidx[slot] = gidx;
    g_psort[(size_t)slot*3+0] = p[3*i+0];
    g_psort[(size_t)slot*3+1] = p[3*i+1];
    g_psort[(size_t)slot*3+2] = p[3*i+2];
}
__global__ void maxpool_kernel(float* __restrict__ dst) {
    int t = blockIdx.x*blockDim.x + threadIdx.x;
    if (t >= BG_*8) return;
    int cell = t >> 3, q = (t & 7) * 4;
    int s = g_start[cell], n = g_hist[cell];
    float4 m = make_float4(0.f, 0.f, 0.f, 0.f);
    if (n > 0) {
        m = *reinterpret_cast<const float4*>(&g_net[(size_t)s*HID_ + q]);
        for (int k = 1; k < n; k++) {
            float4 v = *reinterpret_cast<const float4*>(&g_net[(size_t)(s+k)*HID_ + q]);
            m.x = fmaxf(m.x, v.x); m.y = fmaxf(m.y, v.y);
            m.z = fmaxf(m.z, v.z); m.w = fmaxf(m.w, v.w);
        }
    }
    *reinterpret_cast<float4*>(&dst[cell*HID_ + q]) = m;
}

/* -------- stage 0 (persistent, M=256, 2 CTA/SM) -------- */
__global__ void __launch_bounds__(BDIM) point0_kernel(
    const float* __restrict__ Wp, const float* __restrict__ Bp,
    const float* __restrict__ w0, const float* __restrict__ b0g,
    const float* __restrict__ w1, const float* __restrict__ b1g,
    const float* __restrict__ ws, int N)
{
    extern __shared__ __align__(16) char sm[];
    uint32_t su = smem_u32(sm);
    int tid = threadIdx.x, wid = tid >> 5, lane = tid & 31;
    for (int t = tid; t < 18432/4; t += BDIM) ((uint32_t*)(sm + O_WP))[t] = 0;
    __syncthreads();
    prepB(sm+O_WP, tid, Wp, 60, 64, 64, BP64);
    prepB(sm+P_W0, tid, w0, 64, 64, 32, BP32);
    prepB(sm+P_WS, tid, ws, 64, 64, 32, BP32);
    prepB(sm+P_W1, tid, w1, 32, 32, 32, BP32);
    if (tid < 32) { ((float*)(sm+P_SB0))[tid] = b0g[tid]; ((float*)(sm+P_SB1))[tid] = b1g[tid]; }
    if (tid >= 64 && tid < 128) ((float*)(sm+P_SBP))[tid-64] = Bp[tid-64];
    __syncthreads();
    const float* b0 = (const float*)(sm+P_SB0);
    const float* b1 = (const float*)(sm+P_SB1);
    const float* sbp = (const float*)(sm+P_SBP);

    int nTiles = (N + MTILE - 1) / MTILE;
    for (int tile = blockIdx.x; tile < nTiles; tile += gridDim.x) {
        int ctaBase = tile*MTILE;
        int slot = ctaBase + tid;
        float p0 = 0.f, p1 = 0.f, p2 = 0.f;
        if (slot < N) { p0 = g_psort[(size_t)slot*3]; p1 = g_psort[(size_t)slot*3+1]; p2 = g_psort[(size_t)slot*3+2]; }
        float pe[64];
#pragma unroll
        for (int j = 60; j < 64; j++) pe[j] = 0.f;
        float q[3] = {2.f*p0-1.f, 2.f*p1-1.f, 2.f*p2-1.f};
#pragma unroll
        for (int d = 0; d < 3; d++) {
            float y = q[d];
#pragma unroll 1
            for (int l = 0; l < 10; l++) {
                float s, c; sincospif(y, &s, &c);
                pe[l*6+d] = s; pe[l*6+3+d] = c;
                y *= 2.f;
            }
        }
        writeRow64(sm+O_A, tid, pe, false);
        __syncwarp();
        float accX[2][8][4] = {};
        gemm3<4,8>(su+O_A, 128, su+O_WP, 64, BP64, wid, lane, accX);
        __syncwarp();
        fragToA<8>(sm+O_A, wid, lane, accX, sbp, true);
        __syncwarp();
        float accH[2][4][4] = {};
        gemm3<4,4>(su+O_A, 128, su+P_W0, 64, BP32, wid, lane, accH);
        __syncwarp();
        fragToA<8>(sm+O_A, wid, lane, accX, sbp, false);
        __syncwarp();
        float accO[2][4][4] = {};
        gemm3<4,4>(su+O_A, 128, su+P_WS, 64, BP32, wid, lane, accO);
        __syncwarp();
        fragToA<4>(sm+O_A, wid, lane, accH, b0, true);
        __syncwarp();
        gemm3<2,4>(su+O_A, 64, su+P_W1, 32, BP32, wid, lane, accO);
        fragStore(ctaBase, N, wid, lane, accO, b1);
        __syncwarp();
    }
}

/* -------- stages 1..3 (persistent, M=256, 2 CTA/SM) -------- */
__global__ void __launch_bounds__(BDIM) pool_block_kernel(
    const float* __restrict__ w0, const float* __restrict__ b0g,
    const float* __restrict__ w1, const float* __restrict__ b1g,
    const float* __restrict__ ws, const float* __restrict__ cellSrc, int N)
{
    extern __shared__ __align__(16) char sm[];
    uint32_t su = smem_u32(sm);
    int tid = threadIdx.x, wid = tid >> 5, lane = tid & 31;
    prepB(sm+O_W0, tid, w0, 64, 64, 32, BP32);
    prepB(sm+O_WS, tid, ws, 64, 64, 32, BP32);
    prepB(sm+O_W1, tid, w1, 32, 32, 32, BP32);
    if (tid < 32) { ((float*)(sm+O_SB0))[tid] = b0g[tid]; ((float*)(sm+O_SB1))[tid] = b1g[tid]; }
    __syncthreads();
    const float* b0 = (const float*)(sm+O_SB0);
    const float* b1 = (const float*)(sm+O_SB1);

    int nTiles = (N + MTILE - 1) / MTILE;
    for (int tile = blockIdx.x; tile < nTiles; tile += gridDim.x) {
        int ctaBase = tile*MTILE;
        int slot = ctaBase + tid;
        float x[64];
        if (slot < N) {
            int gidx = g_sgidx[slot];
            const float4* np = (const float4*)&g_net[(size_t)slot*HID_];
            const float4* pp = (const float4*)&cellSrc[gidx*HID_];
#pragma unroll
            for (int j = 0; j < 8; j++) {
                float4 a = np[j]; x[4*j]=a.x; x[4*j+1]=a.y; x[4*j+2]=a.z; x[4*j+3]=a.w;
                float4 pb = pp[j]; x[32+4*j]=pb.x; x[32+4*j+1]=pb.y; x[32+4*j+2]=pb.z; x[32+4*j+3]=pb.w;
            }
        } else {
#pragma unroll
            for (int j = 0; j < 64; j++) x[j] = 0.f;
        }
        writeRow64(sm+O_A, tid, x, true);
        __syncwarp();
        float accH[2][4][4] = {};
        gemm3<4,4>(su+O_A, 128, su+O_W0, 64, BP32, wid, lane, accH);
        __syncwarp();
        writeRow64(sm+O_A, tid, x, false);
        __syncwarp();
        float accO[2][4][4] = {};
        gemm3<4,4>(su+O_A, 128, su+O_WS, 64, BP32, wid, lane, accO);
        __syncwarp();
        fragToA<4>(sm+O_A, wid, lane, accH, b0, true);
        __syncwarp();
        gemm3<2,4>(su+O_A, 64, su+O_W1, 32, BP32, wid, lane, accO);
        fragStore(ctaBase, N, wid, lane, accO, b1);
        __syncwarp();
    }
}

/* -------- stage 4 + fc_c (persistent, M=256, 2 CTA/SM) -------- */
__global__ void __launch_bounds__(BDIM) final_kernel(
    const float* __restrict__ w0, const float* __restrict__ b0g,
    const float* __restrict__ w1, const float* __restrict__ b1g,
    const float* __restrict__ ws,
    const float* __restrict__ fcw, const float* __restrict__ fcb,
    const float* __restrict__ cellSrc, int N)
{
    extern __shared__ __align__(16) char sm[];
    uint32_t su = smem_u32(sm);
    int tid = threadIdx.x, wid = tid >> 5, lane = tid & 31;
    prepB(sm+O_W0, tid, w0, 64, 64, 32, BP32);
    prepB(sm+O_WS, tid, ws, 64, 64, 32, BP32);
    prepB(sm+O_W1, tid, w1, 32, 32, 32, BP32);
    prepB(sm+O_FC, tid, fcw, 32, 32, 32, BP32);
    if (tid < 32) {
        ((float*)(sm+O_SB0))[tid] = b0g[tid];
        ((float*)(sm+O_SB1))[tid] = b1g[tid];
        ((float*)(sm+O_SFB))[tid] = fcb[tid];
    }
    __syncthreads();
    const float* b0 = (const float*)(sm+O_SB0);
    const float* b1 = (const float*)(sm+O_SB1);
    const float* sfb = (const float*)(sm+O_SFB);

    int nTiles = (N + MTILE - 1) / MTILE;
    for (int tile = blockIdx.x; tile < nTiles; tile += gridDim.x) {
        int ctaBase = tile*MTILE;
        int slot = ctaBase + tid;
        float x[64];
        if (slot < N) {
            int gidx = g_sgidx[slot];
            const float4* np = (const float4*)&g_net[(size_t)slot*HID_];
            const float4* pp = (const float4*)&cellSrc[gidx*HID_];
#pragma unroll
            for (int j = 0; j < 8; j++) {
                float4 a = np[j]; x[4*j]=a.x; x[4*j+1]=a.y; x[4*j+2]=a.z; x[4*j+3]=a.w;
                float4 pb = pp[j]; x[32+4*j]=pb.x; x[32+4*j+1]=pb.y; x[32+4*j+2]=pb.z; x[32+4*j+3]=pb.w;
            }
        } else {
#pragma unroll
            for (int j = 0; j < 64; j++) x[j] = 0.f;
        }
        writeRow64(sm+O_A, tid, x, true);
        __syncwarp();
        float accH[2][4][4] = {};
        gemm3<4,4>(su+O_A, 128, su+O_W0, 64, BP32, wid, lane, accH);
        __syncwarp();
        writeRow64(sm+O_A, tid, x, false);
        __syncwarp();
        float accO[2][4][4] = {};
        gemm3<4,4>(su+O_A, 128, su+O_WS, 64, BP32, wid, lane, accO);
        __syncwarp();
        fragToA<4>(sm+O_A, wid, lane, accH, b0, true);
        __syncwarp();
        gemm3<2,4>(su+O_A, 64, su+O_W1, 32, BP32, wid, lane, accO);
        __syncwarp();
        fragToA<4>(sm+O_A, wid, lane, accO, b1, false);
        __syncwarp();
        float accC[2][4][4] = {};
        gemm3<2,4>(su+O_A, 64, su+O_FC, 32, BP32, wid, lane, accC);
        fragStore(ctaBase, N, wid, lane, accC, sfb);
        __syncwarp();
    }
}

/* -------- output: CSR mean + transpose -------- */
__global__ void output_kernel(float* __restrict__ out, int total) {
    int t = blockIdx.x*blockDim.x + threadIdx.x;
    if (t >= total) return;
    int bg = t >> 5, ch = t & 31;
    int s = g_start[bg], n = g_hist[bg];
    float sum = 0.0f;
    for (int k = 0; k < n; k++) sum += g_net[(size_t)(s+k)*HID_ + ch];
    float mean = sum / fmaxf((float)n, 1.0f);
    int b = bg >> 15, g = bg & (G_ - 1);
    out[((size_t)b*HID_ + ch)*G_ + g] = mean;
}

/* -------- host -------- */
extern "C" void kernel_launch(void* const* d_in, const int* in_sizes, int n_in,
                              void* d_out, int out_size) {
    const float* p   = (const float*)d_in[0];
    const float* Wp  = (const float*)d_in[1];
    const float* Bp  = (const float*)d_in[2];
    const float* W0  = (const float*)d_in[3];
    const float* B0  = (const float*)d_in[4];
    const float* W1  = (const float*)d_in[5];
    const float* B1  = (const float*)d_in[6];
    const float* Ws  = (const float*)d_in[7];
    const float* Fc  = (const float*)d_in[8];
    const float* FcB = (const float*)d_in[9];
    float* out = (float*)d_out;

    int T = in_sizes[0] / (B_ * 3);
    int N = B_ * T;
    int nbp = (N + 255) / 256;
    int nTiles = (N + MTILE - 1) / MTILE;
    int nb = nTiles < MAXCTA ? nTiles : MAXCTA;

    cudaFuncSetAttribute(point0_kernel, cudaFuncAttributeMaxDynamicSharedMemorySize, SM_P0);
    cudaFuncSetAttribute(pool_block_kernel, cudaFuncAttributeMaxDynamicSharedMemorySize, SM_POOL);
    cudaFuncSetAttribute(final_kernel, cudaFuncAttributeMaxDynamicSharedMemorySize, SM_FIN);

    float* cellA; cudaGetSymbolAddress((void**)&cellA, g_cellA);
    float* cellB; cudaGetSymbolAddress((void**)&cellB, g_cellB);

    zero_hist_kernel<<<64, 256>>>();
    index_hist_kernel<<<nbp, 256>>>(p, T, N);
    scan_kernel<<<1, 1024>>>();
    perm_kernel<<<nbp, 256>>>(p, N);

    point0_kernel<<<nb, BDIM, SM_P0>>>(Wp, Bp, W0, B0, W1, B1, Ws, N);
    maxpool_kernel<<<BG_*8/256, 256>>>(cellA);

    pool_block_kernel<<<nb, BDIM, SM_POOL>>>(W0 + 1*64*HID_, B0 + 1*HID_,
        W1 + 1*HID_*HID_, B1 + 1*HID_, Ws + 1*64*HID_, cellA, N);
    maxpool_kernel<<<BG_*8/256, 256>>>(cellB);

    pool_block_kernel<<<nb, BDIM, SM_POOL>>>(W0 + 2*64*HID_, B0 + 2*HID_,
        W1 + 2*HID_*HID_, B1 + 2*HID_, Ws + 2*64*HID_, cellB, N);
    maxpool_kernel<<<BG_*8/256, 256>>>(cellA);

    pool_block_kernel<<<nb, BDIM, SM_POOL>>>(W0 + 3*64*HID_, B0 + 3*HID_,
        W1 + 3*HID_*HID_, B1 + 3*HID_, Ws + 3*64*HID_, cellA, N);
    maxpool_kernel<<<BG_*8/256, 256>>>(cellB);

    final_kernel<<<nb, BDIM, SM_FIN>>>(W0 + 4*64*HID_, B0 + 4*HID_,
        W1 + 4*HID_*HID_, B1 + 4*HID_, Ws + 4*64*HID_, Fc, FcB, cellB, N);

    output_kernel<<<(out_size + 255)/256, 256>>>(out, out_size);
}

// round 14
// speedup vs baseline: 1.9425x; 1.0779x over previous
#include <cuda_runtime.h>
#include <cuda_bf16.h>
#include <math.h>
#include <stdint.h>

#define B_ 2
#define RESO_ 32
#define G_ 32768
#define BG_ 65536
#define HID_ 32
#define NMAX_ 524288
#define BDIM 256
#define MTILE 256
#define APAD 272
#define BP32 80
#define BP64 144
#define MAXCTA 296

#define O_A   0
#define O_W0  69632
#define O_WS  79872
#define O_W1  90112
#define O_SB0 95232
#define O_SB1 95360
#define SM_POOL 95488
#define O_FC  95488
#define O_SFB 100608
#define SM_FIN 100736
#define O_WP  69632
#define P_W0  88064
#define P_WS  98304
#define P_W1  108544
#define P_SB0 113664
#define P_SB1 113792
#define P_SBP 113920
#define SM_P0 114176

/* -------- scratch -------- */
__device__ float g_net[(size_t)NMAX_*HID_];
__device__ float g_psort[(size_t)NMAX_*3];
__device__ int   g_gidx[NMAX_];
__device__ int   g_sgidx[NMAX_];
__device__ int   g_hist[BG_];
__device__ int   g_start[BG_];
__device__ int   g_cursor[BG_];
__device__ float g_cellA[BG_*HID_];
__device__ float g_cellB[BG_*HID_];

/* -------- helpers -------- */
__device__ __forceinline__ uint32_t smem_u32(const void* p) {
    uint32_t a;
    asm("{ .reg .u64 t; cvta.to.shared.u64 t, %1; cvt.u32.u64 %0, t; }" : "=r"(a) : "l"(p));
    return a;
}
__device__ __forceinline__ void ldmA(uint32_t a[4], uint32_t addr) {
    asm volatile("ldmatrix.sync.aligned.m8n8.x4.shared.b16 {%0,%1,%2,%3}, [%4];"
        : "=r"(a[0]), "=r"(a[1]), "=r"(a[2]), "=r"(a[3]) : "r"(addr));
}
__device__ __forceinline__ void ldmB(uint32_t b[2], uint32_t addr) {
    asm volatile("ldmatrix.sync.aligned.m8n8.x2.trans.shared.b16 {%0,%1}, [%2];"
        : "=r"(b[0]), "=r"(b[1]) : "r"(addr));
}
__device__ __forceinline__ void mma16816(float d[4], const uint32_t a[4], const uint32_t b[2]) {
    asm volatile("mma.sync.aligned.m16n8k16.row.col.f32.bf16.bf16.f32 "
        "{%0,%1,%2,%3},{%4,%5,%6,%7},{%8,%9},{%0,%1,%2,%3};"
        : "+f"(d[0]), "+f"(d[1]), "+f"(d[2]), "+f"(d[3])
        : "r"(a[0]), "r"(a[1]), "r"(a[2]), "r"(a[3]), "r"(b[0]), "r"(b[1]));
}
__device__ __forceinline__ void hm(float a, float b, uint32_t& H, uint32_t& M) {
    __nv_bfloat16 h0 = __float2bfloat16(a), h1 = __float2bfloat16(b);
    uint16_t u0 = *reinterpret_cast<uint16_t*>(&h0), u1 = *reinterpret_cast<uint16_t*>(&h1);
    H = ((uint32_t)u1 << 16) | u0;
    __nv_bfloat162 m = __floats2bfloat162_rn(a - __bfloat162float(h0), b - __bfloat162float(h1));
    M = *reinterpret_cast<uint32_t*>(&m);
}
/* row v[64] -> A = [hi(128B) | mid(128B)] */
__device__ __forceinline__ void writeRow64(char* A, int row, const float* v, bool dorelu) {
    char* base = A + row*APAD;
#pragma unroll
    for (int g = 0; g < 8; g++) {
        uint32_t H[4], M[4];
#pragma unroll
        for (int j = 0; j < 4; j++) {
            float a = v[8*g+2*j], b = v[8*g+2*j+1];
            if (dorelu) { a = fmaxf(a, 0.f); b = fmaxf(b, 0.f); }
            hm(a, b, H[j], M[j]);
        }
        *(uint4*)(base + g*16)       = make_uint4(H[0], H[1], H[2], H[3]);
        *(uint4*)(base + 128 + g*16) = make_uint4(M[0], M[1], M[2], M[3]);
    }
}
template<int NT>
__device__ __forceinline__ void fragToA(char* A, int wid, int lane,
                                        float acc[2][NT][4], const float* bias, bool dorelu) {
    const int K2 = NT*16;
    int r0 = wid*32 + (lane >> 2);
    int cb = (lane & 3)*2;
#pragma unroll
    for (int mt = 0; mt < 2; mt++)
#pragma unroll
    for (int half = 0; half < 2; half++) {
        char* base = A + (r0 + mt*16 + half*8)*APAD;
#pragma unroll
        for (int nt = 0; nt < NT; nt++) {
            int c = nt*8 + cb;
            float v0 = acc[mt][nt][half*2+0] + bias[c];
            float v1 = acc[mt][nt][half*2+1] + bias[c+1];
            if (dorelu) { v0 = fmaxf(v0, 0.f); v1 = fmaxf(v1, 0.f); }
            uint32_t H, M; hm(v0, v1, H, M);
            *(uint32_t*)(base + c*2)      = H;
            *(uint32_t*)(base + K2 + c*2) = M;
        }
    }
}
__device__ __forceinline__ void fragStore(int ctaBase, int N, int wid, int lane,
                                          float acc[2][4][4], const float* bias) {
    int r0 = wid*32 + (lane >> 2);
    int cb = (lane & 3)*2;
#pragma unroll
    for (int mt = 0; mt < 2; mt++)
#pragma unroll
    for (int half = 0; half < 2; half++) {
        int slot = ctaBase + r0 + mt*16 + half*8;
        if (slot < N) {
            float* g = &g_net[(size_t)slot*HID_];
#pragma unroll
            for (int nt = 0; nt < 4; nt++) {
                int c = nt*8 + cb;
                *(float2*)(g + c) = make_float2(acc[mt][nt][half*2] + bias[c],
                                                acc[mt][nt][half*2+1] + bias[c+1]);
            }
        }
    }
}
/* fused 3-product split GEMM: acc += Ahi*Bh + Amid*Bh + Ahi*Bm
   A = [hi | mid at +aMid], B = [Bh ; Bm at row bMidRows]            */
template<int KT, int NT>
__device__ __forceinline__ void gemm3(uint32_t aU, int aMid, uint32_t bU, int bMidRows, int bpad,
                                      int wid, int lane, float acc[2][NT][4]) {
    uint32_t aAddr = aU + (uint32_t)(wid*32 + (lane & 15))*APAD + (uint32_t)((lane & 16) ? 16 : 0);
    uint32_t bRow = (uint32_t)(lane & 15);
#pragma unroll
    for (int kt = 0; kt < KT; kt++) {
        uint32_t h0[4], h1[4], m0[4], m1[4];
        ldmA(h0, aAddr + kt*32);
        ldmA(h1, aAddr + kt*32 + 16*APAD);
        ldmA(m0, aAddr + aMid + kt*32);
        ldmA(m1, aAddr + aMid + kt*32 + 16*APAD);
#pragma unroll
        for (int nt = 0; nt < NT; nt++) {
            uint32_t bh[2], bm[2];
            ldmB(bh, bU + (kt*16 + bRow)*bpad + nt*16);
            ldmB(bm, bU + (bMidRows + kt*16 + bRow)*bpad + nt*16);
            mma16816(acc[0][nt], h0, bh);
            mma16816(acc[1][nt], h1, bh);
            mma16816(acc[0][nt], m0, bh);
            mma16816(acc[1][nt], m1, bh);
            mma16816(acc[0][nt], h0, bm);
            mma16816(acc[1][nt], h1, bm);
        }
    }
}
/* weights gmem [K][N] -> [Bh; Bm] (mid block at row Kpad) */
__device__ void prepB(char* dst, int tid, const float* __restrict__ g,
                      int K, int Kpad, int N, int bpad) {
    for (int t = tid; t < K*N; t += BDIM) {
        int k = t / N, n = t - k*N;
        float w = g[t];
        __nv_bfloat16 h = __float2bfloat16(w);
        __nv_bfloat16 m = __float2bfloat16(w - __bfloat162float(h));
        *(__nv_bfloat16*)(dst + k*bpad + n*2) = h;
        *(__nv_bfloat16*)(dst + (Kpad+k)*bpad + n*2) = m;
    }
}

/* -------- sort pre-pass + pooling -------- */
__global__ void zero_hist_kernel() {
    int s = gridDim.x*blockDim.x;
    for (int i = blockIdx.x*blockDim.x + threadIdx.x; i < BG_; i += s) g_hist[i] = 0;
}
__global__ void index_hist_kernel(const float* __restrict__ p, int T, int N) {
    int i = blockIdx.x*blockDim.x + threadIdx.x;
    if (i >= N) return;
    float p0 = p[3*i+0], p1 = p[3*i+1], p2 = p[3*i+2];
    int b = i / T;
    float pn0 = fminf(fmaxf(__fdiv_rn(p0, 1.101f) + 0.5f, 0.0f), 0.999f);
    float pn1 = fminf(fmaxf(__fdiv_rn(p1, 1.101f) + 0.5f, 0.0f), 0.999f);
    float pn2 = fminf(fmaxf(__fdiv_rn(p2, 1.101f) + 0.5f, 0.0f), 0.999f);
    int gidx = (int)floorf(pn0*32.f) + RESO_*((int)floorf(pn1*32.f) + RESO_*(int)floorf(pn2*32.f)) + b*G_;
    g_gidx[i] = gidx;
    atomicAdd(&g_hist[gidx], 1);
}
__global__ void scan_kernel() {
    __shared__ int part[1024];
    int t = threadIdx.x, base = t*64, s = 0;
#pragma unroll
    for (int j = 0; j < 64; j++) s += g_hist[base+j];
    part[t] = s; __syncthreads();
    for (int off = 1; off < 1024; off <<= 1) {
        int v = (t >= off) ? part[t-off] : 0;
        __syncthreads(); part[t] += v; __syncthreads();
    }
    int run = (t == 0) ? 0 : part[t-1];
#pragma unroll
    for (int j = 0; j < 64; j++) {
        int c = g_hist[base+j];
        g_start[base+j] = run; g_cursor[base+j] = run; run += c;
    }
}
__global__ void perm_kernel(const float* __restrict__ p, int N) {
    int i = blockIdx.x*blockDim.x + threadIdx.x;
    if (i >= N) return;
    int gidx = g_gidx[i];
    int slot = atomicAdd(&g_cursor[gidx], 1);
    g_sgidx[slot] = gidx;
    g_psort[(size_t)slot*3+0] = p[3*i+0];
    g_psort[(size_t)slot*3+1] = p[3*i+1];
    g_psort[(size_t)slot*3+2] = p[3*i+2];
}
__global__ void maxpool_kernel(float* __restrict__ dst) {
    int t = blockIdx.x*blockDim.x + threadIdx.x;
    if (t >= BG_*8) return;
    int cell = t >> 3, q = (t & 7) * 4;
    int s = g_start[cell], n = g_hist[cell];
    float4 m = make_float4(0.f, 0.f, 0.f, 0.f);
    if (n > 0) {
        m = *reinterpret_cast<const float4*>(&g_net[(size_t)s*HID_ + q]);
        for (int k = 1; k < n; k++) {
            float4 v = *reinterpret_cast<const float4*>(&g_net[(size_t)(s+k)*HID_ + q]);
            m.x = fmaxf(m.x, v.x); m.y = fmaxf(m.y, v.y);
            m.z = fmaxf(m.z, v.z); m.w = fmaxf(m.w, v.w);
        }
    }
    *reinterpret_cast<float4*>(&dst[cell*HID_ + q]) = m;
}

/* -------- stage 0 -------- */
__global__ void __launch_bounds__(BDIM) point0_kernel(
    const float* __restrict__ Wp, const float* __restrict__ Bp,
    const float* __restrict__ w0, const float* __restrict__ b0g,
    const float* __restrict__ w1, const float* __restrict__ b1g,
    const float* __restrict__ ws, int N)
{
    extern __shared__ __align__(16) char sm[];
    uint32_t su = smem_u32(sm);
    int tid = threadIdx.x, wid = tid >> 5, lane = tid & 31;
    for (int t = tid; t < 18432/4; t += BDIM) ((uint32_t*)(sm + O_WP))[t] = 0;
    __syncthreads();
    prepB(sm+O_WP, tid, Wp, 60, 64, 64, BP64);
    prepB(sm+P_W0, tid, w0, 64, 64, 32, BP32);
    prepB(sm+P_WS, tid, ws, 64, 64, 32, BP32);
    prepB(sm+P_W1, tid, w1, 32, 32, 32, BP32);
    if (tid < 32) { ((float*)(sm+P_SB0))[tid] = b0g[tid]; ((float*)(sm+P_SB1))[tid] = b1g[tid]; }
    if (tid >= 64 && tid < 128) ((float*)(sm+P_SBP))[tid-64] = Bp[tid-64];
    __syncthreads();
    const float* b0 = (const float*)(sm+P_SB0);
    const float* b1 = (const float*)(sm+P_SB1);
    const float* sbp = (const float*)(sm+P_SBP);

    int nTiles = (N + MTILE - 1) / MTILE;
    for (int tile = blockIdx.x; tile < nTiles; tile += gridDim.x) {
        int ctaBase = tile*MTILE;
        int slot = ctaBase + tid;
        float p0 = 0.f, p1 = 0.f, p2 = 0.f;
        if (slot < N) { p0 = g_psort[(size_t)slot*3]; p1 = g_psort[(size_t)slot*3+1]; p2 = g_psort[(size_t)slot*3+2]; }
        float pe[64];
#pragma unroll
        for (int j = 60; j < 64; j++) pe[j] = 0.f;
        float q[3] = {2.f*p0-1.f, 2.f*p1-1.f, 2.f*p2-1.f};
#pragma unroll
        for (int d = 0; d < 3; d++) {
            float s, c;
            sincospif(q[d], &s, &c);
#pragma unroll
            for (int l = 0; l < 10; l++) {
                if (l == 5) sincospif(q[d]*32.f, &s, &c);   /* reseed: cap recurrence error */
                pe[l*6+d] = s; pe[l*6+3+d] = c;
                float s2 = 2.f*s*c;
                c = fmaf(-2.f*s, s, 1.f);
                s = s2;
            }
        }
        writeRow64(sm+O_A, tid, pe, false);
        __syncwarp();
        float accX[2][8][4] = {};
        gemm3<4,8>(su+O_A, 128, su+O_WP, 64, BP64, wid, lane, accX);
        __syncwarp();
        fragToA<8>(sm+O_A, wid, lane, accX, sbp, true);
        __syncwarp();
        float accH[2][4][4] = {};
        gemm3<4,4>(su+O_A, 128, su+P_W0, 64, BP32, wid, lane, accH);
        __syncwarp();
        fragToA<8>(sm+O_A, wid, lane, accX, sbp, false);
        __syncwarp();
        float accO[2][4][4] = {};
        gemm3<4,4>(su+O_A, 128, su+P_WS, 64, BP32, wid, lane, accO);
        __syncwarp();
        fragToA<4>(sm+O_A, wid, lane, accH, b0, true);
        __syncwarp();
        gemm3<2,4>(su+O_A, 64, su+P_W1, 32, BP32, wid, lane, accO);
        fragStore(ctaBase, N, wid, lane, accO, b1);
        __syncwarp();
    }
}

/* -------- stages 1..3 -------- */
__global__ void __launch_bounds__(BDIM) pool_block_kernel(
    const float* __restrict__ w0, const float* __restrict__ b0g,
    const float* __restrict__ w1, const float* __restrict__ b1g,
    const float* __restrict__ ws, const float* __restrict__ cellSrc, int N)
{
    extern __shared__ __align__(16) char sm[];
    uint32_t su = smem_u32(sm);
    int tid = threadIdx.x, wid = tid >> 5, lane = tid & 31;
    prepB(sm+O_W0, tid, w0, 64, 64, 32, BP32);
    prepB(sm+O_WS, tid, ws, 64, 64, 32, BP32);
    prepB(sm+O_W1, tid, w1, 32, 32, 32, BP32);
    if (tid < 32) { ((float*)(sm+O_SB0))[tid] = b0g[tid]; ((float*)(sm+O_SB1))[tid] = b1g[tid]; }
    __syncthreads();
    const float* b0 = (const float*)(sm+O_SB0);
    const float* b1 = (const float*)(sm+O_SB1);

    int nTiles = (N + MTILE - 1) / MTILE;
    for (int tile = blockIdx.x; tile < nTiles; tile += gridDim.x) {
        int ctaBase = tile*MTILE;
        int slot = ctaBase + tid;
        float x[64];
        if (slot < N) {
            int gidx = g_sgidx[slot];
            const float4* np = (const float4*)&g_net[(size_t)slot*HID_];
            const float4* pp = (const float4*)&cellSrc[gidx*HID_];
#pragma unroll
            for (int j = 0; j < 8; j++) {
                float4 a = np[j]; x[4*j]=a.x; x[4*j+1]=a.y; x[4*j+2]=a.z; x[4*j+3]=a.w;
                float4 pb = pp[j]; x[32+4*j]=pb.x; x[32+4*j+1]=pb.y; x[32+4*j+2]=pb.z; x[32+4*j+3]=pb.w;
            }
        } else {
#pragma unroll
            for (int j = 0; j < 64; j++) x[j] = 0.f;
        }
        writeRow64(sm+O_A, tid, x, true);
        __syncwarp();
        float accH[2][4][4] = {};
        gemm3<4,4>(su+O_A, 128, su+O_W0, 64, BP32, wid, lane, accH);
        __syncwarp();
        writeRow64(sm+O_A, tid, x, false);
        __syncwarp();
        float accO[2][4][4] = {};
        gemm3<4,4>(su+O_A, 128, su+O_WS, 64, BP32, wid, lane, accO);
        __syncwarp();
        fragToA<4>(sm+O_A, wid, lane, accH, b0, true);
        __syncwarp();
        gemm3<2,4>(su+O_A, 64, su+O_W1, 32, BP32, wid, lane, accO);
        fragStore(ctaBase, N, wid, lane, accO, b1);
        __syncwarp();
    }
}

/* -------- stage 4 + fc_c -------- */
__global__ void __launch_bounds__(BDIM) final_kernel(
    const float* __restrict__ w0, const float* __restrict__ b0g,
    const float* __restrict__ w1, const float* __restrict__ b1g,
    const float* __restrict__ ws,
    const float* __restrict__ fcw, const float* __restrict__ fcb,
    const float* __restrict__ cellSrc, int N)
{
    extern __shared__ __align__(16) char sm[];
    uint32_t su = smem_u32(sm);
    int tid = threadIdx.x, wid = tid >> 5, lane = tid & 31;
    prepB(sm+O_W0, tid, w0, 64, 64, 32, BP32);
    prepB(sm+O_WS, tid, ws, 64, 64, 32, BP32);
    prepB(sm+O_W1, tid, w1, 32, 32, 32, BP32);
    prepB(sm+O_FC, tid, fcw, 32, 32, 32, BP32);
    if (tid < 32) {
        ((float*)(sm+O_SB0))[tid] = b0g[tid];
        ((float*)(sm+O_SB1))[tid] = b1g[tid];
        ((float*)(sm+O_SFB))[tid] = fcb[tid];
    }
    __syncthreads();
    const float* b0 = (const float*)(sm+O_SB0);
    const float* b1 = (const float*)(sm+O_SB1);
    const float* sfb = (const float*)(sm+O_SFB);

    int nTiles = (N + MTILE - 1) / MTILE;
    for (int tile = blockIdx.x; tile < nTiles; tile += gridDim.x) {
        int ctaBase = tile*MTILE;
        int slot = ctaBase + tid;
        float x[64];
        if (slot < N) {
            int gidx = g_sgidx[slot];
            const float4* np = (const float4*)&g_net[(size_t)slot*HID_];
            const float4* pp = (const float4*)&cellSrc[gidx*HID_];
#pragma unroll
            for (int j = 0; j < 8; j++) {
                float4 a = np[j]; x[4*j]=a.x; x[4*j+1]=a.y; x[4*j+2]=a.z; x[4*j+3]=a.w;
                float4 pb = pp[j]; x[32+4*j]=pb.x; x[32+4*j+1]=pb.y; x[32+4*j+2]=pb.z; x[32+4*j+3]=pb.w;
            }
        } else {
#pragma unroll
            for (int j = 0; j < 64; j++) x[j] = 0.f;
        }
        writeRow64(sm+O_A, tid, x, true);
        __syncwarp();
        float accH[2][4][4] = {};
        gemm3<4,4>(su+O_A, 128, su+O_W0, 64, BP32, wid, lane, accH);
        __syncwarp();
        writeRow64(sm+O_A, tid, x, false);
        __syncwarp();
        float accO[2][4][4] = {};
        gemm3<4,4>(su+O_A, 128, su+O_WS, 64, BP32, wid, lane, accO);
        __syncwarp();
        fragToA<4>(sm+O_A, wid, lane, accH, b0, true);
        __syncwarp();
        gemm3<2,4>(su+O_A, 64, su+O_W1, 32, BP32, wid, lane, accO);
        __syncwarp();
        fragToA<4>(sm+O_A, wid, lane, accO, b1, false);
        __syncwarp();
        float accC[2][4][4] = {};
        gemm3<2,4>(su+O_A, 64, su+O_FC, 32, BP32, wid, lane, accC);
        fragStore(ctaBase, N, wid, lane, accC, sfb);
        __syncwarp();
    }
}

/* -------- output: CSR mean + transpose -------- */
__global__ void output_kernel(float* __restrict__ out, int total) {
    int t = blockIdx.x*blockDim.x + threadIdx.x;
    if (t >= total) return;
    int bg = t >> 5, ch = t & 31;
    int s = g_start[bg], n = g_hist[bg];
    float sum = 0.0f;
    for (int k = 0; k < n; k++) sum += g_net[(size_t)(s+k)*HID_ + ch];
    float mean = sum / fmaxf((float)n, 1.0f);
    int b = bg >> 15, g = bg & (G_ - 1);
    out[((size_t)b*HID_ + ch)*G_ + g] = mean;
}

/* -------- host -------- */
extern "C" void kernel_launch(void* const* d_in, const int* in_sizes, int n_in,
                              void* d_out, int out_size) {
    const float* p   = (const float*)d_in[0];
    const float* Wp  = (const float*)d_in[1];
    const float* Bp  = (const float*)d_in[2];
    const float* W0  = (const float*)d_in[3];
    const float* B0  = (const float*)d_in[4];
    const float* W1  = (const float*)d_in[5];
    const float* B1  = (const float*)d_in[6];
    const float* Ws  = (const float*)d_in[7];
    const float* Fc  = (const float*)d_in[8];
    const float* FcB = (const float*)d_in[9];
    float* out = (float*)d_out;

    int T = in_sizes[0] / (B_ * 3);
    int N = B_ * T;
    int nbp = (N + 255) / 256;
    int nTiles = (N + MTILE - 1) / MTILE;
    int nb = nTiles < MAXCTA ? nTiles : MAXCTA;

    cudaFuncSetAttribute(point0_kernel, cudaFuncAttributeMaxDynamicSharedMemorySize, SM_P0);
    cudaFuncSetAttribute(pool_block_kernel, cudaFuncAttributeMaxDynamicSharedMemorySize, SM_POOL);
    cudaFuncSetAttribute(final_kernel, cudaFuncAttributeMaxDynamicSharedMemorySize, SM_FIN);

    float* cellA; cudaGetSymbolAddress((void**)&cellA, g_cellA);
    float* cellB; cudaGetSymbolAddress((void**)&cellB, g_cellB);

    zero_hist_kernel<<<64, 256>>>();
    index_hist_kernel<<<nbp, 256>>>(p, T, N);
    scan_kernel<<<1, 1024>>>();
    perm_kernel<<<nbp, 256>>>(p, N);

    point0_kernel<<<nb, BDIM, SM_P0>>>(Wp, Bp, W0, B0, W1, B1, Ws, N);
    maxpool_kernel<<<BG_*8/256, 256>>>(cellA);

    pool_block_kernel<<<nb, BDIM, SM_POOL>>>(W0 + 1*64*HID_, B0 + 1*HID_,
        W1 + 1*HID_*HID_, B1 + 1*HID_, Ws + 1*64*HID_, cellA, N);
    maxpool_kernel<<<BG_*8/256, 256>>>(cellB);

    pool_block_kernel<<<nb, BDIM, SM_POOL>>>(W0 + 2*64*HID_, B0 + 2*HID_,
        W1 + 2*HID_*HID_, B1 + 2*HID_, Ws + 2*64*HID_, cellB, N);
    maxpool_kernel<<<BG_*8/256, 256>>>(cellA);

    pool_block_kernel<<<nb, BDIM, SM_POOL>>>(W0 + 3*64*HID_, B0 + 3*HID_,
        W1 + 3*HID_*HID_, B1 + 3*HID_, Ws + 3*64*HID_, cellA, N);
    maxpool_kernel<<<BG_*8/256, 256>>>(cellB);

    final_kernel<<<nb, BDIM, SM_FIN>>>(W0 + 4*64*HID_, B0 + 4*HID_,
        W1 + 4*HID_*HID_, B1 + 4*HID_, Ws + 4*64*HID_, Fc, FcB, cellB, N);

    output_kernel<<<(out_size + 255)/256, 256>>>(out, out_size);
}

// round 15
// speedup vs baseline: 2.0799x; 1.0707x over previous
#include <cuda_runtime.h>
#include <cuda_bf16.h>
#include <math.h>
#include <stdint.h>

#define B_ 2
#define RESO_ 32
#define G_ 32768
#define BG_ 65536
#define HID_ 32
#define NMAX_ 524288
#define BDIM 256
#define MTILE 256
#define APAD 272
#define BP32 80
#define BP64 144
#define MAXCTA 148

/* A1 relu-tile, A2 raw-tile, each 256*272 = 69632 */
#define O_A1  0
#define O_A2  69632
#define O_W0  139264
#define O_WS  149504
#define O_W1  159744
#define O_SB0 164864
#define O_SB1 164992
#define SM_POOL 165120
#define O_FC  165120
#define O_SFB 170240
#define SM_FIN 170368
#define P_WP  165120
#define P_SBP 183552
#define SM_P0 183808

/* -------- scratch -------- */
__device__ float g_net[(size_t)NMAX_*HID_];
__device__ float g_psort[(size_t)NMAX_*3];
__device__ int   g_gidx[NMAX_];
__device__ int   g_sgidx[NMAX_];
__device__ int   g_hist[BG_];
__device__ int   g_start[BG_];
__device__ int   g_cursor[BG_];
__device__ float g_cellA[BG_*HID_];
__device__ float g_cellB[BG_*HID_];

/* -------- helpers -------- */
__device__ __forceinline__ uint32_t smem_u32(const void* p) {
    uint32_t a;
    asm("{ .reg .u64 t; cvta.to.shared.u64 t, %1; cvt.u32.u64 %0, t; }" : "=r"(a) : "l"(p));
    return a;
}
__device__ __forceinline__ void ldmA(uint32_t a[4], uint32_t addr) {
    asm volatile("ldmatrix.sync.aligned.m8n8.x4.shared.b16 {%0,%1,%2,%3}, [%4];"
        : "=r"(a[0]), "=r"(a[1]), "=r"(a[2]), "=r"(a[3]) : "r"(addr));
}
/* x4 trans: b[0..1] = n-tile nt (k0-7,k8-15), b[2..3] = n-tile nt+1.
   lane addr: row = lane&15, col offset +16B for lanes 16-31. */
__device__ __forceinline__ void ldmB4(uint32_t b[4], uint32_t addr) {
    asm volatile("ldmatrix.sync.aligned.m8n8.x4.trans.shared.b16 {%0,%1,%2,%3}, [%4];"
        : "=r"(b[0]), "=r"(b[1]), "=r"(b[2]), "=r"(b[3]) : "r"(addr));
}
__device__ __forceinline__ void mma16816(float d[4], const uint32_t a[4], const uint32_t b[2]) {
    asm volatile("mma.sync.aligned.m16n8k16.row.col.f32.bf16.bf16.f32 "
        "{%0,%1,%2,%3},{%4,%5,%6,%7},{%8,%9},{%0,%1,%2,%3};"
        : "+f"(d[0]), "+f"(d[1]), "+f"(d[2]), "+f"(d[3])
        : "r"(a[0]), "r"(a[1]), "r"(a[2]), "r"(a[3]), "r"(b[0]), "r"(b[1]));
}
__device__ __forceinline__ void hm(float a, float b, uint32_t& H, uint32_t& M) {
    __nv_bfloat16 h0 = __float2bfloat16(a), h1 = __float2bfloat16(b);
    uint16_t u0 = *reinterpret_cast<uint16_t*>(&h0), u1 = *reinterpret_cast<uint16_t*>(&h1);
    H = ((uint32_t)u1 << 16) | u0;
    __nv_bfloat162 m = __floats2bfloat162_rn(a - __bfloat162float(h0), b - __bfloat162float(h1));
    M = *reinterpret_cast<uint32_t*>(&m);
}
/* row v[64] -> A = [hi|mid] */
__device__ __forceinline__ void writeRow64(char* A, int row, const float* v) {
    char* base = A + row*APAD;
#pragma unroll
    for (int g = 0; g < 8; g++) {
        uint32_t H[4], M[4];
#pragma unroll
        for (int j = 0; j < 4; j++) hm(v[8*g+2*j], v[8*g+2*j+1], H[j], M[j]);
        *(uint4*)(base + g*16)       = make_uint4(H[0], H[1], H[2], H[3]);
        *(uint4*)(base + 128 + g*16) = make_uint4(M[0], M[1], M[2], M[3]);
    }
}
/* row v[64]: relu->A1, raw->A2 in one pass */
__device__ __forceinline__ void writeRowDual(char* A1, char* A2, int row, const float* v) {
    char* b1 = A1 + row*APAD;
    char* b2 = A2 + row*APAD;
#pragma unroll
    for (int g = 0; g < 8; g++) {
        uint32_t RH[4], RM[4], H[4], M[4];
#pragma unroll
        for (int j = 0; j < 4; j++) {
            float a = v[8*g+2*j], b = v[8*g+2*j+1];
            hm(a, b, H[j], M[j]);
            hm(fmaxf(a, 0.f), fmaxf(b, 0.f), RH[j], RM[j]);
        }
        *(uint4*)(b1 + g*16)       = make_uint4(RH[0], RH[1], RH[2], RH[3]);
        *(uint4*)(b1 + 128 + g*16) = make_uint4(RM[0], RM[1], RM[2], RM[3]);
        *(uint4*)(b2 + g*16)       = make_uint4(H[0], H[1], H[2], H[3]);
        *(uint4*)(b2 + 128 + g*16) = make_uint4(M[0], M[1], M[2], M[3]);
    }
}
template<int NT>
__device__ __forceinline__ void fragToA(char* A, int wid, int lane,
                                        float acc[2][NT][4], const float* bias, bool dorelu) {
    const int K2 = NT*16;
    int r0 = wid*32 + (lane >> 2);
    int cb = (lane & 3)*2;
#pragma unroll
    for (int mt = 0; mt < 2; mt++)
#pragma unroll
    for (int half = 0; half < 2; half++) {
        char* base = A + (r0 + mt*16 + half*8)*APAD;
#pragma unroll
        for (int nt = 0; nt < NT; nt++) {
            int c = nt*8 + cb;
            float v0 = acc[mt][nt][half*2+0] + bias[c];
            float v1 = acc[mt][nt][half*2+1] + bias[c+1];
            if (dorelu) { v0 = fmaxf(v0, 0.f); v1 = fmaxf(v1, 0.f); }
            uint32_t H, M; hm(v0, v1, H, M);
            *(uint32_t*)(base + c*2)      = H;
            *(uint32_t*)(base + K2 + c*2) = M;
        }
    }
}
template<int NT>
__device__ __forceinline__ void fragToA_dual(char* A1, char* A2, int wid, int lane,
                                             float acc[2][NT][4], const float* bias) {
    const int K2 = NT*16;
    int r0 = wid*32 + (lane >> 2);
    int cb = (lane & 3)*2;
#pragma unroll
    for (int mt = 0; mt < 2; mt++)
#pragma unroll
    for (int half = 0; half < 2; half++) {
        char* b1 = A1 + (r0 + mt*16 + half*8)*APAD;
        char* b2 = A2 + (r0 + mt*16 + half*8)*APAD;
#pragma unroll
        for (int nt = 0; nt < NT; nt++) {
            int c = nt*8 + cb;
            float v0 = acc[mt][nt][half*2+0] + bias[c];
            float v1 = acc[mt][nt][half*2+1] + bias[c+1];
            uint32_t H, M; hm(v0, v1, H, M);
            *(uint32_t*)(b2 + c*2)      = H;
            *(uint32_t*)(b2 + K2 + c*2) = M;
            hm(fmaxf(v0, 0.f), fmaxf(v1, 0.f), H, M);
            *(uint32_t*)(b1 + c*2)      = H;
            *(uint32_t*)(b1 + K2 + c*2) = M;
        }
    }
}
__device__ __forceinline__ void fragStore(int ctaBase, int N, int wid, int lane,
                                          float acc[2][4][4], const float* bias) {
    int r0 = wid*32 + (lane >> 2);
    int cb = (lane & 3)*2;
#pragma unroll
    for (int mt = 0; mt < 2; mt++)
#pragma unroll
    for (int half = 0; half < 2; half++) {
        int slot = ctaBase + r0 + mt*16 + half*8;
        if (slot < N) {
            float* g = &g_net[(size_t)slot*HID_];
#pragma unroll
            for (int nt = 0; nt < 4; nt++) {
                int c = nt*8 + cb;
                *(float2*)(g + c) = make_float2(acc[mt][nt][half*2] + bias[c],
                                                acc[mt][nt][half*2+1] + bias[c+1]);
            }
        }
    }
}
/* fused 3-product split GEMM, x4 B loads (NT even) */
template<int KT, int NT>
__device__ __forceinline__ void gemm3x(uint32_t aU, int aMid, uint32_t bU, int bMidRows, int bpad,
                                       int wid, int lane, float acc[2][NT][4]) {
    uint32_t aAddr = aU + (uint32_t)(wid*32 + (lane & 15))*APAD + (uint32_t)((lane & 16) ? 16 : 0);
    uint32_t bBase = bU + (uint32_t)(lane & 15)*bpad + (uint32_t)(((lane >> 4) & 1)*16);
#pragma unroll
    for (int kt = 0; kt < KT; kt++) {
        uint32_t h0[4], h1[4], m0[4], m1[4];
        ldmA(h0, aAddr + kt*32);
        ldmA(h1, aAddr + kt*32 + 16*APAD);
        ldmA(m0, aAddr + aMid + kt*32);
        ldmA(m1, aAddr + aMid + kt*32 + 16*APAD);
#pragma unroll
        for (int nt = 0; nt < NT; nt += 2) {
            uint32_t bh[4], bm[4];
            ldmB4(bh, bBase + (uint32_t)(kt*16)*bpad + nt*16);
            ldmB4(bm, bBase + (uint32_t)((bMidRows + kt*16))*bpad + nt*16);
            mma16816(acc[0][nt], h0, bh); mma16816(acc[1][nt], h1, bh);
            mma16816(acc[0][nt], m0, bh); mma16816(acc[1][nt], m1, bh);
            mma16816(acc[0][nt], h0, bm); mma16816(acc[1][nt], h1, bm);
            mma16816(acc[0][nt+1], h0, bh+2); mma16816(acc[1][nt+1], h1, bh+2);
            mma16816(acc[0][nt+1], m0, bh+2); mma16816(acc[1][nt+1], m1, bh+2);
            mma16816(acc[0][nt+1], h0, bm+2); mma16816(acc[1][nt+1], h1, bm+2);
        }
    }
}
/* fused W0(relu-A1)->accH  +  Ws(raw-A2)->accO, one loop (KT=4, NT=4) */
__device__ __forceinline__ void gemm_dual(uint32_t a1, uint32_t a2,
                                          uint32_t bW0, uint32_t bWS,
                                          int wid, int lane,
                                          float accH[2][4][4], float accO[2][4][4]) {
    uint32_t rowOff = (uint32_t)(wid*32 + (lane & 15))*APAD + (uint32_t)((lane & 16) ? 16 : 0);
    uint32_t aAddr1 = a1 + rowOff, aAddr2 = a2 + rowOff;
    uint32_t bOff = (uint32_t)(lane & 15)*BP32 + (uint32_t)(((lane >> 4) & 1)*16);
    uint32_t b1 = bW0 + bOff, b2 = bWS + bOff;
#pragma unroll
    for (int kt = 0; kt < 4; kt++) {
        uint32_t rh0[4], rh1[4], rm0[4], rm1[4], xh0[4], xh1[4], xm0[4], xm1[4];
        ldmA(rh0, aAddr1 + kt*32);
        ldmA(rh1, aAddr1 + kt*32 + 16*APAD);
        ldmA(rm0, aAddr1 + 128 + kt*32);
        ldmA(rm1, aAddr1 + 128 + kt*32 + 16*APAD);
        ldmA(xh0, aAddr2 + kt*32);
        ldmA(xh1, aAddr2 + kt*32 + 16*APAD);
        ldmA(xm0, aAddr2 + 128 + kt*32);
        ldmA(xm1, aAddr2 + 128 + kt*32 + 16*APAD);
#pragma unroll
        for (int nt = 0; nt < 4; nt += 2) {
            uint32_t wh[4], wm[4], sh[4], sm2[4];
            ldmB4(wh,  b1 + (uint32_t)(kt*16)*BP32 + nt*16);
            ldmB4(wm,  b1 + (uint32_t)((64 + kt*16))*BP32 + nt*16);
            ldmB4(sh,  b2 + (uint32_t)(kt*16)*BP32 + nt*16);
            ldmB4(sm2, b2 + (uint32_t)((64 + kt*16))*BP32 + nt*16);
            mma16816(accH[0][nt], rh0, wh);  mma16816(accH[1][nt], rh1, wh);
            mma16816(accO[0][nt], xh0, sh);  mma16816(accO[1][nt], xh1, sh);
            mma16816(accH[0][nt], rm0, wh);  mma16816(accH[1][nt], rm1, wh);
            mma16816(accO[0][nt], xm0, sh);  mma16816(accO[1][nt], xm1, sh);
            mma16816(accH[0][nt], rh0, wm);  mma16816(accH[1][nt], rh1, wm);
            mma16816(accO[0][nt], xh0, sm2); mma16816(accO[1][nt], xh1, sm2);
            mma16816(accH[0][nt+1], rh0, wh+2);  mma16816(accH[1][nt+1], rh1, wh+2);
            mma16816(accO[0][nt+1], xh0, sh+2);  mma16816(accO[1][nt+1], xh1, sh+2);
            mma16816(accH[0][nt+1], rm0, wh+2);  mma16816(accH[1][nt+1], rm1, wh+2);
            mma16816(accO[0][nt+1], xm0, sh+2);  mma16816(accO[1][nt+1], xm1, sh+2);
            mma16816(accH[0][nt+1], rh0, wm+2);  mma16816(accH[1][nt+1], rh1, wm+2);
            mma16816(accO[0][nt+1], xh0, sm2+2); mma16816(accO[1][nt+1], xh1, sm2+2);
        }
    }
}
/* weights gmem [K][N] -> [Bh; Bm] */
__device__ void prepB(char* dst, int tid, const float* __restrict__ g,
                      int K, int Kpad, int N, int bpad) {
    for (int t = tid; t < K*N; t += BDIM) {
        int k = t / N, n = t - k*N;
        float w = g[t];
        __nv_bfloat16 h = __float2bfloat16(w);
        __nv_bfloat16 m = __float2bfloat16(w - __bfloat162float(h));
        *(__nv_bfloat16*)(dst + k*bpad + n*2) = h;
        *(__nv_bfloat16*)(dst + (Kpad+k)*bpad + n*2) = m;
    }
}

/* -------- sort pre-pass + pooling -------- */
__global__ void zero_hist_kernel() {
    int s = gridDim.x*blockDim.x;
    for (int i = blockIdx.x*blockDim.x + threadIdx.x; i < BG_; i += s) g_hist[i] = 0;
}
__global__ void index_hist_kernel(const float* __restrict__ p, int T, int N) {
    int i = blockIdx.x*blockDim.x + threadIdx.x;
    if (i >= N) return;
    float p0 = p[3*i+0], p1 = p[3*i+1], p2 = p[3*i+2];
    int b = i / T;
    float pn0 = fminf(fmaxf(__fdiv_rn(p0, 1.101f) + 0.5f, 0.0f), 0.999f);
    float pn1 = fminf(fmaxf(__fdiv_rn(p1, 1.101f) + 0.5f, 0.0f), 0.999f);
    float pn2 = fminf(fmaxf(__fdiv_rn(p2, 1.101f) + 0.5f, 0.0f), 0.999f);
    int gidx = (int)floorf(pn0*32.f) + RESO_*((int)floorf(pn1*32.f) + RESO_*(int)floorf(pn2*32.f)) + b*G_;
    g_gidx[i] = gidx;
    atomicAdd(&g_hist[gidx], 1);
}
__global__ void scan_kernel() {
    __shared__ int part[1024];
    int t = threadIdx.x, base = t*64, s = 0;
#pragma unroll
    for (int j = 0; j < 64; j++) s += g_hist[base+j];
    part[t] = s; __syncthreads();
    for (int off = 1; off < 1024; off <<= 1) {
        int v = (t >= off) ? part[t-off] : 0;
        __syncthreads(); part[t] += v; __syncthreads();
    }
    int run = (t == 0) ? 0 : part[t-1];
#pragma unroll
    for (int j = 0; j < 64; j++) {
        int c = g_hist[base+j];
        g_start[base+j] = run; g_cursor[base+j] = run; run += c;
    }
}
__global__ void perm_kernel(const float* __restrict__ p, int N) {
    int i = blockIdx.x*blockDim.x + threadIdx.x;
    if (i >= N) return;
    int gidx = g_gidx[i];
    int slot = atomicAdd(&g_cursor[gidx], 1);
    g_sgidx[slot] = gidx;
    g_psort[(size_t)slot*3+0] = p[3*i+0];
    g_psort[(size_t)slot*3+1] = p[3*i+1];
    g_psort[(size_t)slot*3+2] = p[3*i+2];
}
__global__ void maxpool_kernel(float* __restrict__ dst) {
    int t = blockIdx.x*blockDim.x + threadIdx.x;
    if (t >= BG_*8) return;
    int cell = t >> 3, q = (t & 7) * 4;
    int s = g_start[cell], n = g_hist[cell];
    float4 m = make_float4(0.f, 0.f, 0.f, 0.f);
    if (n > 0) {
        m = *reinterpret_cast<const float4*>(&g_net[(size_t)s*HID_ + q]);
        for (int k = 1; k < n; k++) {
            float4 v = *reinterpret_cast<const float4*>(&g_net[(size_t)(s+k)*HID_ + q]);
            m.x = fmaxf(m.x, v.x); m.y = fmaxf(m.y, v.y);
            m.z = fmaxf(m.z, v.z); m.w = fmaxf(m.w, v.w);
        }
    }
    *reinterpret_cast<float4*>(&dst[cell*HID_ + q]) = m;
}

/* -------- stage 0 -------- */
__global__ void __launch_bounds__(BDIM, 1) point0_kernel(
    const float* __restrict__ Wp, const float* __restrict__ Bp,
    const float* __restrict__ w0, const float* __restrict__ b0g,
    const float* __restrict__ w1, const float* __restrict__ b1g,
    const float* __restrict__ ws, int N)
{
    extern __shared__ __align__(16) char sm[];
    uint32_t su = smem_u32(sm);
    int tid = threadIdx.x, wid = tid >> 5, lane = tid & 31;
    for (int t = tid; t < 18432/4; t += BDIM) ((uint32_t*)(sm + P_WP))[t] = 0;
    __syncthreads();
    prepB(sm+P_WP, tid, Wp, 60, 64, 64, BP64);
    prepB(sm+O_W0, tid, w0, 64, 64, 32, BP32);
    prepB(sm+O_WS, tid, ws, 64, 64, 32, BP32);
    prepB(sm+O_W1, tid, w1, 32, 32, 32, BP32);
    if (tid < 32) { ((float*)(sm+O_SB0))[tid] = b0g[tid]; ((float*)(sm+O_SB1))[tid] = b1g[tid]; }
    if (tid >= 64 && tid < 128) ((float*)(sm+P_SBP))[tid-64] = Bp[tid-64];
    __syncthreads();
    const float* b0 = (const float*)(sm+O_SB0);
    const float* b1 = (const float*)(sm+O_SB1);
    const float* sbp = (const float*)(sm+P_SBP);

    int nTiles = (N + MTILE - 1) / MTILE;
    for (int tile = blockIdx.x; tile < nTiles; tile += gridDim.x) {
        int ctaBase = tile*MTILE;
        int slot = ctaBase + tid;
        float p0 = 0.f, p1 = 0.f, p2 = 0.f;
        if (slot < N) { p0 = g_psort[(size_t)slot*3]; p1 = g_psort[(size_t)slot*3+1]; p2 = g_psort[(size_t)slot*3+2]; }
        float pe[64];
#pragma unroll
        for (int j = 60; j < 64; j++) pe[j] = 0.f;
        float q[3] = {2.f*p0-1.f, 2.f*p1-1.f, 2.f*p2-1.f};
#pragma unroll
        for (int d = 0; d < 3; d++) {
            float s, c;
            sincospif(q[d], &s, &c);
#pragma unroll
            for (int l = 0; l < 10; l++) {
                if (l == 5) sincospif(q[d]*32.f, &s, &c);
                pe[l*6+d] = s; pe[l*6+3+d] = c;
                float s2 = 2.f*s*c;
                c = fmaf(-2.f*s, s, 1.f);
                s = s2;
            }
        }
        writeRow64(sm+O_A1, tid, pe);
        __syncwarp();
        float accX[2][8][4] = {};
        gemm3x<4,8>(su+O_A1, 128, su+P_WP, 64, BP64, wid, lane, accX);
        __syncwarp();
        fragToA_dual<8>(sm+O_A1, sm+O_A2, wid, lane, accX, sbp);
        __syncwarp();
        float accH[2][4][4] = {}, accO[2][4][4] = {};
        gemm_dual(su+O_A1, su+O_A2, su+O_W0, su+O_WS, wid, lane, accH, accO);
        __syncwarp();
        fragToA<4>(sm+O_A1, wid, lane, accH, b0, true);
        __syncwarp();
        gemm3x<2,4>(su+O_A1, 64, su+O_W1, 32, BP32, wid, lane, accO);
        fragStore(ctaBase, N, wid, lane, accO, b1);
        __syncwarp();
    }
}

/* -------- stages 1..3 -------- */
__global__ void __launch_bounds__(BDIM, 1) pool_block_kernel(
    const float* __restrict__ w0, const float* __restrict__ b0g,
    const float* __restrict__ w1, const float* __restrict__ b1g,
    const float* __restrict__ ws, const float* __restrict__ cellSrc, int N)
{
    extern __shared__ __align__(16) char sm[];
    uint32_t su = smem_u32(sm);
    int tid = threadIdx.x, wid = tid >> 5, lane = tid & 31;
    prepB(sm+O_W0, tid, w0, 64, 64, 32, BP32);
    prepB(sm+O_WS, tid, ws, 64, 64, 32, BP32);
    prepB(sm+O_W1, tid, w1, 32, 32, 32, BP32);
    if (tid < 32) { ((float*)(sm+O_SB0))[tid] = b0g[tid]; ((float*)(sm+O_SB1))[tid] = b1g[tid]; }
    __syncthreads();
    const float* b0 = (const float*)(sm+O_SB0);
    const float* b1 = (const float*)(sm+O_SB1);

    int nTiles = (N + MTILE - 1) / MTILE;
    for (int tile = blockIdx.x; tile < nTiles; tile += gridDim.x) {
        int ctaBase = tile*MTILE;
        int slot = ctaBase + tid;
        float x[64];
        if (slot < N) {
            int gidx = g_sgidx[slot];
            const float4* np = (const float4*)&g_net[(size_t)slot*HID_];
            const float4* pp = (const float4*)&cellSrc[gidx*HID_];
#pragma unroll
            for (int j = 0; j < 8; j++) {
                float4 a = np[j]; x[4*j]=a.x; x[4*j+1]=a.y; x[4*j+2]=a.z; x[4*j+3]=a.w;
                float4 pb = pp[j]; x[32+4*j]=pb.x; x[32+4*j+1]=pb.y; x[32+4*j+2]=pb.z; x[32+4*j+3]=pb.w;
            }
        } else {
#pragma unroll
            for (int j = 0; j < 64; j++) x[j] = 0.f;
        }
        writeRowDual(sm+O_A1, sm+O_A2, tid, x);
        __syncwarp();
        float accH[2][4][4] = {}, accO[2][4][4] = {};
        gemm_dual(su+O_A1, su+O_A2, su+O_W0, su+O_WS, wid, lane, accH, accO);
        __syncwarp();
        fragToA<4>(sm+O_A1, wid, lane, accH, b0, true);
        __syncwarp();
        gemm3x<2,4>(su+O_A1, 64, su+O_W1, 32, BP32, wid, lane, accO);
        fragStore(ctaBase, N, wid, lane, accO, b1);
        __syncwarp();
    }
}

/* -------- stage 4 + fc_c -------- */
__global__ void __launch_bounds__(BDIM, 1) final_kernel(
    const float* __restrict__ w0, const float* __restrict__ b0g,
    const float* __restrict__ w1, const float* __restrict__ b1g,
    const float* __restrict__ ws,
    const float* __restrict__ fcw, const float* __restrict__ fcb,
    const float* __restrict__ cellSrc, int N)
{
    extern __shared__ __align__(16) char sm[];
    uint32_t su = smem_u32(sm);
    int tid = threadIdx.x, wid = tid >> 5, lane = tid & 31;
    prepB(sm+O_W0, tid, w0, 64, 64, 32, BP32);
    prepB(sm+O_WS, tid, ws, 64, 64, 32, BP32);
    prepB(sm+O_W1, tid, w1, 32, 32, 32, BP32);
    prepB(sm+O_FC, tid, fcw, 32, 32, 32, BP32);
    if (tid < 32) {
        ((float*)(sm+O_SB0))[tid] = b0g[tid];
        ((float*)(sm+O_SB1))[tid] = b1g[tid];
        ((float*)(sm+O_SFB))[tid] = fcb[tid];
    }
    __syncthreads();
    const float* b0 = (const float*)(sm+O_SB0);
    const float* b1 = (const float*)(sm+O_SB1);
    const float* sfb = (const float*)(sm+O_SFB);

    int nTiles = (N + MTILE - 1) / MTILE;
    for (int tile = blockIdx.x; tile < nTiles; tile += gridDim.x) {
        int ctaBase = tile*MTILE;
        int slot = ctaBase + tid;
        float x[64];
        if (slot < N) {
            int gidx = g_sgidx[slot];
            const float4* np = (const float4*)&g_net[(size_t)slot*HID_];
            const float4* pp = (const float4*)&cellSrc[gidx*HID_];
#pragma unroll
            for (int j = 0; j < 8; j++) {
                float4 a = np[j]; x[4*j]=a.x; x[4*j+1]=a.y; x[4*j+2]=a.z; x[4*j+3]=a.w;
                float4 pb = pp[j]; x[32+4*j]=pb.x; x[32+4*j+1]=pb.y; x[32+4*j+2]=pb.z; x[32+4*j+3]=pb.w;
            }
        } else {
#pragma unroll
            for (int j = 0; j < 64; j++) x[j] = 0.f;
        }
        writeRowDual(sm+O_A1, sm+O_A2, tid, x);
        __syncwarp();
        float accH[2][4][4] = {}, accO[2][4][4] = {};
        gemm_dual(su+O_A1, su+O_A2, su+O_W0, su+O_WS, wid, lane, accH, accO);
        __syncwarp();
        fragToA<4>(sm+O_A1, wid, lane, accH, b0, true);
        __syncwarp();
        gemm3x<2,4>(su+O_A1, 64, su+O_W1, 32, BP32, wid, lane, accO);
        __syncwarp();
        fragToA<4>(sm+O_A1, wid, lane, accO, b1, false);
        __syncwarp();
        float accC[2][4][4] = {};
        gemm3x<2,4>(su+O_A1, 64, su+O_FC, 32, BP32, wid, lane, accC);
        fragStore(ctaBase, N, wid, lane, accC, sfb);
        __syncwarp();
    }
}

/* -------- output: CSR mean + transpose -------- */
__global__ void output_kernel(float* __restrict__ out, int total) {
    int t = blockIdx.x*blockDim.x + threadIdx.x;
    if (t >= total) return;
    int bg = t >> 5, ch = t & 31;
    int s = g_start[bg], n = g_hist[bg];
    float sum = 0.0f;
    for (int k = 0; k < n; k++) sum += g_net[(size_t)(s+k)*HID_ + ch];
    float mean = sum / fmaxf((float)n, 1.0f);
    int b = bg >> 15, g = bg & (G_ - 1);
    out[((size_t)b*HID_ + ch)*G_ + g] = mean;
}

/* -------- host -------- */
extern "C" void kernel_launch(void* const* d_in, const int* in_sizes, int n_in,
                              void* d_out, int out_size) {
    const float* p   = (const float*)d_in[0];
    const float* Wp  = (const float*)d_in[1];
    const float* Bp  = (const float*)d_in[2];
    const float* W0  = (const float*)d_in[3];
    const float* B0  = (const float*)d_in[4];
    const float* W1  = (const float*)d_in[5];
    const float* B1  = (const float*)d_in[6];
    const float* Ws  = (const float*)d_in[7];
    const float* Fc  = (const float*)d_in[8];
    const float* FcB = (const float*)d_in[9];
    float* out = (float*)d_out;

    int T = in_sizes[0] / (B_ * 3);
    int N = B_ * T;
    int nbp = (N + 255) / 256;
    int nTiles = (N + MTILE - 1) / MTILE;
    int nb = nTiles < MAXCTA ? nTiles : MAXCTA;

    cudaFuncSetAttribute(point0_kernel, cudaFuncAttributeMaxDynamicSharedMemorySize, SM_P0);
    cudaFuncSetAttribute(pool_block_kernel, cudaFuncAttributeMaxDynamicSharedMemorySize, SM_POOL);
    cudaFuncSetAttribute(final_kernel, cudaFuncAttributeMaxDynamicSharedMemorySize, SM_FIN);

    float* cellA; cudaGetSymbolAddress((void**)&cellA, g_cellA);
    float* cellB; cudaGetSymbolAddress((void**)&cellB, g_cellB);

    zero_hist_kernel<<<64, 256>>>();
    index_hist_kernel<<<nbp, 256>>>(p, T, N);
    scan_kernel<<<1, 1024>>>();
    perm_kernel<<<nbp, 256>>>(p, N);

    point0_kernel<<<nb, BDIM, SM_P0>>>(Wp, Bp, W0, B0, W1, B1, Ws, N);
    maxpool_kernel<<<BG_*8/256, 256>>>(cellA);

    pool_block_kernel<<<nb, BDIM, SM_POOL>>>(W0 + 1*64*HID_, B0 + 1*HID_,
        W1 + 1*HID_*HID_, B1 + 1*HID_, Ws + 1*64*HID_, cellA, N);
    maxpool_kernel<<<BG_*8/256, 256>>>(cellB);

    pool_block_kernel<<<nb, BDIM, SM_POOL>>>(W0 + 2*64*HID_, B0 + 2*HID_,
        W1 + 2*HID_*HID_, B1 + 2*HID_, Ws + 2*64*HID_, cellB, N);
    maxpool_kernel<<<BG_*8/256, 256>>>(cellA);

    pool_block_kernel<<<nb, BDIM, SM_POOL>>>(W0 + 3*64*HID_, B0 + 3*HID_,
        W1 + 3*HID_*HID_, B1 + 3*HID_, Ws + 3*64*HID_, cellA, N);
    maxpool_kernel<<<BG_*8/256, 256>>>(cellB);

    final_kernel<<<nb, BDIM, SM_FIN>>>(W0 + 4*64*HID_, B0 + 4*HID_,
        W1 + 4*HID_*HID_, B1 + 4*HID_, Ws + 4*64*HID_, Fc, FcB, cellB, N);

    output_kernel<<<(out_size + 255)/256, 256>>>(out, out_size);
}

// round 16
// speedup vs baseline: 2.1136x; 1.0162x over previous
#include <cuda_runtime.h>
#include <cuda_bf16.h>
#include <math.h>
#include <stdint.h>

#define B_ 2
#define RESO_ 32
#define G_ 32768
#define BG_ 65536
#define HID_ 32
#define NMAX_ 524288
#define BDIM 256
#define MTILE 256
#define APAD 272
#define BP32 80
#define BP64 144
#define MAXCTA 148

#define O_A1  0
#define O_A2  69632
#define O_W0  139264
#define O_WS  149504
#define O_W1  159744
#define O_SB0 164864
#define O_SB1 164992
#define SM_POOL 165120
#define O_FC  165120
#define O_SFB 170240
#define SM_FIN 170368
#define P_WP  165120
#define P_SBP 183552
#define SM_P0 183808

/* -------- scratch -------- */
__device__ float g_net[(size_t)NMAX_*HID_];
__device__ float g_psort[(size_t)NMAX_*3];
__device__ int   g_gidx[NMAX_];
__device__ int   g_sgidx[NMAX_];
__device__ int   g_hist[BG_];
__device__ int   g_start[BG_];
__device__ int   g_cursor[BG_];
__device__ float g_cellA[BG_*HID_];
__device__ float g_cellB[BG_*HID_];

/* -------- helpers -------- */
__device__ __forceinline__ uint32_t smem_u32(const void* p) {
    uint32_t a;
    asm("{ .reg .u64 t; cvta.to.shared.u64 t, %1; cvt.u32.u64 %0, t; }" : "=r"(a) : "l"(p));
    return a;
}
__device__ __forceinline__ void ldmA(uint32_t a[4], uint32_t addr) {
    asm volatile("ldmatrix.sync.aligned.m8n8.x4.shared.b16 {%0,%1,%2,%3}, [%4];"
        : "=r"(a[0]), "=r"(a[1]), "=r"(a[2]), "=r"(a[3]) : "r"(addr));
}
__device__ __forceinline__ void ldmB4(uint32_t b[4], uint32_t addr) {
    asm volatile("ldmatrix.sync.aligned.m8n8.x4.trans.shared.b16 {%0,%1,%2,%3}, [%4];"
        : "=r"(b[0]), "=r"(b[1]), "=r"(b[2]), "=r"(b[3]) : "r"(addr));
}
__device__ __forceinline__ void mma16816(float d[4], const uint32_t a[4], const uint32_t b[2]) {
    asm volatile("mma.sync.aligned.m16n8k16.row.col.f32.bf16.bf16.f32 "
        "{%0,%1,%2,%3},{%4,%5,%6,%7},{%8,%9},{%0,%1,%2,%3};"
        : "+f"(d[0]), "+f"(d[1]), "+f"(d[2]), "+f"(d[3])
        : "r"(a[0]), "r"(a[1]), "r"(a[2]), "r"(a[3]), "r"(b[0]), "r"(b[1]));
}
__device__ __forceinline__ void hm(float a, float b, uint32_t& H, uint32_t& M) {
    __nv_bfloat16 h0 = __float2bfloat16(a), h1 = __float2bfloat16(b);
    uint16_t u0 = *reinterpret_cast<uint16_t*>(&h0), u1 = *reinterpret_cast<uint16_t*>(&h1);
    H = ((uint32_t)u1 << 16) | u0;
    __nv_bfloat162 m = __floats2bfloat162_rn(a - __bfloat162float(h0), b - __bfloat162float(h1));
    M = *reinterpret_cast<uint32_t*>(&m);
}
__device__ __forceinline__ void writeRow64(char* A, int row, const float* v) {
    char* base = A + row*APAD;
#pragma unroll
    for (int g = 0; g < 8; g++) {
        uint32_t H[4], M[4];
#pragma unroll
        for (int j = 0; j < 4; j++) hm(v[8*g+2*j], v[8*g+2*j+1], H[j], M[j]);
        *(uint4*)(base + g*16)       = make_uint4(H[0], H[1], H[2], H[3]);
        *(uint4*)(base + 128 + g*16) = make_uint4(M[0], M[1], M[2], M[3]);
    }
}
__device__ __forceinline__ void writeRowDual(char* A1, char* A2, int row, const float* v) {
    char* b1 = A1 + row*APAD;
    char* b2 = A2 + row*APAD;
#pragma unroll
    for (int g = 0; g < 8; g++) {
        uint32_t RH[4], RM[4], H[4], M[4];
#pragma unroll
        for (int j = 0; j < 4; j++) {
            float a = v[8*g+2*j], b = v[8*g+2*j+1];
            hm(a, b, H[j], M[j]);
            hm(fmaxf(a, 0.f), fmaxf(b, 0.f), RH[j], RM[j]);
        }
        *(uint4*)(b1 + g*16)       = make_uint4(RH[0], RH[1], RH[2], RH[3]);
        *(uint4*)(b1 + 128 + g*16) = make_uint4(RM[0], RM[1], RM[2], RM[3]);
        *(uint4*)(b2 + g*16)       = make_uint4(H[0], H[1], H[2], H[3]);
        *(uint4*)(b2 + 128 + g*16) = make_uint4(M[0], M[1], M[2], M[3]);
    }
}
template<int NT>
__device__ __forceinline__ void fragToA_dual(char* A1, char* A2, int wid, int lane,
                                             float acc[2][NT][4], const float* bias) {
    const int K2 = NT*16;
    int r0 = wid*32 + (lane >> 2);
    int cb = (lane & 3)*2;
#pragma unroll
    for (int mt = 0; mt < 2; mt++)
#pragma unroll
    for (int half = 0; half < 2; half++) {
        char* b1 = A1 + (r0 + mt*16 + half*8)*APAD;
        char* b2 = A2 + (r0 + mt*16 + half*8)*APAD;
#pragma unroll
        for (int nt = 0; nt < NT; nt++) {
            int c = nt*8 + cb;
            float v0 = acc[mt][nt][half*2+0] + bias[c];
            float v1 = acc[mt][nt][half*2+1] + bias[c+1];
            uint32_t H, M; hm(v0, v1, H, M);
            *(uint32_t*)(b2 + c*2)      = H;
            *(uint32_t*)(b2 + K2 + c*2) = M;
            hm(fmaxf(v0, 0.f), fmaxf(v1, 0.f), H, M);
            *(uint32_t*)(b1 + c*2)      = H;
            *(uint32_t*)(b1 + K2 + c*2) = M;
        }
    }
}
/* D accumulators (N=32) -> in-register A fragments (K=32) hi+mid, bias(+relu) */
__device__ __forceinline__ void accToFragA(float acc[2][4][4], const float* bias, bool dorelu,
                                           int lane, uint32_t ah[2][2][4], uint32_t am[2][2][4]) {
    int cb = (lane & 3)*2;
#pragma unroll
    for (int mt = 0; mt < 2; mt++)
#pragma unroll
    for (int kc = 0; kc < 2; kc++)
#pragma unroll
    for (int half = 0; half < 2; half++) {
        int nt = kc*2 + half;
        float b0v = bias[nt*8+cb], b1v = bias[nt*8+cb+1];
        float v0 = acc[mt][nt][0] + b0v, v1 = acc[mt][nt][1] + b1v;
        float v2 = acc[mt][nt][2] + b0v, v3 = acc[mt][nt][3] + b1v;
        if (dorelu) {
            v0 = fmaxf(v0, 0.f); v1 = fmaxf(v1, 0.f);
            v2 = fmaxf(v2, 0.f); v3 = fmaxf(v3, 0.f);
        }
        uint32_t H0, M0, H1, M1;
        hm(v0, v1, H0, M0); hm(v2, v3, H1, M1);
        ah[mt][kc][half*2+0] = H0; ah[mt][kc][half*2+1] = H1;
        am[mt][kc][half*2+0] = M0; am[mt][kc][half*2+1] = M1;
    }
}
/* GEMM with in-register A frags (K=32): acc += Ah*Bh + Am*Bh + Ah*Bm */
__device__ __forceinline__ void gemm_reg(uint32_t ah[2][2][4], uint32_t am[2][2][4],
                                         uint32_t bU, int lane, float acc[2][4][4]) {
    uint32_t bBase = bU + (uint32_t)(lane & 15)*BP32 + (uint32_t)(((lane >> 4) & 1)*16);
#pragma unroll
    for (int kc = 0; kc < 2; kc++) {
#pragma unroll
        for (int nt = 0; nt < 4; nt += 2) {
            uint32_t bh[4], bm[4];
            ldmB4(bh, bBase + (uint32_t)(kc*16)*BP32 + nt*16);
            ldmB4(bm, bBase + (uint32_t)((32 + kc*16))*BP32 + nt*16);
#pragma unroll
            for (int mt = 0; mt < 2; mt++) {
                mma16816(acc[mt][nt],   ah[mt][kc], bh);
                mma16816(acc[mt][nt],   am[mt][kc], bh);
                mma16816(acc[mt][nt],   ah[mt][kc], bm);
                mma16816(acc[mt][nt+1], ah[mt][kc], bh+2);
                mma16816(acc[mt][nt+1], am[mt][kc], bh+2);
                mma16816(acc[mt][nt+1], ah[mt][kc], bm+2);
            }
        }
    }
}
__device__ __forceinline__ void fragStore(int ctaBase, int N, int wid, int lane,
                                          float acc[2][4][4], const float* bias) {
    int r0 = wid*32 + (lane >> 2);
    int cb = (lane & 3)*2;
#pragma unroll
    for (int mt = 0; mt < 2; mt++)
#pragma unroll
    for (int half = 0; half < 2; half++) {
        int slot = ctaBase + r0 + mt*16 + half*8;
        if (slot < N) {
            float* g = &g_net[(size_t)slot*HID_];
#pragma unroll
            for (int nt = 0; nt < 4; nt++) {
                int c = nt*8 + cb;
                *(float2*)(g + c) = make_float2(acc[mt][nt][half*2] + bias[c],
                                                acc[mt][nt][half*2+1] + bias[c+1]);
            }
        }
    }
}
/* fused 3-product split GEMM over smem A, x4 B loads (NT even) */
template<int KT, int NT>
__device__ __forceinline__ void gemm3x(uint32_t aU, int aMid, uint32_t bU, int bMidRows, int bpad,
                                       int wid, int lane, float acc[2][NT][4]) {
    uint32_t aAddr = aU + (uint32_t)(wid*32 + (lane & 15))*APAD + (uint32_t)((lane & 16) ? 16 : 0);
    uint32_t bBase = bU + (uint32_t)(lane & 15)*bpad + (uint32_t)(((lane >> 4) & 1)*16);
#pragma unroll
    for (int kt = 0; kt < KT; kt++) {
        uint32_t h0[4], h1[4], m0[4], m1[4];
        ldmA(h0, aAddr + kt*32);
        ldmA(h1, aAddr + kt*32 + 16*APAD);
        ldmA(m0, aAddr + aMid + kt*32);
        ldmA(m1, aAddr + aMid + kt*32 + 16*APAD);
#pragma unroll
        for (int nt = 0; nt < NT; nt += 2) {
            uint32_t bh[4], bm[4];
            ldmB4(bh, bBase + (uint32_t)(kt*16)*bpad + nt*16);
            ldmB4(bm, bBase + (uint32_t)((bMidRows + kt*16))*bpad + nt*16);
            mma16816(acc[0][nt], h0, bh); mma16816(acc[1][nt], h1, bh);
            mma16816(acc[0][nt], m0, bh); mma16816(acc[1][nt], m1, bh);
            mma16816(acc[0][nt], h0, bm); mma16816(acc[1][nt], h1, bm);
            mma16816(acc[0][nt+1], h0, bh+2); mma16816(acc[1][nt+1], h1, bh+2);
            mma16816(acc[0][nt+1], m0, bh+2); mma16816(acc[1][nt+1], m1, bh+2);
            mma16816(acc[0][nt+1], h0, bm+2); mma16816(acc[1][nt+1], h1, bm+2);
        }
    }
}
/* fused W0(relu-A1)->accH + Ws(raw-A2)->accO */
__device__ __forceinline__ void gemm_dual(uint32_t a1, uint32_t a2,
                                          uint32_t bW0, uint32_t bWS,
                                          int wid, int lane,
                                          float accH[2][4][4], float accO[2][4][4]) {
    uint32_t rowOff = (uint32_t)(wid*32 + (lane & 15))*APAD + (uint32_t)((lane & 16) ? 16 : 0);
    uint32_t aAddr1 = a1 + rowOff, aAddr2 = a2 + rowOff;
    uint32_t bOff = (uint32_t)(lane & 15)*BP32 + (uint32_t)(((lane >> 4) & 1)*16);
    uint32_t b1 = bW0 + bOff, b2 = bWS + bOff;
#pragma unroll
    for (int kt = 0; kt < 4; kt++) {
        uint32_t rh0[4], rh1[4], rm0[4], rm1[4], xh0[4], xh1[4], xm0[4], xm1[4];
        ldmA(rh0, aAddr1 + kt*32);
        ldmA(rh1, aAddr1 + kt*32 + 16*APAD);
        ldmA(rm0, aAddr1 + 128 + kt*32);
        ldmA(rm1, aAddr1 + 128 + kt*32 + 16*APAD);
        ldmA(xh0, aAddr2 + kt*32);
        ldmA(xh1, aAddr2 + kt*32 + 16*APAD);
        ldmA(xm0, aAddr2 + 128 + kt*32);
        ldmA(xm1, aAddr2 + 128 + kt*32 + 16*APAD);
#pragma unroll
        for (int nt = 0; nt < 4; nt += 2) {
            uint32_t wh[4], wm[4], sh[4], sm2[4];
            ldmB4(wh,  b1 + (uint32_t)(kt*16)*BP32 + nt*16);
            ldmB4(wm,  b1 + (uint32_t)((64 + kt*16))*BP32 + nt*16);
            ldmB4(sh,  b2 + (uint32_t)(kt*16)*BP32 + nt*16);
            ldmB4(sm2, b2 + (uint32_t)((64 + kt*16))*BP32 + nt*16);
            mma16816(accH[0][nt], rh0, wh);  mma16816(accH[1][nt], rh1, wh);
            mma16816(accO[0][nt], xh0, sh);  mma16816(accO[1][nt], xh1, sh);
            mma16816(accH[0][nt], rm0, wh);  mma16816(accH[1][nt], rm1, wh);
            mma16816(accO[0][nt], xm0, sh);  mma16816(accO[1][nt], xm1, sh);
            mma16816(accH[0][nt], rh0, wm);  mma16816(accH[1][nt], rh1, wm);
            mma16816(accO[0][nt], xh0, sm2); mma16816(accO[1][nt], xh1, sm2);
            mma16816(accH[0][nt+1], rh0, wh+2);  mma16816(accH[1][nt+1], rh1, wh+2);
            mma16816(accO[0][nt+1], xh0, sh+2);  mma16816(accO[1][nt+1], xh1, sh+2);
            mma16816(accH[0][nt+1], rm0, wh+2);  mma16816(accH[1][nt+1], rm1, wh+2);
            mma16816(accO[0][nt+1], xm0, sh+2);  mma16816(accO[1][nt+1], xm1, sh+2);
            mma16816(accH[0][nt+1], rh0, wm+2);  mma16816(accH[1][nt+1], rh1, wm+2);
            mma16816(accO[0][nt+1], xh0, sm2+2); mma16816(accO[1][nt+1], xh1, sm2+2);
        }
    }
}
__device__ void prepB(char* dst, int tid, const float* __restrict__ g,
                      int K, int Kpad, int N, int bpad) {
    for (int t = tid; t < K*N; t += BDIM) {
        int k = t / N, n = t - k*N;
        float w = g[t];
        __nv_bfloat16 h = __float2bfloat16(w);
        __nv_bfloat16 m = __float2bfloat16(w - __bfloat162float(h));
        *(__nv_bfloat16*)(dst + k*bpad + n*2) = h;
        *(__nv_bfloat16*)(dst + (Kpad+k)*bpad + n*2) = m;
    }
}

/* -------- sort pre-pass + pooling -------- */
__global__ void zero_hist_kernel() {
    int s = gridDim.x*blockDim.x;
    for (int i = blockIdx.x*blockDim.x + threadIdx.x; i < BG_; i += s) g_hist[i] = 0;
}
__global__ void index_hist_kernel(const float* __restrict__ p, int T, int N) {
    int i = blockIdx.x*blockDim.x + threadIdx.x;
    if (i >= N) return;
    float p0 = p[3*i+0], p1 = p[3*i+1], p2 = p[3*i+2];
    int b = i / T;
    float pn0 = fminf(fmaxf(__fdiv_rn(p0, 1.101f) + 0.5f, 0.0f), 0.999f);
    float pn1 = fminf(fmaxf(__fdiv_rn(p1, 1.101f) + 0.5f, 0.0f), 0.999f);
    float pn2 = fminf(fmaxf(__fdiv_rn(p2, 1.101f) + 0.5f, 0.0f), 0.999f);
    int gidx = (int)floorf(pn0*32.f) + RESO_*((int)floorf(pn1*32.f) + RESO_*(int)floorf(pn2*32.f)) + b*G_;
    g_gidx[i] = gidx;
    atomicAdd(&g_hist[gidx], 1);
}
__global__ void scan_kernel() {
    __shared__ int part[1024];
    int t = threadIdx.x, base = t*64, s = 0;
#pragma unroll
    for (int j = 0; j < 64; j++) s += g_hist[base+j];
    part[t] = s; __syncthreads();
    for (int off = 1; off < 1024; off <<= 1) {
        int v = (t >= off) ? part[t-off] : 0;
        __syncthreads(); part[t] += v; __syncthreads();
    }
    int run = (t == 0) ? 0 : part[t-1];
#pragma unroll
    for (int j = 0; j < 64; j++) {
        int c = g_hist[base+j];
        g_start[base+j] = run; g_cursor[base+j] = run; run += c;
    }
}
__global__ void perm_kernel(const float* __restrict__ p, int N) {
    int i = blockIdx.x*blockDim.x + threadIdx.x;
    if (i >= N) return;
    int gidx = g_gidx[i];
    int slot = atomicAdd(&g_cursor[gidx], 1);
    g_sgidx[slot] = gidx;
    g_psort[(size_t)slot*3+0] = p[3*i+0];
    g_psort[(size_t)slot*3+1] = p[3*i+1];
    g_psort[(size_t)slot*3+2] = p[3*i+2];
}
__global__ void maxpool_kernel(float* __restrict__ dst) {
    int t = blockIdx.x*blockDim.x + threadIdx.x;
    if (t >= BG_*8) return;
    int cell = t >> 3, q = (t & 7) * 4;
    int s = g_start[cell], n = g_hist[cell];
    float4 m = make_float4(0.f, 0.f, 0.f, 0.f);
    if (n > 0) {
        m = *reinterpret_cast<const float4*>(&g_net[(size_t)s*HID_ + q]);
        for (int k = 1; k < n; k++) {
            float4 v = *reinterpret_cast<const float4*>(&g_net[(size_t)(s+k)*HID_ + q]);
            m.x = fmaxf(m.x, v.x); m.y = fmaxf(m.y, v.y);
            m.z = fmaxf(m.z, v.z); m.w = fmaxf(m.w, v.w);
        }
    }
    *reinterpret_cast<float4*>(&dst[cell*HID_ + q]) = m;
}

/* -------- stage 0 -------- */
__global__ void __launch_bounds__(BDIM, 1) point0_kernel(
    const float* __restrict__ Wp, const float* __restrict__ Bp,
    const float* __restrict__ w0, const float* __restrict__ b0g,
    const float* __restrict__ w1, const float* __restrict__ b1g,
    const float* __restrict__ ws, int N)
{
    extern __shared__ __align__(16) char sm[];
    uint32_t su = smem_u32(sm);
    int tid = threadIdx.x, wid = tid >> 5, lane = tid & 31;
    for (int t = tid; t < 18432/4; t += BDIM) ((uint32_t*)(sm + P_WP))[t] = 0;
    __syncthreads();
    prepB(sm+P_WP, tid, Wp, 60, 64, 64, BP64);
    prepB(sm+O_W0, tid, w0, 64, 64, 32, BP32);
    prepB(sm+O_WS, tid, ws, 64, 64, 32, BP32);
    prepB(sm+O_W1, tid, w1, 32, 32, 32, BP32);
    if (tid < 32) { ((float*)(sm+O_SB0))[tid] = b0g[tid]; ((float*)(sm+O_SB1))[tid] = b1g[tid]; }
    if (tid >= 64 && tid < 128) ((float*)(sm+P_SBP))[tid-64] = Bp[tid-64];
    __syncthreads();
    const float* b0 = (const float*)(sm+O_SB0);
    const float* b1 = (const float*)(sm+O_SB1);
    const float* sbp = (const float*)(sm+P_SBP);

    int nTiles = (N + MTILE - 1) / MTILE;
    for (int tile = blockIdx.x; tile < nTiles; tile += gridDim.x) {
        int ctaBase = tile*MTILE;
        int slot = ctaBase + tid;
        float p0 = 0.f, p1 = 0.f, p2 = 0.f;
        if (slot < N) { p0 = g_psort[(size_t)slot*3]; p1 = g_psort[(size_t)slot*3+1]; p2 = g_psort[(size_t)slot*3+2]; }
        float pe[64];
#pragma unroll
        for (int j = 60; j < 64; j++) pe[j] = 0.f;
        float q[3] = {2.f*p0-1.f, 2.f*p1-1.f, 2.f*p2-1.f};
#pragma unroll
        for (int d = 0; d < 3; d++) {
            float s, c;
            sincospif(q[d], &s, &c);
#pragma unroll
            for (int l = 0; l < 10; l++) {
                if (l == 5) sincospif(q[d]*32.f, &s, &c);
                pe[l*6+d] = s; pe[l*6+3+d] = c;
                float s2 = 2.f*s*c;
                c = fmaf(-2.f*s, s, 1.f);
                s = s2;
            }
        }
        writeRow64(sm+O_A1, tid, pe);
        __syncwarp();
        float accX[2][8][4] = {};
        gemm3x<4,8>(su+O_A1, 128, su+P_WP, 64, BP64, wid, lane, accX);
        __syncwarp();
        fragToA_dual<8>(sm+O_A1, sm+O_A2, wid, lane, accX, sbp);
        __syncwarp();
        float accH[2][4][4] = {}, accO[2][4][4] = {};
        gemm_dual(su+O_A1, su+O_A2, su+O_W0, su+O_WS, wid, lane, accH, accO);
        uint32_t ah[2][2][4], am[2][2][4];
        accToFragA(accH, b0, true, lane, ah, am);
        gemm_reg(ah, am, su+O_W1, lane, accO);
        fragStore(ctaBase, N, wid, lane, accO, b1);
        __syncwarp();
    }
}

/* -------- stages 1..3 -------- */
__global__ void __launch_bounds__(BDIM, 1) pool_block_kernel(
    const float* __restrict__ w0, const float* __restrict__ b0g,
    const float* __restrict__ w1, const float* __restrict__ b1g,
    const float* __restrict__ ws, const float* __restrict__ cellSrc, int N)
{
    extern __shared__ __align__(16) char sm[];
    uint32_t su = smem_u32(sm);
    int tid = threadIdx.x, wid = tid >> 5, lane = tid & 31;
    prepB(sm+O_W0, tid, w0, 64, 64, 32, BP32);
    prepB(sm+O_WS, tid, ws, 64, 64, 32, BP32);
    prepB(sm+O_W1, tid, w1, 32, 32, 32, BP32);
    if (tid < 32) { ((float*)(sm+O_SB0))[tid] = b0g[tid]; ((float*)(sm+O_SB1))[tid] = b1g[tid]; }
    __syncthreads();
    const float* b0 = (const float*)(sm+O_SB0);
    const float* b1 = (const float*)(sm+O_SB1);

    int nTiles = (N + MTILE - 1) / MTILE;
    for (int tile = blockIdx.x; tile < nTiles; tile += gridDim.x) {
        int ctaBase = tile*MTILE;
        int slot = ctaBase + tid;
        float x[64];
        if (slot < N) {
            int gidx = g_sgidx[slot];
            const float4* np = (const float4*)&g_net[(size_t)slot*HID_];
            const float4* pp = (const float4*)&cellSrc[gidx*HID_];
#pragma unroll
            for (int j = 0; j < 8; j++) {
                float4 a = np[j]; x[4*j]=a.x; x[4*j+1]=a.y; x[4*j+2]=a.z; x[4*j+3]=a.w;
                float4 pb = pp[j]; x[32+4*j]=pb.x; x[32+4*j+1]=pb.y; x[32+4*j+2]=pb.z; x[32+4*j+3]=pb.w;
            }
        } else {
#pragma unroll
            for (int j = 0; j < 64; j++) x[j] = 0.f;
        }
        writeRowDual(sm+O_A1, sm+O_A2, tid, x);
        __syncwarp();
        float accH[2][4][4] = {}, accO[2][4][4] = {};
        gemm_dual(su+O_A1, su+O_A2, su+O_W0, su+O_WS, wid, lane, accH, accO);
        uint32_t ah[2][2][4], am[2][2][4];
        accToFragA(accH, b0, true, lane, ah, am);
        gemm_reg(ah, am, su+O_W1, lane, accO);
        fragStore(ctaBase, N, wid, lane, accO, b1);
        __syncwarp();
    }
}

/* -------- stage 4 + fc_c -------- */
__global__ void __launch_bounds__(BDIM, 1) final_kernel(
    const float* __restrict__ w0, const float* __restrict__ b0g,
    const float* __restrict__ w1, const float* __restrict__ b1g,
    const float* __restrict__ ws,
    const float* __restrict__ fcw, const float* __restrict__ fcb,
    const float* __restrict__ cellSrc, int N)
{
    extern __shared__ __align__(16) char sm[];
    uint32_t su = smem_u32(sm);
    int tid = threadIdx.x, wid = tid >> 5, lane = tid & 31;
    prepB(sm+O_W0, tid, w0, 64, 64, 32, BP32);
    prepB(sm+O_WS, tid, ws, 64, 64, 32, BP32);
    prepB(sm+O_W1, tid, w1, 32, 32, 32, BP32);
    prepB(sm+O_FC, tid, fcw, 32, 32, 32, BP32);
    if (tid < 32) {
        ((float*)(sm+O_SB0))[tid] = b0g[tid];
        ((float*)(sm+O_SB1))[tid] = b1g[tid];
        ((float*)(sm+O_SFB))[tid] = fcb[tid];
    }
    __syncthreads();
    const float* b0 = (const float*)(sm+O_SB0);
    const float* b1 = (const float*)(sm+O_SB1);
    const float* sfb = (const float*)(sm+O_SFB);

    int nTiles = (N + MTILE - 1) / MTILE;
    for (int tile = blockIdx.x; tile < nTiles; tile += gridDim.x) {
        int ctaBase = tile*MTILE;
        int slot = ctaBase + tid;
        float x[64];
        if (slot < N) {
            int gidx = g_sgidx[slot];
            const float4* np = (const float4*)&g_net[(size_t)slot*HID_];
            const float4* pp = (const float4*)&cellSrc[gidx*HID_];
#pragma unroll
            for (int j = 0; j < 8; j++) {
                float4 a = np[j]; x[4*j]=a.x; x[4*j+1]=a.y; x[4*j+2]=a.z; x[4*j+3]=a.w;
                float4 pb = pp[j]; x[32+4*j]=pb.x; x[32+4*j+1]=pb.y; x[32+4*j+2]=pb.z; x[32+4*j+3]=pb.w;
            }
        } else {
#pragma unroll
            for (int j = 0; j < 64; j++) x[j] = 0.f;
        }
        writeRowDual(sm+O_A1, sm+O_A2, tid, x);
        __syncwarp();
        float accH[2][4][4] = {}, accO[2][4][4] = {};
        gemm_dual(su+O_A1, su+O_A2, su+O_W0, su+O_WS, wid, lane, accH, accO);
        uint32_t ah[2][2][4], am[2][2][4];
        accToFragA(accH, b0, true, lane, ah, am);
        gemm_reg(ah, am, su+O_W1, lane, accO);
        /* out -> fc_c, also in-register */
        float accC[2][4][4] = {};
        accToFragA(accO, b1, false, lane, ah, am);
        gemm_reg(ah, am, su+O_FC, lane, accC);
        fragStore(ctaBase, N, wid, lane, accC, sfb);
        __syncwarp();
    }
}

/* -------- output: CSR mean + transpose -------- */
__global__ void output_kernel(float* __restrict__ out, int total) {
    int t = blockIdx.x*blockDim.x + threadIdx.x;
    if (t >= total) return;
    int bg = t >> 5, ch = t & 31;
    int s = g_start[bg], n = g_hist[bg];
    float sum = 0.0f;
    for (int k = 0; k < n; k++) sum += g_net[(size_t)(s+k)*HID_ + ch];
    float mean = sum / fmaxf((float)n, 1.0f);
    int b = bg >> 15, g = bg & (G_ - 1);
    out[((size_t)b*HID_ + ch)*G_ + g] = mean;
}

/* -------- host -------- */
extern "C" void kernel_launch(void* const* d_in, const int* in_sizes, int n_in,
                              void* d_out, int out_size) {
    const float* p   = (const float*)d_in[0];
    const float* Wp  = (const float*)d_in[1];
    const float* Bp  = (const float*)d_in[2];
    const float* W0  = (const float*)d_in[3];
    const float* B0  = (const float*)d_in[4];
    const float* W1  = (const float*)d_in[5];
    const float* B1  = (const float*)d_in[6];
    const float* Ws  = (const float*)d_in[7];
    const float* Fc  = (const float*)d_in[8];
    const float* FcB = (const float*)d_in[9];
    float* out = (float*)d_out;

    int T = in_sizes[0] / (B_ * 3);
    int N = B_ * T;
    int nbp = (N + 255) / 256;
    int nTiles = (N + MTILE - 1) / MTILE;
    int nb = nTiles < MAXCTA ? nTiles : MAXCTA;

    cudaFuncSetAttribute(point0_kernel, cudaFuncAttributeMaxDynamicSharedMemorySize, SM_P0);
    cudaFuncSetAttribute(pool_block_kernel, cudaFuncAttributeMaxDynamicSharedMemorySize, SM_POOL);
    cudaFuncSetAttribute(final_kernel, cudaFuncAttributeMaxDynamicSharedMemorySize, SM_FIN);

    float* cellA; cudaGetSymbolAddress((void**)&cellA, g_cellA);
    float* cellB; cudaGetSymbolAddress((void**)&cellB, g_cellB);

    zero_hist_kernel<<<64, 256>>>();
    index_hist_kernel<<<nbp, 256>>>(p, T, N);
    scan_kernel<<<1, 1024>>>();
    perm_kernel<<<nbp, 256>>>(p, N);

    point0_kernel<<<nb, BDIM, SM_P0>>>(Wp, Bp, W0, B0, W1, B1, Ws, N);
    maxpool_kernel<<<BG_*8/256, 256>>>(cellA);

    pool_block_kernel<<<nb, BDIM, SM_POOL>>>(W0 + 1*64*HID_, B0 + 1*HID_,
        W1 + 1*HID_*HID_, B1 + 1*HID_, Ws + 1*64*HID_, cellA, N);
    maxpool_kernel<<<BG_*8/256, 256>>>(cellB);

    pool_block_kernel<<<nb, BDIM, SM_POOL>>>(W0 + 2*64*HID_, B0 + 2*HID_,
        W1 + 2*HID_*HID_, B1 + 2*HID_, Ws + 2*64*HID_, cellB, N);
    maxpool_kernel<<<BG_*8/256, 256>>>(cellA);

    pool_block_kernel<<<nb, BDIM, SM_POOL>>>(W0 + 3*64*HID_, B0 + 3*HID_,
        W1 + 3*HID_*HID_, B1 + 3*HID_, Ws + 3*64*HID_, cellA, N);
    maxpool_kernel<<<BG_*8/256, 256>>>(cellB);

    final_kernel<<<nb, BDIM, SM_FIN>>>(W0 + 4*64*HID_, B0 + 4*HID_,
        W1 + 4*HID_*HID_, B1 + 4*HID_, Ws + 4*64*HID_, Fc, FcB, cellB, N);

    output_kernel<<<(out_size + 255)/256, 256>>>(out, out_size);
}

// round 17
// speedup vs baseline: 2.3229x; 1.0990x over previous
#include <cuda_runtime.h>
#include <cuda_bf16.h>
#include <math.h>
#include <stdint.h>

#define B_ 2
#define RESO_ 32
#define G_ 32768
#define BG_ 65536
#define HID_ 32
#define NMAX_ 524288
#define BDIM 256
#define MTILE 256
#define APAD 272
#define BP32 80
#define BP64 144
#define MAXCTA 148

/* pool/final smem: weights only */
#define O_W0  0
#define O_WS  10240
#define O_W1  20480
#define O_SB0 25600
#define O_SB1 25728
#define SM_POOL 25856
#define O_FC  25856
#define O_SFB 30976
#define SM_FIN 31104
/* point0: A1 tile + weights */
#define O_A1  0
#define P_WP  69632
#define P_W0  88064
#define P_WS  98304
#define P_W1  108544
#define P_SB0 113664
#define P_SB1 113792
#define P_SBP 113920
#define SM_P0 114176

/* -------- scratch -------- */
__device__ float g_net[(size_t)NMAX_*HID_];
__device__ float g_psort[(size_t)NMAX_*3];
__device__ int   g_gidx[NMAX_];
__device__ int   g_sgidx[NMAX_];
__device__ int   g_hist[BG_];
__device__ int   g_start[BG_];
__device__ int   g_cursor[BG_];
__device__ float g_cellA[BG_*HID_];
__device__ float g_cellB[BG_*HID_];

/* -------- helpers -------- */
__device__ __forceinline__ uint32_t smem_u32(const void* p) {
    uint32_t a;
    asm("{ .reg .u64 t; cvta.to.shared.u64 t, %1; cvt.u32.u64 %0, t; }" : "=r"(a) : "l"(p));
    return a;
}
__device__ __forceinline__ void ldmA(uint32_t a[4], uint32_t addr) {
    asm volatile("ldmatrix.sync.aligned.m8n8.x4.shared.b16 {%0,%1,%2,%3}, [%4];"
        : "=r"(a[0]), "=r"(a[1]), "=r"(a[2]), "=r"(a[3]) : "r"(addr));
}
__device__ __forceinline__ void ldmB4(uint32_t b[4], uint32_t addr) {
    asm volatile("ldmatrix.sync.aligned.m8n8.x4.trans.shared.b16 {%0,%1,%2,%3}, [%4];"
        : "=r"(b[0]), "=r"(b[1]), "=r"(b[2]), "=r"(b[3]) : "r"(addr));
}
__device__ __forceinline__ void mma16816(float d[4], const uint32_t a[4], const uint32_t b[2]) {
    asm volatile("mma.sync.aligned.m16n8k16.row.col.f32.bf16.bf16.f32 "
        "{%0,%1,%2,%3},{%4,%5,%6,%7},{%8,%9},{%0,%1,%2,%3};"
        : "+f"(d[0]), "+f"(d[1]), "+f"(d[2]), "+f"(d[3])
        : "r"(a[0]), "r"(a[1]), "r"(a[2]), "r"(a[3]), "r"(b[0]), "r"(b[1]));
}
__device__ __forceinline__ void hm(float a, float b, uint32_t& H, uint32_t& M) {
    __nv_bfloat16 h0 = __float2bfloat16(a), h1 = __float2bfloat16(b);
    uint16_t u0 = *reinterpret_cast<uint16_t*>(&h0), u1 = *reinterpret_cast<uint16_t*>(&h1);
    H = ((uint32_t)u1 << 16) | u0;
    __nv_bfloat162 m = __floats2bfloat162_rn(a - __bfloat162float(h0), b - __bfloat162float(h1));
    M = *reinterpret_cast<uint32_t*>(&m);
}
__device__ __forceinline__ void writeRow64(char* A, int row, const float* v) {
    char* base = A + row*APAD;
#pragma unroll
    for (int g = 0; g < 8; g++) {
        uint32_t H[4], M[4];
#pragma unroll
        for (int j = 0; j < 4; j++) hm(v[8*g+2*j], v[8*g+2*j+1], H[j], M[j]);
        *(uint4*)(base + g*16)       = make_uint4(H[0], H[1], H[2], H[3]);
        *(uint4*)(base + 128 + g*16) = make_uint4(M[0], M[1], M[2], M[3]);
    }
}
/* D accumulators (N=32) -> in-register A frags (K=32), hi+mid, bias(+relu) */
__device__ __forceinline__ void accToFragA(float acc[2][4][4], const float* bias, bool dorelu,
                                           int lane, uint32_t ah[2][2][4], uint32_t am[2][2][4]) {
    int cb = (lane & 3)*2;
#pragma unroll
    for (int mt = 0; mt < 2; mt++)
#pragma unroll
    for (int kc = 0; kc < 2; kc++)
#pragma unroll
    for (int half = 0; half < 2; half++) {
        int nt = kc*2 + half;
        float b0v = bias[nt*8+cb], b1v = bias[nt*8+cb+1];
        float v0 = acc[mt][nt][0] + b0v, v1 = acc[mt][nt][1] + b1v;
        float v2 = acc[mt][nt][2] + b0v, v3 = acc[mt][nt][3] + b1v;
        if (dorelu) {
            v0 = fmaxf(v0, 0.f); v1 = fmaxf(v1, 0.f);
            v2 = fmaxf(v2, 0.f); v3 = fmaxf(v3, 0.f);
        }
        uint32_t H0, M0, H1, M1;
        hm(v0, v1, H0, M0); hm(v2, v3, H1, M1);
        ah[mt][kc][half*2+0] = H0; ah[mt][kc][half*2+1] = H1;
        am[mt][kc][half*2+0] = M0; am[mt][kc][half*2+1] = M1;
    }
}
/* GEMM with in-register A frags (K=32): acc += Ah*Bh + Am*Bh + Ah*Bm */
__device__ __forceinline__ void gemm_reg(uint32_t ah[2][2][4], uint32_t am[2][2][4],
                                         uint32_t bU, int lane, float acc[2][4][4]) {
    uint32_t bBase = bU + (uint32_t)(lane & 15)*BP32 + (uint32_t)(((lane >> 4) & 1)*16);
#pragma unroll
    for (int kc = 0; kc < 2; kc++) {
#pragma unroll
        for (int nt = 0; nt < 4; nt += 2) {
            uint32_t bh[4], bm[4];
            ldmB4(bh, bBase + (uint32_t)(kc*16)*BP32 + nt*16);
            ldmB4(bm, bBase + (uint32_t)((32 + kc*16))*BP32 + nt*16);
#pragma unroll
            for (int mt = 0; mt < 2; mt++) {
                mma16816(acc[mt][nt],   ah[mt][kc], bh);
                mma16816(acc[mt][nt],   am[mt][kc], bh);
                mma16816(acc[mt][nt],   ah[mt][kc], bm);
                mma16816(acc[mt][nt+1], ah[mt][kc], bh+2);
                mma16816(acc[mt][nt+1], am[mt][kc], bh+2);
                mma16816(acc[mt][nt+1], ah[mt][kc], bm+2);
            }
        }
    }
}
__device__ __forceinline__ void fragStore(int ctaBase, int N, int wid, int lane,
                                          float acc[2][4][4], const float* bias) {
    int r0 = wid*32 + (lane >> 2);
    int cb = (lane & 3)*2;
#pragma unroll
    for (int mt = 0; mt < 2; mt++)
#pragma unroll
    for (int half = 0; half < 2; half++) {
        int slot = ctaBase + r0 + mt*16 + half*8;
        if (slot < N) {
            float* g = &g_net[(size_t)slot*HID_];
#pragma unroll
            for (int nt = 0; nt < 4; nt++) {
                int c = nt*8 + cb;
                *(float2*)(g + c) = make_float2(acc[mt][nt][half*2] + bias[c],
                                                acc[mt][nt][half*2+1] + bias[c+1]);
            }
        }
    }
}
/* dual-GEMM inner MMA block on frags for one kt */
#define DUAL_MMAS(nt) do { \
    mma16816(accH[0][nt], rH[0], wh);   mma16816(accH[1][nt], rH[1], wh); \
    mma16816(accO[0][nt], xH[0], sh);   mma16816(accO[1][nt], xH[1], sh); \
    mma16816(accH[0][nt], rM[0], wh);   mma16816(accH[1][nt], rM[1], wh); \
    mma16816(accO[0][nt], xM[0], sh);   mma16816(accO[1][nt], xM[1], sh); \
    mma16816(accH[0][nt], rH[0], wm);   mma16816(accH[1][nt], rH[1], wm); \
    mma16816(accO[0][nt], xH[0], sm2);  mma16816(accO[1][nt], xH[1], sm2); \
    mma16816(accH[0][nt+1], rH[0], wh+2);  mma16816(accH[1][nt+1], rH[1], wh+2); \
    mma16816(accO[0][nt+1], xH[0], sh+2);  mma16816(accO[1][nt+1], xH[1], sh+2); \
    mma16816(accH[0][nt+1], rM[0], wh+2);  mma16816(accH[1][nt+1], rM[1], wh+2); \
    mma16816(accO[0][nt+1], xM[0], sh+2);  mma16816(accO[1][nt+1], xM[1], sh+2); \
    mma16816(accH[0][nt+1], rH[0], wm+2);  mma16816(accH[1][nt+1], rH[1], wm+2); \
    mma16816(accO[0][nt+1], xH[0], sm2+2); mma16816(accO[1][nt+1], xH[1], sm2+2); \
} while (0)

/* dual GEMM (W0 on relu(x) -> accH, Ws on x -> accO), A built from xv registers */
__device__ __forceinline__ void gemm_dualX(const float2 xv[4][8],
                                           uint32_t bW0, uint32_t bWS, int lane,
                                           float accH[2][4][4], float accO[2][4][4]) {
    uint32_t bOff = (uint32_t)(lane & 15)*BP32 + (uint32_t)(((lane >> 4) & 1)*16);
    uint32_t b1 = bW0 + bOff, b2 = bWS + bOff;
#pragma unroll
    for (int kt = 0; kt < 4; kt++) {
        uint32_t rH[2][4], rM[2][4], xH[2][4], xM[2][4];
#pragma unroll
        for (int mt = 0; mt < 2; mt++)
#pragma unroll
        for (int gg = 0; gg < 2; gg++)
#pragma unroll
        for (int rr = 0; rr < 2; rr++) {
            float2 v = xv[mt*2+rr][2*kt+gg];
            int idx = gg*2 + rr;
            hm(v.x, v.y, xH[mt][idx], xM[mt][idx]);
            hm(fmaxf(v.x, 0.f), fmaxf(v.y, 0.f), rH[mt][idx], rM[mt][idx]);
        }
#pragma unroll
        for (int nt = 0; nt < 4; nt += 2) {
            uint32_t wh[4], wm[4], sh[4], sm2[4];
            ldmB4(wh,  b1 + (uint32_t)(kt*16)*BP32 + nt*16);
            ldmB4(wm,  b1 + (uint32_t)((64 + kt*16))*BP32 + nt*16);
            ldmB4(sh,  b2 + (uint32_t)(kt*16)*BP32 + nt*16);
            ldmB4(sm2, b2 + (uint32_t)((64 + kt*16))*BP32 + nt*16);
            DUAL_MMAS(nt);
        }
    }
}
/* dual GEMM, A built from D accumulators (N=64) + bias (point0) */
__device__ __forceinline__ void gemm_dualAcc(float acc[2][8][4], const float* bias,
                                             uint32_t bW0, uint32_t bWS, int lane,
                                             float accH[2][4][4], float accO[2][4][4]) {
    int cb = (lane & 3)*2;
    uint32_t bOff = (uint32_t)(lane & 15)*BP32 + (uint32_t)(((lane >> 4) & 1)*16);
    uint32_t b1 = bW0 + bOff, b2 = bWS + bOff;
#pragma unroll
    for (int kt = 0; kt < 4; kt++) {
        uint32_t rH[2][4], rM[2][4], xH[2][4], xM[2][4];
#pragma unroll
        for (int mt = 0; mt < 2; mt++)
#pragma unroll
        for (int gg = 0; gg < 2; gg++) {
            int nt = 2*kt + gg;
            float b0v = bias[nt*8+cb], b1v = bias[nt*8+cb+1];
#pragma unroll
            for (int rr = 0; rr < 2; rr++) {
                float v0 = acc[mt][nt][rr*2+0] + b0v;
                float v1 = acc[mt][nt][rr*2+1] + b1v;
                int idx = gg*2 + rr;
                hm(v0, v1, xH[mt][idx], xM[mt][idx]);
                hm(fmaxf(v0, 0.f), fmaxf(v1, 0.f), rH[mt][idx], rM[mt][idx]);
            }
        }
#pragma unroll
        for (int nt = 0; nt < 4; nt += 2) {
            uint32_t wh[4], wm[4], sh[4], sm2[4];
            ldmB4(wh,  b1 + (uint32_t)(kt*16)*BP32 + nt*16);
            ldmB4(wm,  b1 + (uint32_t)((64 + kt*16))*BP32 + nt*16);
            ldmB4(sh,  b2 + (uint32_t)(kt*16)*BP32 + nt*16);
            ldmB4(sm2, b2 + (uint32_t)((64 + kt*16))*BP32 + nt*16);
            DUAL_MMAS(nt);
        }
    }
}
/* smem-A 3-product GEMM (point0 PE only) */
template<int KT, int NT>
__device__ __forceinline__ void gemm3x(uint32_t aU, int aMid, uint32_t bU, int bMidRows, int bpad,
                                       int wid, int lane, float acc[2][NT][4]) {
    uint32_t aAddr = aU + (uint32_t)(wid*32 + (lane & 15))*APAD + (uint32_t)((lane & 16) ? 16 : 0);
    uint32_t bBase = bU + (uint32_t)(lane & 15)*bpad + (uint32_t)(((lane >> 4) & 1)*16);
#pragma unroll
    for (int kt = 0; kt < KT; kt++) {
        uint32_t h0[4], h1[4], m0[4], m1[4];
        ldmA(h0, aAddr + kt*32);
        ldmA(h1, aAddr + kt*32 + 16*APAD);
        ldmA(m0, aAddr + aMid + kt*32);
        ldmA(m1, aAddr + aMid + kt*32 + 16*APAD);
#pragma unroll
        for (int nt = 0; nt < NT; nt += 2) {
            uint32_t bh[4], bm[4];
            ldmB4(bh, bBase + (uint32_t)(kt*16)*bpad + nt*16);
            ldmB4(bm, bBase + (uint32_t)((bMidRows + kt*16))*bpad + nt*16);
            mma16816(acc[0][nt], h0, bh); mma16816(acc[1][nt], h1, bh);
            mma16816(acc[0][nt], m0, bh); mma16816(acc[1][nt], m1, bh);
            mma16816(acc[0][nt], h0, bm); mma16816(acc[1][nt], h1, bm);
            mma16816(acc[0][nt+1], h0, bh+2); mma16816(acc[1][nt+1], h1, bh+2);
            mma16816(acc[0][nt+1], m0, bh+2); mma16816(acc[1][nt+1], m1, bh+2);
            mma16816(acc[0][nt+1], h0, bm+2); mma16816(acc[1][nt+1], h1, bm+2);
        }
    }
}
__device__ void prepB(char* dst, int tid, const float* __restrict__ g,
                      int K, int Kpad, int N, int bpad) {
    for (int t = tid; t < K*N; t += BDIM) {
        int k = t / N, n = t - k*N;
        float w = g[t];
        __nv_bfloat16 h = __float2bfloat16(w);
        __nv_bfloat16 m = __float2bfloat16(w - __bfloat162float(h));
        *(__nv_bfloat16*)(dst + k*bpad + n*2) = h;
        *(__nv_bfloat16*)(dst + (Kpad+k)*bpad + n*2) = m;
    }
}
/* load x fragment values directly from gmem (pool/final stages) */
__device__ __forceinline__ void loadXV(float2 xv[4][8], int ctaBase, int N,
                                       int wid, int lane, const float* __restrict__ cellSrc) {
    int r0 = wid*32 + (lane >> 2);
    int cb = (lane & 3)*2;
#pragma unroll
    for (int rr = 0; rr < 4; rr++) {
        int row = ctaBase + r0 + rr*8;
        if (row < N) {
            int gidx = g_sgidx[row];
            const float* nrow = &g_net[(size_t)row*HID_];
            const float* crow = &cellSrc[gidx*HID_];
#pragma unroll
            for (int g = 0; g < 4; g++) xv[rr][g]   = *(const float2*)(nrow + g*8 + cb);
#pragma unroll
            for (int g = 0; g < 4; g++) xv[rr][4+g] = *(const float2*)(crow + g*8 + cb);
        } else {
#pragma unroll
            for (int g = 0; g < 8; g++) xv[rr][g] = make_float2(0.f, 0.f);
        }
    }
}

/* -------- sort pre-pass + pooling -------- */
__global__ void zero_hist_kernel() {
    int s = gridDim.x*blockDim.x;
    for (int i = blockIdx.x*blockDim.x + threadIdx.x; i < BG_; i += s) g_hist[i] = 0;
}
__global__ void index_hist_kernel(const float* __restrict__ p, int T, int N) {
    int i = blockIdx.x*blockDim.x + threadIdx.x;
    if (i >= N) return;
    float p0 = p[3*i+0], p1 = p[3*i+1], p2 = p[3*i+2];
    int b = i / T;
    float pn0 = fminf(fmaxf(__fdiv_rn(p0, 1.101f) + 0.5f, 0.0f), 0.999f);
    float pn1 = fminf(fmaxf(__fdiv_rn(p1, 1.101f) + 0.5f, 0.0f), 0.999f);
    float pn2 = fminf(fmaxf(__fdiv_rn(p2, 1.101f) + 0.5f, 0.0f), 0.999f);
    int gidx = (int)floorf(pn0*32.f) + RESO_*((int)floorf(pn1*32.f) + RESO_*(int)floorf(pn2*32.f)) + b*G_;
    g_gidx[i] = gidx;
    atomicAdd(&g_hist[gidx], 1);
}
__global__ void scan_kernel() {
    __shared__ int part[1024];
    int t = threadIdx.x, base = t*64, s = 0;
#pragma unroll
    for (int j = 0; j < 64; j++) s += g_hist[base+j];
    part[t] = s; __syncthreads();
    for (int off = 1; off < 1024; off <<= 1) {
        int v = (t >= off) ? part[t-off] : 0;
        __syncthreads(); part[t] += v; __syncthreads();
    }
    int run = (t == 0) ? 0 : part[t-1];
#pragma unroll
    for (int j = 0; j < 64; j++) {
        int c = g_hist[base+j];
        g_start[base+j] = run; g_cursor[base+j] = run; run += c;
    }
}
__global__ void perm_kernel(const float* __restrict__ p, int N) {
    int i = blockIdx.x*blockDim.x + threadIdx.x;
    if (i >= N) return;
    int gidx = g_gidx[i];
    int slot = atomicAdd(&g_cursor[gidx], 1);
    g_sgidx[slot] = gidx;
    g_psort[(size_t)slot*3+0] = p[3*i+0];
    g_psort[(size_t)slot*3+1] = p[3*i+1];
    g_psort[(size_t)slot*3+2] = p[3*i+2];
}
__global__ void maxpool_kernel(float* __restrict__ dst) {
    int t = blockIdx.x*blockDim.x + threadIdx.x;
    if (t >= BG_*8) return;
    int cell = t >> 3, q = (t & 7) * 4;
    int s = g_start[cell], n = g_hist[cell];
    float4 m = make_float4(0.f, 0.f, 0.f, 0.f);
    if (n > 0) {
        m = *reinterpret_cast<const float4*>(&g_net[(size_t)s*HID_ + q]);
        for (int k = 1; k < n; k++) {
            float4 v = *reinterpret_cast<const float4*>(&g_net[(size_t)(s+k)*HID_ + q]);
            m.x = fmaxf(m.x, v.x); m.y = fmaxf(m.y, v.y);
            m.z = fmaxf(m.z, v.z); m.w = fmaxf(m.w, v.w);
        }
    }
    *reinterpret_cast<float4*>(&dst[cell*HID_ + q]) = m;
}

/* -------- stage 0 -------- */
__global__ void __launch_bounds__(BDIM, 1) point0_kernel(
    const float* __restrict__ Wp, const float* __restrict__ Bp,
    const float* __restrict__ w0, const float* __restrict__ b0g,
    const float* __restrict__ w1, const float* __restrict__ b1g,
    const float* __restrict__ ws, int N)
{
    extern __shared__ __align__(16) char sm[];
    uint32_t su = smem_u32(sm);
    int tid = threadIdx.x, wid = tid >> 5, lane = tid & 31;
    for (int t = tid; t < 18432/4; t += BDIM) ((uint32_t*)(sm + P_WP))[t] = 0;
    __syncthreads();
    prepB(sm+P_WP, tid, Wp, 60, 64, 64, BP64);
    prepB(sm+P_W0, tid, w0, 64, 64, 32, BP32);
    prepB(sm+P_WS, tid, ws, 64, 64, 32, BP32);
    prepB(sm+P_W1, tid, w1, 32, 32, 32, BP32);
    if (tid < 32) { ((float*)(sm+P_SB0))[tid] = b0g[tid]; ((float*)(sm+P_SB1))[tid] = b1g[tid]; }
    if (tid >= 64 && tid < 128) ((float*)(sm+P_SBP))[tid-64] = Bp[tid-64];
    __syncthreads();
    const float* b0 = (const float*)(sm+P_SB0);
    const float* b1 = (const float*)(sm+P_SB1);
    const float* sbp = (const float*)(sm+P_SBP);

    int nTiles = (N + MTILE - 1) / MTILE;
    for (int tile = blockIdx.x; tile < nTiles; tile += gridDim.x) {
        int ctaBase = tile*MTILE;
        int slot = ctaBase + tid;
        float p0 = 0.f, p1 = 0.f, p2 = 0.f;
        if (slot < N) { p0 = g_psort[(size_t)slot*3]; p1 = g_psort[(size_t)slot*3+1]; p2 = g_psort[(size_t)slot*3+2]; }
        float pe[64];
#pragma unroll
        for (int j = 60; j < 64; j++) pe[j] = 0.f;
        float q[3] = {2.f*p0-1.f, 2.f*p1-1.f, 2.f*p2-1.f};
#pragma unroll
        for (int d = 0; d < 3; d++) {
            float s, c;
            sincospif(q[d], &s, &c);
#pragma unroll
            for (int l = 0; l < 10; l++) {
                if (l == 5) sincospif(q[d]*32.f, &s, &c);
                pe[l*6+d] = s; pe[l*6+3+d] = c;
                float s2 = 2.f*s*c;
                c = fmaf(-2.f*s, s, 1.f);
                s = s2;
            }
        }
        writeRow64(sm+O_A1, tid, pe);
        __syncwarp();
        float accX[2][8][4] = {};
        gemm3x<4,8>(su+O_A1, 128, su+P_WP, 64, BP64, wid, lane, accX);
        float accH[2][4][4] = {}, accO[2][4][4] = {};
        gemm_dualAcc(accX, sbp, su+P_W0, su+P_WS, lane, accH, accO);
        uint32_t ah[2][2][4], am[2][2][4];
        accToFragA(accH, b0, true, lane, ah, am);
        gemm_reg(ah, am, su+P_W1, lane, accO);
        fragStore(ctaBase, N, wid, lane, accO, b1);
        __syncwarp();
    }
}

/* -------- stages 1..3 -------- */
__global__ void __launch_bounds__(BDIM, 1) pool_block_kernel(
    const float* __restrict__ w0, const float* __restrict__ b0g,
    const float* __restrict__ w1, const float* __restrict__ b1g,
    const float* __restrict__ ws, const float* __restrict__ cellSrc, int N)
{
    extern __shared__ __align__(16) char sm[];
    uint32_t su = smem_u32(sm);
    int tid = threadIdx.x, wid = tid >> 5, lane = tid & 31;
    prepB(sm+O_W0, tid, w0, 64, 64, 32, BP32);
    prepB(sm+O_WS, tid, ws, 64, 64, 32, BP32);
    prepB(sm+O_W1, tid, w1, 32, 32, 32, BP32);
    if (tid < 32) { ((float*)(sm+O_SB0))[tid] = b0g[tid]; ((float*)(sm+O_SB1))[tid] = b1g[tid]; }
    __syncthreads();
    const float* b0 = (const float*)(sm+O_SB0);
    const float* b1 = (const float*)(sm+O_SB1);

    int nTiles = (N + MTILE - 1) / MTILE;
    for (int tile = blockIdx.x; tile < nTiles; tile += gridDim.x) {
        int ctaBase = tile*MTILE;
        float2 xv[4][8];
        loadXV(xv, ctaBase, N, wid, lane, cellSrc);
        float accH[2][4][4] = {}, accO[2][4][4] = {};
        gemm_dualX(xv, su+O_W0, su+O_WS, lane, accH, accO);
        uint32_t ah[2][2][4], am[2][2][4];
        accToFragA(accH, b0, true, lane, ah, am);
        gemm_reg(ah, am, su+O_W1, lane, accO);
        fragStore(ctaBase, N, wid, lane, accO, b1);
    }
}

/* -------- stage 4 + fc_c -------- */
__global__ void __launch_bounds__(BDIM, 1) final_kernel(
    const float* __restrict__ w0, const float* __restrict__ b0g,
    const float* __restrict__ w1, const float* __restrict__ b1g,
    const float* __restrict__ ws,
    const float* __restrict__ fcw, const float* __restrict__ fcb,
    const float* __restrict__ cellSrc, int N)
{
    extern __shared__ __align__(16) char sm[];
    uint32_t su = smem_u32(sm);
    int tid = threadIdx.x, wid = tid >> 5, lane = tid & 31;
    prepB(sm+O_W0, tid, w0, 64, 64, 32, BP32);
    prepB(sm+O_WS, tid, ws, 64, 64, 32, BP32);
    prepB(sm+O_W1, tid, w1, 32, 32, 32, BP32);
    prepB(sm+O_FC, tid, fcw, 32, 32, 32, BP32);
    if (tid < 32) {
        ((float*)(sm+O_SB0))[tid] = b0g[tid];
        ((float*)(sm+O_SB1))[tid] = b1g[tid];
        ((float*)(sm+O_SFB))[tid] = fcb[tid];
    }
    __syncthreads();
    const float* b0 = (const float*)(sm+O_SB0);
    const float* b1 = (const float*)(sm+O_SB1);
    const float* sfb = (const float*)(sm+O_SFB);

    int nTiles = (N + MTILE - 1) / MTILE;
    for (int tile = blockIdx.x; tile < nTiles; tile += gridDim.x) {
        int ctaBase = tile*MTILE;
        float2 xv[4][8];
        loadXV(xv, ctaBase, N, wid, lane, cellSrc);
        float accH[2][4][4] = {}, accO[2][4][4] = {};
        gemm_dualX(xv, su+O_W0, su+O_WS, lane, accH, accO);
        uint32_t ah[2][2][4], am[2][2][4];
        accToFragA(accH, b0, true, lane, ah, am);
        gemm_reg(ah, am, su+O_W1, lane, accO);
        float accC[2][4][4] = {};
        accToFragA(accO, b1, false, lane, ah, am);
        gemm_reg(ah, am, su+O_FC, lane, accC);
        fragStore(ctaBase, N, wid, lane, accC, sfb);
    }
}

/* -------- output: CSR mean + transpose -------- */
__global__ void output_kernel(float* __restrict__ out, int total) {
    int t = blockIdx.x*blockDim.x + threadIdx.x;
    if (t >= total) return;
    int bg = t >> 5, ch = t & 31;
    int s = g_start[bg], n = g_hist[bg];
    float sum = 0.0f;
    for (int k = 0; k < n; k++) sum += g_net[(size_t)(s+k)*HID_ + ch];
    float mean = sum / fmaxf((float)n, 1.0f);
    int b = bg >> 15, g = bg & (G_ - 1);
    out[((size_t)b*HID_ + ch)*G_ + g] = mean;
}

/* -------- host -------- */
extern "C" void kernel_launch(void* const* d_in, const int* in_sizes, int n_in,
                              void* d_out, int out_size) {
    const float* p   = (const float*)d_in[0];
    const float* Wp  = (const float*)d_in[1];
    const float* Bp  = (const float*)d_in[2];
    const float* W0  = (const float*)d_in[3];
    const float* B0  = (const float*)d_in[4];
    const float* W1  = (const float*)d_in[5];
    const float* B1  = (const float*)d_in[6];
    const float* Ws  = (const float*)d_in[7];
    const float* Fc  = (const float*)d_in[8];
    const float* FcB = (const float*)d_in[9];
    float* out = (float*)d_out;

    int T = in_sizes[0] / (B_ * 3);
    int N = B_ * T;
    int nbp = (N + 255) / 256;
    int nTiles = (N + MTILE - 1) / MTILE;
    int nb = nTiles < MAXCTA ? nTiles : MAXCTA;

    cudaFuncSetAttribute(point0_kernel, cudaFuncAttributeMaxDynamicSharedMemorySize, SM_P0);
    cudaFuncSetAttribute(pool_block_kernel, cudaFuncAttributeMaxDynamicSharedMemorySize, SM_POOL);
    cudaFuncSetAttribute(final_kernel, cudaFuncAttributeMaxDynamicSharedMemorySize, SM_FIN);

    float* cellA; cudaGetSymbolAddress((void**)&cellA, g_cellA);
    float* cellB; cudaGetSymbolAddress((void**)&cellB, g_cellB);

    zero_hist_kernel<<<64, 256>>>();
    index_hist_kernel<<<nbp, 256>>>(p, T, N);
    scan_kernel<<<1, 1024>>>();
    perm_kernel<<<nbp, 256>>>(p, N);

    point0_kernel<<<nb, BDIM, SM_P0>>>(Wp, Bp, W0, B0, W1, B1, Ws, N);
    maxpool_kernel<<<BG_*8/256, 256>>>(cellA);

    pool_block_kernel<<<nb, BDIM, SM_POOL>>>(W0 + 1*64*HID_, B0 + 1*HID_,
        W1 + 1*HID_*HID_, B1 + 1*HID_, Ws + 1*64*HID_, cellA, N);
    maxpool_kernel<<<BG_*8/256, 256>>>(cellB);

    pool_block_kernel<<<nb, BDIM, SM_POOL>>>(W0 + 2*64*HID_, B0 + 2*HID_,
        W1 + 2*HID_*HID_, B1 + 2*HID_, Ws + 2*64*HID_, cellB, N);
    maxpool_kernel<<<BG_*8/256, 256>>>(cellA);

    pool_block_kernel<<<nb, BDIM, SM_POOL>>>(W0 + 3*64*HID_, B0 + 3*HID_,
        W1 + 3*HID_*HID_, B1 + 3*HID_, Ws + 3*64*HID_, cellA, N);
    maxpool_kernel<<<BG_*8/256, 256>>>(cellB);

    final_kernel<<<nb, BDIM, SM_FIN>>>(W0 + 4*64*HID_, B0 + 4*HID_,
        W1 + 4*HID_*HID_, B1 + 4*HID_, Ws + 4*64*HID_, Fc, FcB, cellB, N);

    output_kernel<<<(out_size + 255)/256, 256>>>(out, out_size);
}